// round 5
// baseline (speedup 1.0000x reference)
#include <cuda_runtime.h>
#include <math.h>
#include <stdint.h>

#define B_  2
#define T_  2048
#define D_  2048
#define H_  16
#define DH  128
#define MROWS (B_*T_)          // 4096
#define QKV_N (3*D_)           // 6144

// Scratch (device globals — no allocation allowed)
__device__ float g_qkv[(size_t)MROWS * QKV_N];    // tf32; Q/K cols k-permuted
__device__ float g_o[(size_t)MROWS * D_];         // tf32, k-permuted
__device__ float g_xr[(size_t)MROWS * D_];        // x tf32, k-permuted
__device__ float g_WqkvT[(size_t)QKV_N * D_];     // [N,K] tf32, k-permuted
__device__ float g_WoutT[(size_t)D_ * D_];        // [N,K] tf32, k-permuted

// k-permute within each 8-float group: stored[PERM_POS(j)] = orig[j]
// stored order = [k0,k4,k1,k5,k2,k6,k3,k7]; fragment pair (qc, qc+4) -> one LDS.64
__host__ __device__ __forceinline__ int PERM_POS(int j) {
    return ((j & 3) << 1) | (j >> 2);
}

// ---------------------------------------------------------------------------
// Helpers
// ---------------------------------------------------------------------------
__device__ __forceinline__ void cp_async16(uint32_t s, const void* g) {
    asm volatile("cp.async.cg.shared.global [%0], [%1], 16;" :: "r"(s), "l"(g));
}
__device__ __forceinline__ void cp_commit() {
    asm volatile("cp.async.commit_group;" ::: "memory");
}
template <int N> __device__ __forceinline__ void cp_wait() {
    asm volatile("cp.async.wait_group %0;" :: "n"(N) : "memory");
}
__device__ __forceinline__ uint32_t smem_u32(const void* p) {
    uint32_t a;
    asm("{ .reg .u64 t; cvta.to.shared.u64 t, %1; cvt.u32.u64 %0, t; }"
        : "=r"(a) : "l"(p));
    return a;
}
__device__ __forceinline__ uint32_t f2tf32(float x) {
    uint32_t r;
    asm("cvt.rna.tf32.f32 %0, %1;" : "=r"(r) : "f"(x));
    return r;
}
__device__ __forceinline__ float roundtf(float x) {
    return __uint_as_float(f2tf32(x));
}
__device__ __forceinline__ void mma_tf32(float c[4],
    uint32_t a0, uint32_t a1, uint32_t a2, uint32_t a3,
    uint32_t b0, uint32_t b1)
{
    asm volatile(
        "mma.sync.aligned.m16n8k8.row.col.f32.tf32.tf32.f32 "
        "{%0,%1,%2,%3}, {%4,%5,%6,%7}, {%8,%9}, {%0,%1,%2,%3};"
        : "+f"(c[0]), "+f"(c[1]), "+f"(c[2]), "+f"(c[3])
        : "r"(a0), "r"(a1), "r"(a2), "r"(a3), "r"(b0), "r"(b1));
}

// ---------------------------------------------------------------------------
// x pre-pass: tf32 round + k-permute. One thread handles one 8-float group.
// ---------------------------------------------------------------------------
__global__ __launch_bounds__(256) void round_perm_kernel(
    const float* __restrict__ in, float* __restrict__ out)
{
    const size_t g = (size_t)blockIdx.x * 256 + threadIdx.x;   // 8-group index
    float4 a = ((const float4*)in)[2 * g];
    float4 b = ((const float4*)in)[2 * g + 1];
    float4 o0, o1;     // stored order: k0,k4,k1,k5 | k2,k6,k3,k7
    o0.x = roundtf(a.x); o0.y = roundtf(b.x);
    o0.z = roundtf(a.y); o0.w = roundtf(b.y);
    o1.x = roundtf(a.z); o1.y = roundtf(b.z);
    o1.z = roundtf(a.w); o1.w = roundtf(b.w);
    ((float4*)out)[2 * g]     = o0;
    ((float4*)out)[2 * g + 1] = o1;
}

// ---------------------------------------------------------------------------
// Weight transpose + tf32 round + k-permute: At[N, perm(K)] = round(A[K,N]^T)
// ---------------------------------------------------------------------------
__global__ __launch_bounds__(256) void transpose_kernel(
    const float* __restrict__ A, float* __restrict__ At, int R, int C)
{
    __shared__ float tile[32][33];
    const int c = blockIdx.x * 32 + threadIdx.x;
    const int r = blockIdx.y * 32 + threadIdx.y;
    #pragma unroll
    for (int i = 0; i < 32; i += 8)
        tile[threadIdx.y + i][threadIdx.x] = A[(size_t)(r + i) * C + c];
    __syncthreads();
    const int tc = blockIdx.y * 32 + threadIdx.x;          // k index
    const int tr = blockIdx.x * 32 + threadIdx.y;          // n index
    const int kp = (tc & ~7) + PERM_POS(tc & 7);
    #pragma unroll
    for (int i = 0; i < 32; i += 8)
        At[(size_t)(tr + i) * R + kp] = roundtf(tile[threadIdx.x][threadIdx.y + i]);
}

// ---------------------------------------------------------------------------
// tf32 mma.sync GEMM + bias: C[M,N] = A[M,K] @ BT[N,K]^T + bias[N]
// A, BT in k-permuted tf32 layout. CTA 128x256, 256 threads (8 warps, 2m x 4n),
// warp tile 64x64 = 4(m) x 8(n) m16n8k8. BK=32, 3-stage cp.async.
// SMEM row stride 40 floats -> LDS.64 fragment loads conflict-free.
// ---------------------------------------------------------------------------
#define GBM 128
#define GBN 256
#define GBK 32
#define GSTRIDE 40
#define A_TILE_FLOATS (128 * GSTRIDE)                 // 5120
#define B_TILE_FLOATS (256 * GSTRIDE)                 // 10240
#define STAGE_FLOATS  (A_TILE_FLOATS + B_TILE_FLOATS) // 15360
#define GEMM_SMEM     (3 * STAGE_FLOATS * 4)          // 184320

__device__ __forceinline__ void gemm_load_stage(
    const float* __restrict__ A, const float* __restrict__ BT, int K,
    uint32_t sa, uint32_t sb, int brow, int bcol, int k0, int tid)
{
    #pragma unroll
    for (int i = 0; i < 4; i++) {           // A: 128 rows x 8 chunks
        int idx = tid + i * 256;            // 0..1023
        int row = idx >> 3;
        int c = idx & 7;
        cp_async16(sa + (row * GSTRIDE + c * 4) * 4,
                   &A[(size_t)(brow + row) * K + k0 + c * 4]);
    }
    #pragma unroll
    for (int i = 0; i < 8; i++) {           // B^T: 256 n-rows x 8 chunks
        int idx = tid + i * 256;            // 0..2047
        int row = idx >> 3;
        int c = idx & 7;
        cp_async16(sb + (row * GSTRIDE + c * 4) * 4,
                   &BT[(size_t)(bcol + row) * K + k0 + c * 4]);
    }
}

template <bool ROUND_OUT, bool PERM_QK>
__global__ __launch_bounds__(256) void mma_gemm_bias(
    const float* __restrict__ A, const float* __restrict__ BT,
    const float* __restrict__ bias, float* __restrict__ C,
    int M, int N, int K)
{
    extern __shared__ float sm[];
    const int tid  = threadIdx.x;
    const int wid  = tid >> 5;
    const int lane = tid & 31;
    const int brow = blockIdx.y * GBM;
    const int bcol = blockIdx.x * GBN;
    const int warp_m = wid & 1;            // rows warp_m*64
    const int warp_n = wid >> 1;           // cols warp_n*64
    const int qr = lane >> 2;
    const int qc = lane & 3;

    const uint32_t smem_base = smem_u32(sm);

    float acc[4][8][4];
    #pragma unroll
    for (int mt = 0; mt < 4; mt++)
        #pragma unroll
        for (int nt = 0; nt < 8; nt++)
            #pragma unroll
            for (int i = 0; i < 4; i++)
                acc[mt][nt][i] = 0.0f;

    const int KT = K / GBK;

    #pragma unroll
    for (int s = 0; s < 3; s++) {
        uint32_t sa = smem_base + s * STAGE_FLOATS * 4;
        gemm_load_stage(A, BT, K, sa, sa + A_TILE_FLOATS * 4,
                        brow, bcol, s * GBK, tid);
        cp_commit();
    }

    int st = 0;
    for (int kt = 0; kt < KT; kt++) {
        cp_wait<2>();
        __syncthreads();

        const uint32_t* Au = (const uint32_t*)(sm + st * STAGE_FLOATS);
        const uint32_t* Bu = Au + A_TILE_FLOATS;

        uint2 aF[2][4][2], bF[2][8];
        // prime k8=0
        #pragma unroll
        for (int mt = 0; mt < 4; mt++) {
            const int rb = warp_m * 64 + mt * 16 + qr;
            aF[0][mt][0] = *(const uint2*)&Au[rb * GSTRIDE + 2 * qc];
            aF[0][mt][1] = *(const uint2*)&Au[(rb + 8) * GSTRIDE + 2 * qc];
        }
        #pragma unroll
        for (int nt = 0; nt < 8; nt++) {
            const int cb = warp_n * 64 + nt * 8 + qr;
            bF[0][nt] = *(const uint2*)&Bu[cb * GSTRIDE + 2 * qc];
        }

        #pragma unroll
        for (int k8 = 0; k8 < 4; k8++) {
            const int cur = k8 & 1, nxt = cur ^ 1;
            if (k8 < 3) {
                const int kk = (k8 + 1) * 8;
                #pragma unroll
                for (int mt = 0; mt < 4; mt++) {
                    const int rb = warp_m * 64 + mt * 16 + qr;
                    aF[nxt][mt][0] = *(const uint2*)&Au[rb * GSTRIDE + kk + 2 * qc];
                    aF[nxt][mt][1] = *(const uint2*)&Au[(rb + 8) * GSTRIDE + kk + 2 * qc];
                }
                #pragma unroll
                for (int nt = 0; nt < 8; nt++) {
                    const int cb = warp_n * 64 + nt * 8 + qr;
                    bF[nxt][nt] = *(const uint2*)&Bu[cb * GSTRIDE + kk + 2 * qc];
                }
            }
            #pragma unroll
            for (int nt = 0; nt < 8; nt++)
                #pragma unroll
                for (int mt = 0; mt < 4; mt++)
                    mma_tf32(acc[mt][nt],
                             aF[cur][mt][0].x, aF[cur][mt][1].x,
                             aF[cur][mt][0].y, aF[cur][mt][1].y,
                             bF[cur][nt].x, bF[cur][nt].y);
        }
        __syncthreads();

        const int lkt = kt + 3;
        if (lkt < KT) {
            const uint32_t sa = smem_base + st * STAGE_FLOATS * 4;
            gemm_load_stage(A, BT, K, sa, sa + A_TILE_FLOATS * 4,
                            brow, bcol, lkt * GBK, tid);
        }
        cp_commit();

        if (++st == 3) st = 0;
    }

    // Epilogue
    #pragma unroll
    for (int mt = 0; mt < 4; mt++) {
        #pragma unroll
        for (int half = 0; half < 2; half++) {
            const int row = brow + warp_m * 64 + mt * 16 + qr + half * 8;
            #pragma unroll
            for (int nt = 0; nt < 8; nt++) {
                const int col = bcol + warp_n * 64 + nt * 8 + 2 * qc;
                float vx = acc[mt][nt][half * 2 + 0] + bias[col + 0];
                float vy = acc[mt][nt][half * 2 + 1] + bias[col + 1];
                if (ROUND_OUT) { vx = roundtf(vx); vy = roundtf(vy); }
                float* crow = &C[(size_t)row * N];
                if (PERM_QK && col < 2 * D_) {
                    // Q/K region: store k-permuted (feeds flash fragment LDS.64)
                    const int blk = col & ~7;
                    crow[blk + PERM_POS(2 * qc)]     = vx;
                    crow[blk + PERM_POS(2 * qc + 1)] = vy;
                } else {
                    float2 o; o.x = vx; o.y = vy;
                    *(float2*)&crow[col] = o;
                }
            }
        }
    }
}

// ---------------------------------------------------------------------------
// Tensor-core flash attention (tf32 mma, causal, register softmax).
// CTA: 128 q-rows, 256 threads (8 warps x 16 rows). KV tiles of 64,
// double-buffered cp.async. Strides 136 -> LDS.64 Q/K fragments conflict-free.
// Q/K columns arrive k-permuted from GEMM1's epilogue; V columns normal.
// ---------------------------------------------------------------------------
#define FBQ  128
#define QSTR 136
#define KSTR 136
#define VSTR 136
#define Q_FLOATS    (FBQ * QSTR)                 // 17408
#define KV_STAGE_FL (64 * KSTR + 64 * VSTR)      // 17408
#define FLASH_SMEM  ((Q_FLOATS + 2 * KV_STAGE_FL) * 4)   // 208896

__device__ __forceinline__ void load_kv_tile(
    uint32_t kbase, uint32_t vbase, size_t rowbase, int j0, int qcol, int tid)
{
    #pragma unroll
    for (int i = 0; i < 8; i++) {
        int idx = tid + i * 256;          // 0..2047
        int r = idx >> 5;                 // 0..63
        int c4 = idx & 31;
        cp_async16(kbase + (r * KSTR + c4 * 4) * 4,
                   &g_qkv[(rowbase + j0 + r) * (size_t)QKV_N + qcol + D_ + c4 * 4]);
    }
    #pragma unroll
    for (int i = 0; i < 8; i++) {
        int idx = tid + i * 256;
        int r = idx >> 5;
        int c4 = idx & 31;
        cp_async16(vbase + (r * VSTR + c4 * 4) * 4,
                   &g_qkv[(rowbase + j0 + r) * (size_t)QKV_N + qcol + 2 * D_ + c4 * 4]);
    }
}

__global__ __launch_bounds__(256, 1) void flash_mma_kernel()
{
    extern __shared__ float sm[];
    const int qi  = (gridDim.x - 1) - blockIdx.x;   // big q-blocks first
    const int q0  = qi * FBQ;
    const int h   = blockIdx.y;
    const int b   = blockIdx.z;
    const int tid = threadIdx.x;
    const int lane = tid & 31;
    const int wid  = tid >> 5;
    const int qr = lane >> 2;
    const int qc = lane & 3;

    const size_t rowbase = (size_t)b * T_;
    const int qcol = h * DH;
    const float SCALE = 0.08838834764831845f;   // 1/sqrt(128)

    // Q tile -> smem (k-permuted data copied verbatim)
    #pragma unroll
    for (int i = 0; i < 16; i++) {
        int idx = tid + i * 256;          // 0..4095 float4
        int r = idx >> 5;
        int c4 = idx & 31;
        *(float4*)&sm[r * QSTR + c4 * 4] =
            *(const float4*)&g_qkv[(rowbase + q0 + r) * (size_t)QKV_N + qcol + c4 * 4];
    }

    const uint32_t smem_base = smem_u32(sm);
    const int ntile = 2 * qi + 2;

    {
        uint32_t s0 = smem_base + Q_FLOATS * 4;
        load_kv_tile(s0, s0 + 64 * KSTR * 4, rowbase, 0, qcol, tid);
        cp_commit();
        if (ntile > 1) {
            uint32_t s1 = smem_base + (Q_FLOATS + KV_STAGE_FL) * 4;
            load_kv_tile(s1, s1 + 64 * KSTR * 4, rowbase, 64, qcol, tid);
        }
        cp_commit();
    }

    float oacc[16][4];
    #pragma unroll
    for (int n = 0; n < 16; n++)
        #pragma unroll
        for (int i = 0; i < 4; i++) oacc[n][i] = 0.0f;
    float mrow0 = -3.0e38f, mrow1 = -3.0e38f;
    float lrow0 = 0.0f, lrow1 = 0.0f;

    const int mloc = wid * 16;
    const uint32_t* Qu = (const uint32_t*)sm;
    const int s1l = (lane & ~3) | (qc >> 1);
    const int s2l = s1l | 2;
    const bool odd = qc & 1;

    for (int t = 0; t < ntile; t++) {
        cp_wait<1>();
        __syncthreads();

        const uint32_t* Ku = (const uint32_t*)(sm + Q_FLOATS + (t & 1) * KV_STAGE_FL);
        const uint32_t* Vu = Ku + 64 * KSTR;

        // ---- S = Q @ K^T (LDS.64 fragments via k-permuted layout) ----
        float sacc[8][4];
        #pragma unroll
        for (int n = 0; n < 8; n++)
            #pragma unroll
            for (int i = 0; i < 4; i++) sacc[n][i] = 0.0f;

        #pragma unroll
        for (int k8 = 0; k8 < 16; k8++) {
            const int kk = k8 * 8;
            uint2 qa = *(const uint2*)&Qu[(mloc + qr    ) * QSTR + kk + 2 * qc];
            uint2 qb = *(const uint2*)&Qu[(mloc + qr + 8) * QSTR + kk + 2 * qc];
            #pragma unroll
            for (int nt = 0; nt < 8; nt++) {
                uint2 kb = *(const uint2*)&Ku[(nt * 8 + qr) * KSTR + kk + 2 * qc];
                mma_tf32(sacc[nt], qa.x, qb.x, qa.y, qb.y, kb.x, kb.y);
            }
        }

        // ---- causal mask ----
        if (t >= ntile - 2) {
            const int j0 = t * 64;
            const int rg0 = q0 + mloc + qr;
            const int rg1 = rg0 + 8;
            #pragma unroll
            for (int nt = 0; nt < 8; nt++) {
                const int cg = j0 + nt * 8 + 2 * qc;
                if (cg     > rg0) sacc[nt][0] = -1.0e30f;
                if (cg + 1 > rg0) sacc[nt][1] = -1.0e30f;
                if (cg     > rg1) sacc[nt][2] = -1.0e30f;
                if (cg + 1 > rg1) sacc[nt][3] = -1.0e30f;
            }
        }

        // ---- online softmax ----
        float mx0 = -3.0e38f, mx1 = -3.0e38f;
        #pragma unroll
        for (int nt = 0; nt < 8; nt++) {
            mx0 = fmaxf(mx0, fmaxf(sacc[nt][0], sacc[nt][1]));
            mx1 = fmaxf(mx1, fmaxf(sacc[nt][2], sacc[nt][3]));
        }
        mx0 = fmaxf(mx0, __shfl_xor_sync(0xFFFFFFFFu, mx0, 1));
        mx0 = fmaxf(mx0, __shfl_xor_sync(0xFFFFFFFFu, mx0, 2));
        mx1 = fmaxf(mx1, __shfl_xor_sync(0xFFFFFFFFu, mx1, 1));
        mx1 = fmaxf(mx1, __shfl_xor_sync(0xFFFFFFFFu, mx1, 2));
        const float mn0 = fmaxf(mrow0, mx0);
        const float mn1 = fmaxf(mrow1, mx1);
        const float al0 = __expf((mrow0 - mn0) * SCALE);
        const float al1 = __expf((mrow1 - mn1) * SCALE);
        mrow0 = mn0; mrow1 = mn1;

        uint32_t pacc[8][4];
        float ps0 = 0.0f, ps1 = 0.0f;
        #pragma unroll
        for (int nt = 0; nt < 8; nt++) {
            float p0 = __expf((sacc[nt][0] - mn0) * SCALE);
            float p1 = __expf((sacc[nt][1] - mn0) * SCALE);
            float p2 = __expf((sacc[nt][2] - mn1) * SCALE);
            float p3 = __expf((sacc[nt][3] - mn1) * SCALE);
            ps0 += p0 + p1;
            ps1 += p2 + p3;
            pacc[nt][0] = f2tf32(p0);
            pacc[nt][1] = f2tf32(p1);
            pacc[nt][2] = f2tf32(p2);
            pacc[nt][3] = f2tf32(p3);
        }
        ps0 += __shfl_xor_sync(0xFFFFFFFFu, ps0, 1);
        ps0 += __shfl_xor_sync(0xFFFFFFFFu, ps0, 2);
        ps1 += __shfl_xor_sync(0xFFFFFFFFu, ps1, 1);
        ps1 += __shfl_xor_sync(0xFFFFFFFFu, ps1, 2);
        lrow0 = lrow0 * al0 + ps0;
        lrow1 = lrow1 * al1 + ps1;

        #pragma unroll
        for (int n = 0; n < 16; n++) {
            oacc[n][0] *= al0; oacc[n][1] *= al0;
            oacc[n][2] *= al1; oacc[n][3] *= al1;
        }

        // ---- O += P @ V ----
        #pragma unroll
        for (int ks = 0; ks < 8; ks++) {
            uint32_t x0 = __shfl_sync(0xFFFFFFFFu, pacc[ks][0], s1l);
            uint32_t x1 = __shfl_sync(0xFFFFFFFFu, pacc[ks][1], s1l);
            uint32_t x2 = __shfl_sync(0xFFFFFFFFu, pacc[ks][2], s1l);
            uint32_t x3 = __shfl_sync(0xFFFFFFFFu, pacc[ks][3], s1l);
            uint32_t y0 = __shfl_sync(0xFFFFFFFFu, pacc[ks][0], s2l);
            uint32_t y1 = __shfl_sync(0xFFFFFFFFu, pacc[ks][1], s2l);
            uint32_t y2 = __shfl_sync(0xFFFFFFFFu, pacc[ks][2], s2l);
            uint32_t y3 = __shfl_sync(0xFFFFFFFFu, pacc[ks][3], s2l);
            uint32_t a0 = odd ? x1 : x0;
            uint32_t a1 = odd ? x3 : x2;
            uint32_t a2 = odd ? y1 : y0;
            uint32_t a3 = odd ? y3 : y2;
            #pragma unroll
            for (int ntd = 0; ntd < 16; ntd++) {
                uint32_t b0 = Vu[(ks * 8 + qc    ) * VSTR + ntd * 8 + qr];
                uint32_t b1 = Vu[(ks * 8 + qc + 4) * VSTR + ntd * 8 + qr];
                mma_tf32(oacc[ntd], a0, a1, a2, a3, b0, b1);
            }
        }

        __syncthreads();
        if (t + 2 < ntile) {
            uint32_t sb = smem_base + (Q_FLOATS + (t & 1) * KV_STAGE_FL) * 4;
            load_kv_tile(sb, sb + 64 * KSTR * 4, rowbase, (t + 2) * 64, qcol, tid);
        }
        cp_commit();
    }

    // ---- epilogue: normalize, tf32-round, store k-PERMUTED (feeds GEMM2) ----
    const float li0 = 1.0f / lrow0;
    const float li1 = 1.0f / lrow1;
    const int r0 = q0 + mloc + qr;
    const int r1 = r0 + 8;
    const int p0 = PERM_POS(2 * qc);
    const int p1 = PERM_POS(2 * qc + 1);
    #pragma unroll
    for (int ntd = 0; ntd < 16; ntd++) {
        const int blk = qcol + ntd * 8;
        float* row0 = &g_o[(rowbase + r0) * (size_t)D_ + blk];
        float* row1 = &g_o[(rowbase + r1) * (size_t)D_ + blk];
        row0[p0] = roundtf(oacc[ntd][0] * li0);
        row0[p1] = roundtf(oacc[ntd][1] * li0);
        row1[p0] = roundtf(oacc[ntd][2] * li1);
        row1[p1] = roundtf(oacc[ntd][3] * li1);
    }
}

// ---------------------------------------------------------------------------
// Launch
// ---------------------------------------------------------------------------
extern "C" void kernel_launch(void* const* d_in, const int* in_sizes, int n_in,
                              void* d_out, int out_size)
{
    (void)in_sizes; (void)n_in; (void)out_size;
    const float* x    = (const float*)d_in[0];
    const float* Wqkv = (const float*)d_in[1];
    const float* bqkv = (const float*)d_in[2];
    const float* Wout = (const float*)d_in[3];
    const float* bout = (const float*)d_in[4];
    float* out = (float*)d_out;

    static float *qkv_ptr = nullptr, *o_ptr = nullptr, *xr_ptr = nullptr;
    static float *wqkvT_ptr = nullptr, *woutT_ptr = nullptr;
    static bool init_done = false;
    if (!init_done) {
        // First call is the (uncaptured) correctness run; these immediate host
        // APIs never land inside graph capture.
        cudaFuncSetAttribute(flash_mma_kernel,
                             cudaFuncAttributeMaxDynamicSharedMemorySize,
                             FLASH_SMEM);
        cudaFuncSetAttribute(mma_gemm_bias<true, true>,
                             cudaFuncAttributeMaxDynamicSharedMemorySize,
                             GEMM_SMEM);
        cudaFuncSetAttribute(mma_gemm_bias<false, false>,
                             cudaFuncAttributeMaxDynamicSharedMemorySize,
                             GEMM_SMEM);
        void* p;
        cudaGetSymbolAddress(&p, g_qkv);   qkv_ptr   = (float*)p;
        cudaGetSymbolAddress(&p, g_o);     o_ptr     = (float*)p;
        cudaGetSymbolAddress(&p, g_xr);    xr_ptr    = (float*)p;
        cudaGetSymbolAddress(&p, g_WqkvT); wqkvT_ptr = (float*)p;
        cudaGetSymbolAddress(&p, g_WoutT); woutT_ptr = (float*)p;
        init_done = true;
    }

    // 0) pre-pass: x -> tf32+permuted copy; weights -> transposed+tf32+permuted
    round_perm_kernel<<<(MROWS * (size_t)D_ / 8) / 256, 256>>>(x, xr_ptr);
    transpose_kernel<<<dim3(QKV_N / 32, D_ / 32), dim3(32, 8)>>>(Wqkv, wqkvT_ptr, D_, QKV_N);
    transpose_kernel<<<dim3(D_ / 32, D_ / 32), dim3(32, 8)>>>(Wout, woutT_ptr, D_, D_);

    // 1) QKV = x @ Wqkv + bqkv (tf32 mma; Q/K cols permuted for flash)
    mma_gemm_bias<true, true><<<dim3(QKV_N / GBN, MROWS / GBM), 256, GEMM_SMEM>>>(
        xr_ptr, wqkvT_ptr, bqkv, qkv_ptr, MROWS, QKV_N, D_);

    // 2) causal flash attention (tensor cores) -> g_o (tf32, permuted)
    flash_mma_kernel<<<dim3(T_ / FBQ, H_, B_), 256, FLASH_SMEM>>>();

    // 3) out = g_o @ Wout + bout (tf32 mma, fp32 output)
    mma_gemm_bias<false, false><<<dim3(D_ / GBN, MROWS / GBM), 256, GEMM_SMEM>>>(
        o_ptr, woutT_ptr, bout, out, MROWS, D_, D_);
}

// round 6
// speedup vs baseline: 1.9622x; 1.9622x over previous
#include <cuda_runtime.h>
#include <cuda_fp16.h>
#include <math.h>
#include <stdint.h>

#define B_  2
#define T_  2048
#define D_  2048
#define H_  16
#define DH  128
#define MROWS (B_*T_)          // 4096
#define QKV_N (3*D_)           // 6144

// Scratch (device globals — no allocation allowed); all fp16 operands
__device__ __half g_qkv[(size_t)MROWS * QKV_N];    // 50 MB
__device__ __half g_o[(size_t)MROWS * D_];         // 16 MB
__device__ __half g_xh[(size_t)MROWS * D_];        // 16 MB
__device__ __half g_WqkvT[(size_t)QKV_N * D_];     // 25 MB ([N,K] K-contig)
__device__ __half g_WoutT[(size_t)D_ * D_];        // 8 MB

// ---------------------------------------------------------------------------
// Helpers
// ---------------------------------------------------------------------------
__device__ __forceinline__ void cp_async16(uint32_t s, const void* g) {
    asm volatile("cp.async.cg.shared.global [%0], [%1], 16;" :: "r"(s), "l"(g));
}
__device__ __forceinline__ void cp_commit() {
    asm volatile("cp.async.commit_group;" ::: "memory");
}
template <int N> __device__ __forceinline__ void cp_wait() {
    asm volatile("cp.async.wait_group %0;" :: "n"(N) : "memory");
}
__device__ __forceinline__ uint32_t smem_u32(const void* p) {
    uint32_t a;
    asm("{ .reg .u64 t; cvta.to.shared.u64 t, %1; cvt.u32.u64 %0, t; }"
        : "=r"(a) : "l"(p));
    return a;
}
__device__ __forceinline__ void ldm_x4(uint32_t& r0, uint32_t& r1,
                                       uint32_t& r2, uint32_t& r3, uint32_t a) {
    asm volatile("ldmatrix.sync.aligned.m8n8.x4.shared.b16 {%0,%1,%2,%3}, [%4];"
                 : "=r"(r0), "=r"(r1), "=r"(r2), "=r"(r3) : "r"(a));
}
__device__ __forceinline__ void ldm_x4_t(uint32_t& r0, uint32_t& r1,
                                         uint32_t& r2, uint32_t& r3, uint32_t a) {
    asm volatile("ldmatrix.sync.aligned.m8n8.x4.trans.shared.b16 {%0,%1,%2,%3}, [%4];"
                 : "=r"(r0), "=r"(r1), "=r"(r2), "=r"(r3) : "r"(a));
}
__device__ __forceinline__ void mma_f16(float c[4],
    uint32_t a0, uint32_t a1, uint32_t a2, uint32_t a3,
    uint32_t b0, uint32_t b1)
{
    asm volatile(
        "mma.sync.aligned.m16n8k16.row.col.f32.f16.f16.f32 "
        "{%0,%1,%2,%3}, {%4,%5,%6,%7}, {%8,%9}, {%0,%1,%2,%3};"
        : "+f"(c[0]), "+f"(c[1]), "+f"(c[2]), "+f"(c[3])
        : "r"(a0), "r"(a1), "r"(a2), "r"(a3), "r"(b0), "r"(b1));
}
__device__ __forceinline__ uint32_t pack_h2(float x, float y) {
    __half2 h = __floats2half2_rn(x, y);
    return *(uint32_t*)&h;
}

// ---------------------------------------------------------------------------
// x pre-pass: fp32 -> fp16. Each thread converts 8 floats.
// ---------------------------------------------------------------------------
__global__ __launch_bounds__(256) void f2h_kernel(
    const float* __restrict__ in, __half* __restrict__ out)
{
    const size_t i = (size_t)blockIdx.x * 256 + threadIdx.x;
    float4 a = ((const float4*)in)[2 * i];
    float4 b = ((const float4*)in)[2 * i + 1];
    uint4 u;
    u.x = pack_h2(a.x, a.y); u.y = pack_h2(a.z, a.w);
    u.z = pack_h2(b.x, b.y); u.w = pack_h2(b.z, b.w);
    ((uint4*)out)[i] = u;
}

// ---------------------------------------------------------------------------
// Weight transpose + fp16: At[N,K] = h(A[K,N]^T)
// ---------------------------------------------------------------------------
__global__ __launch_bounds__(256) void transpose_kernel(
    const float* __restrict__ A, __half* __restrict__ At, int R, int C)
{
    __shared__ float tile[32][33];
    const int c = blockIdx.x * 32 + threadIdx.x;
    const int r = blockIdx.y * 32 + threadIdx.y;
    #pragma unroll
    for (int i = 0; i < 32; i += 8)
        tile[threadIdx.y + i][threadIdx.x] = A[(size_t)(r + i) * C + c];
    __syncthreads();
    const int tc = blockIdx.y * 32 + threadIdx.x;
    const int tr = blockIdx.x * 32 + threadIdx.y;
    #pragma unroll
    for (int i = 0; i < 32; i += 8)
        At[(size_t)(tr + i) * R + tc] = __float2half_rn(tile[threadIdx.x][threadIdx.y + i]);
}

// ---------------------------------------------------------------------------
// fp16 mma.sync GEMM + bias: C[M,N] = A[M,K] @ BT[N,K]^T + bias[N]
// CTA 128x256, 512 threads (16 warps, 4m x 4n), warp tile 32x64.
// BK=64 halves, 3-stage cp.async, smem row stride 72 halves (ldmatrix
// conflict-free: 144B rows, (9r+c) mod 8 distinct).
// ---------------------------------------------------------------------------
#define GBM 128
#define GBN 256
#define GBK 64
#define STRH 72
#define A_TILE_H (128 * STRH)                 // 9216 halves
#define B_TILE_H (256 * STRH)                 // 18432
#define STAGE_B  ((A_TILE_H + B_TILE_H) * 2)  // 55296 bytes
#define GEMM_SMEM (3 * STAGE_B)               // 165888

__device__ __forceinline__ void gemm_load_stage(
    const __half* __restrict__ A, const __half* __restrict__ BT, int K,
    uint32_t sa, uint32_t sb, int brow, int bcol, int k0, int tid)
{
    #pragma unroll
    for (int i = 0; i < 2; i++) {           // A: 128 rows x 8 chunks
        int idx = tid + i * 512;            // 0..1023
        int row = idx >> 3;
        int c = idx & 7;
        cp_async16(sa + (row * STRH + c * 8) * 2,
                   &A[(size_t)(brow + row) * K + k0 + c * 8]);
    }
    #pragma unroll
    for (int i = 0; i < 4; i++) {           // B^T: 256 n-rows x 8 chunks
        int idx = tid + i * 512;            // 0..2047
        int row = idx >> 3;
        int c = idx & 7;
        cp_async16(sb + (row * STRH + c * 8) * 2,
                   &BT[(size_t)(bcol + row) * K + k0 + c * 8]);
    }
}

template <bool OUT_HALF>
__global__ __launch_bounds__(512) void mma_gemm_bias(
    const __half* __restrict__ A, const __half* __restrict__ BT,
    const float* __restrict__ bias, void* __restrict__ Cv,
    int M, int N, int K)
{
    extern __shared__ char sm[];
    const int tid  = threadIdx.x;
    const int wid  = tid >> 5;
    const int lane = tid & 31;
    const int brow = blockIdx.y * GBM;
    const int bcol = blockIdx.x * GBN;
    const int warp_m = wid & 3;            // rows warp_m*32
    const int warp_n = wid >> 2;           // cols warp_n*64
    const int qr = lane >> 2;
    const int qc = lane & 3;

    const uint32_t base = smem_u32(sm);

    float acc[2][8][4];
    #pragma unroll
    for (int mt = 0; mt < 2; mt++)
        #pragma unroll
        for (int nt = 0; nt < 8; nt++)
            #pragma unroll
            for (int i = 0; i < 4; i++)
                acc[mt][nt][i] = 0.0f;

    const int KT = K / GBK;   // 32

    #pragma unroll
    for (int s = 0; s < 3; s++) {
        uint32_t sa = base + s * STAGE_B;
        gemm_load_stage(A, BT, K, sa, sa + A_TILE_H * 2, brow, bcol, s * GBK, tid);
        cp_commit();
    }

    // per-lane ldmatrix offsets (halves)
    const int la_off = (warp_m * 32 + (lane & 15)) * STRH + (lane >> 4) * 8;
    const int g = lane >> 3;
    const int lb_off = (warp_n * 64 + ((g & 2) ? 8 : 0) + (lane & 7)) * STRH
                     + (g & 1) * 8;

    int st = 0;
    for (int kt = 0; kt < KT; kt++) {
        cp_wait<2>();
        __syncthreads();

        const uint32_t sa = base + st * STAGE_B;
        const uint32_t sb = sa + A_TILE_H * 2;

        #pragma unroll
        for (int k16 = 0; k16 < 4; k16++) {
            const int ko = k16 * 16;
            uint32_t a0[4], a1[4];
            ldm_x4(a0[0], a0[1], a0[2], a0[3], sa + (la_off + ko) * 2);
            ldm_x4(a1[0], a1[1], a1[2], a1[3], sa + (la_off + 16 * STRH + ko) * 2);
            #pragma unroll
            for (int ntp = 0; ntp < 4; ntp++) {
                uint32_t b0, b1, b2, b3;
                ldm_x4(b0, b1, b2, b3, sb + (lb_off + ntp * 16 * STRH + ko) * 2);
                mma_f16(acc[0][2 * ntp    ], a0[0], a0[1], a0[2], a0[3], b0, b1);
                mma_f16(acc[1][2 * ntp    ], a1[0], a1[1], a1[2], a1[3], b0, b1);
                mma_f16(acc[0][2 * ntp + 1], a0[0], a0[1], a0[2], a0[3], b2, b3);
                mma_f16(acc[1][2 * ntp + 1], a1[0], a1[1], a1[2], a1[3], b2, b3);
            }
        }
        __syncthreads();

        const int lkt = kt + 3;
        if (lkt < KT) {
            const uint32_t pa = base + st * STAGE_B;
            gemm_load_stage(A, BT, K, pa, pa + A_TILE_H * 2, brow, bcol, lkt * GBK, tid);
        }
        cp_commit();

        if (++st == 3) st = 0;
    }

    // Epilogue
    #pragma unroll
    for (int mt = 0; mt < 2; mt++) {
        const int row0 = brow + warp_m * 32 + mt * 16 + qr;
        #pragma unroll
        for (int nt = 0; nt < 8; nt++) {
            const int col = bcol + warp_n * 64 + nt * 8 + 2 * qc;
            const float2 bb = *(const float2*)&bias[col];
            const float vx = acc[mt][nt][0] + bb.x;
            const float vy = acc[mt][nt][1] + bb.y;
            const float wx = acc[mt][nt][2] + bb.x;
            const float wy = acc[mt][nt][3] + bb.y;
            if (OUT_HALF) {
                __half* C = (__half*)Cv;
                *(uint32_t*)&C[(size_t)row0 * N + col]       = pack_h2(vx, vy);
                *(uint32_t*)&C[(size_t)(row0 + 8) * N + col] = pack_h2(wx, wy);
            } else {
                float* C = (float*)Cv;
                float2 o0; o0.x = vx; o0.y = vy;
                float2 o1; o1.x = wx; o1.y = wy;
                *(float2*)&C[(size_t)row0 * N + col]       = o0;
                *(float2*)&C[(size_t)(row0 + 8) * N + col] = o1;
            }
        }
    }
}

// ---------------------------------------------------------------------------
// fp16 tensor-core flash attention (causal, register softmax, ldmatrix).
// CTA: 128 q-rows, 256 threads (8 warps x 16 rows). KV tiles of 64,
// double-buffered cp.async. Row stride 136 halves (272B = 17*16B: ldmatrix
// conflict-free). P-fragments packed directly from S accumulators (fp16
// C-layout == A-layout; no shuffles). V via ldmatrix.trans.
// ---------------------------------------------------------------------------
#define FBQ   128
#define FSTR  136
#define Q_BYTES     (128 * FSTR * 2)          // 34816
#define KV_TILE_B   (64 * FSTR * 2)           // 17408
#define KV_STAGE_B  (2 * KV_TILE_B)           // 34816
#define FLASH_SMEM  (Q_BYTES + 2 * KV_STAGE_B)  // 104448

__device__ __forceinline__ void load_kv_tile(
    uint32_t kbase, uint32_t vbase, size_t rowbase, int j0, int qcol, int tid)
{
    #pragma unroll
    for (int i = 0; i < 4; i++) {
        int idx = tid + i * 256;          // 0..1023
        int r = idx >> 4;                 // 0..63
        int c = idx & 15;
        cp_async16(kbase + (r * FSTR + c * 8) * 2,
                   &g_qkv[(rowbase + j0 + r) * (size_t)QKV_N + qcol + D_ + c * 8]);
    }
    #pragma unroll
    for (int i = 0; i < 4; i++) {
        int idx = tid + i * 256;
        int r = idx >> 4;
        int c = idx & 15;
        cp_async16(vbase + (r * FSTR + c * 8) * 2,
                   &g_qkv[(rowbase + j0 + r) * (size_t)QKV_N + qcol + 2 * D_ + c * 8]);
    }
}

__global__ __launch_bounds__(256, 2) void flash_mma_kernel()
{
    extern __shared__ char smc[];
    const int qi  = (gridDim.x - 1) - blockIdx.x;   // big q-blocks first
    const int q0  = qi * FBQ;
    const int h   = blockIdx.y;
    const int b   = blockIdx.z;
    const int tid = threadIdx.x;
    const int lane = tid & 31;
    const int wid  = tid >> 5;
    const int qr = lane >> 2;
    const int qc = lane & 3;

    const size_t rowbase = (size_t)b * T_;
    const int qcol = h * DH;
    const float SCALE = 0.08838834764831845f;   // 1/sqrt(128)

    const uint32_t base = smem_u32(smc);
    const uint32_t Qs = base;
    const int ntile = 2 * qi + 2;

    // Q tile + KV tile 0 -> group 0; KV tile 1 -> group 1
    #pragma unroll
    for (int i = 0; i < 8; i++) {
        int idx = tid + i * 256;          // 0..2047
        int r = idx >> 4;
        int c = idx & 15;
        cp_async16(Qs + (r * FSTR + c * 8) * 2,
                   &g_qkv[(rowbase + q0 + r) * (size_t)QKV_N + qcol + c * 8]);
    }
    {
        uint32_t s0 = base + Q_BYTES;
        load_kv_tile(s0, s0 + KV_TILE_B, rowbase, 0, qcol, tid);
        cp_commit();
        if (ntile > 1) {
            uint32_t s1 = base + Q_BYTES + KV_STAGE_B;
            load_kv_tile(s1, s1 + KV_TILE_B, rowbase, 64, qcol, tid);
        }
        cp_commit();
    }

    float oacc[16][4];
    #pragma unroll
    for (int n = 0; n < 16; n++)
        #pragma unroll
        for (int i = 0; i < 4; i++) oacc[n][i] = 0.0f;
    float mrow0 = -3.0e38f, mrow1 = -3.0e38f;
    float lrow0 = 0.0f, lrow1 = 0.0f;

    const int mloc = wid * 16;
    const int g = lane >> 3;
    // per-lane ldmatrix offsets (halves)
    const int lq_off = (mloc + (lane & 15)) * FSTR + (lane >> 4) * 8;
    const int lk_off = (((g & 2) ? 8 : 0) + (lane & 7)) * FSTR + (g & 1) * 8;
    const int lv_off = ((g & 1) * 8 + (lane & 7)) * FSTR + ((g & 2) ? 8 : 0);

    for (int t = 0; t < ntile; t++) {
        cp_wait<1>();
        __syncthreads();

        const uint32_t Ks = base + Q_BYTES + (t & 1) * KV_STAGE_B;
        const uint32_t Vs = Ks + KV_TILE_B;

        // ---- S = Q @ K^T ----
        float sacc[8][4];
        #pragma unroll
        for (int n = 0; n < 8; n++)
            #pragma unroll
            for (int i = 0; i < 4; i++) sacc[n][i] = 0.0f;

        #pragma unroll
        for (int k16 = 0; k16 < 8; k16++) {
            const int ko = k16 * 16;
            uint32_t qa0, qa1, qa2, qa3;
            ldm_x4(qa0, qa1, qa2, qa3, Qs + (lq_off + ko) * 2);
            #pragma unroll
            for (int ntp = 0; ntp < 4; ntp++) {
                uint32_t b0, b1, b2, b3;
                ldm_x4(b0, b1, b2, b3, Ks + (lk_off + ntp * 16 * FSTR + ko) * 2);
                mma_f16(sacc[2 * ntp    ], qa0, qa1, qa2, qa3, b0, b1);
                mma_f16(sacc[2 * ntp + 1], qa0, qa1, qa2, qa3, b2, b3);
            }
        }

        // ---- causal mask (only last 2 tiles touch the diagonal) ----
        if (t >= ntile - 2) {
            const int j0 = t * 64;
            const int rg0 = q0 + mloc + qr;
            const int rg1 = rg0 + 8;
            #pragma unroll
            for (int nt = 0; nt < 8; nt++) {
                const int cg = j0 + nt * 8 + 2 * qc;
                if (cg     > rg0) sacc[nt][0] = -1.0e30f;
                if (cg + 1 > rg0) sacc[nt][1] = -1.0e30f;
                if (cg     > rg1) sacc[nt][2] = -1.0e30f;
                if (cg + 1 > rg1) sacc[nt][3] = -1.0e30f;
            }
        }

        // ---- online softmax (per-row, quad lanes) ----
        float mx0 = -3.0e38f, mx1 = -3.0e38f;
        #pragma unroll
        for (int nt = 0; nt < 8; nt++) {
            mx0 = fmaxf(mx0, fmaxf(sacc[nt][0], sacc[nt][1]));
            mx1 = fmaxf(mx1, fmaxf(sacc[nt][2], sacc[nt][3]));
        }
        mx0 = fmaxf(mx0, __shfl_xor_sync(0xFFFFFFFFu, mx0, 1));
        mx0 = fmaxf(mx0, __shfl_xor_sync(0xFFFFFFFFu, mx0, 2));
        mx1 = fmaxf(mx1, __shfl_xor_sync(0xFFFFFFFFu, mx1, 1));
        mx1 = fmaxf(mx1, __shfl_xor_sync(0xFFFFFFFFu, mx1, 2));
        const float mn0 = fmaxf(mrow0, mx0);
        const float mn1 = fmaxf(mrow1, mx1);
        const float al0 = __expf((mrow0 - mn0) * SCALE);
        const float al1 = __expf((mrow1 - mn1) * SCALE);
        mrow0 = mn0; mrow1 = mn1;

        float ps0 = 0.0f, ps1 = 0.0f;
        #pragma unroll
        for (int nt = 0; nt < 8; nt++) {
            sacc[nt][0] = __expf((sacc[nt][0] - mn0) * SCALE);
            sacc[nt][1] = __expf((sacc[nt][1] - mn0) * SCALE);
            sacc[nt][2] = __expf((sacc[nt][2] - mn1) * SCALE);
            sacc[nt][3] = __expf((sacc[nt][3] - mn1) * SCALE);
            ps0 += sacc[nt][0] + sacc[nt][1];
            ps1 += sacc[nt][2] + sacc[nt][3];
        }
        ps0 += __shfl_xor_sync(0xFFFFFFFFu, ps0, 1);
        ps0 += __shfl_xor_sync(0xFFFFFFFFu, ps0, 2);
        ps1 += __shfl_xor_sync(0xFFFFFFFFu, ps1, 1);
        ps1 += __shfl_xor_sync(0xFFFFFFFFu, ps1, 2);
        lrow0 = lrow0 * al0 + ps0;
        lrow1 = lrow1 * al1 + ps1;

        #pragma unroll
        for (int n = 0; n < 16; n++) {
            oacc[n][0] *= al0; oacc[n][1] *= al0;
            oacc[n][2] *= al1; oacc[n][3] *= al1;
        }

        // ---- P fragments: direct pack (C-layout == A-layout in fp16) ----
        uint32_t pA[4][4];
        #pragma unroll
        for (int j = 0; j < 4; j++) {
            pA[j][0] = pack_h2(sacc[2 * j][0],     sacc[2 * j][1]);
            pA[j][1] = pack_h2(sacc[2 * j][2],     sacc[2 * j][3]);
            pA[j][2] = pack_h2(sacc[2 * j + 1][0], sacc[2 * j + 1][1]);
            pA[j][3] = pack_h2(sacc[2 * j + 1][2], sacc[2 * j + 1][3]);
        }

        // ---- O += P @ V  (V^T fragments via ldmatrix.trans) ----
        #pragma unroll
        for (int j = 0; j < 4; j++) {
            #pragma unroll
            for (int ntp = 0; ntp < 8; ntp++) {
                uint32_t b0, b1, b2, b3;
                ldm_x4_t(b0, b1, b2, b3,
                         Vs + (lv_off + j * 16 * FSTR + ntp * 16) * 2);
                mma_f16(oacc[2 * ntp    ], pA[j][0], pA[j][1], pA[j][2], pA[j][3], b0, b1);
                mma_f16(oacc[2 * ntp + 1], pA[j][0], pA[j][1], pA[j][2], pA[j][3], b2, b3);
            }
        }

        __syncthreads();
        if (t + 2 < ntile) {
            uint32_t sb = base + Q_BYTES + (t & 1) * KV_STAGE_B;
            load_kv_tile(sb, sb + KV_TILE_B, rowbase, (t + 2) * 64, qcol, tid);
        }
        cp_commit();
    }

    // ---- epilogue: normalize, fp16 store (feeds out-proj GEMM) ----
    const float li0 = 1.0f / lrow0;
    const float li1 = 1.0f / lrow1;
    const int r0 = q0 + mloc + qr;
    const int r1 = r0 + 8;
    #pragma unroll
    for (int ntd = 0; ntd < 16; ntd++) {
        const int col = qcol + ntd * 8 + 2 * qc;
        *(uint32_t*)&g_o[(rowbase + r0) * (size_t)D_ + col] =
            pack_h2(oacc[ntd][0] * li0, oacc[ntd][1] * li0);
        *(uint32_t*)&g_o[(rowbase + r1) * (size_t)D_ + col] =
            pack_h2(oacc[ntd][2] * li1, oacc[ntd][3] * li1);
    }
}

// ---------------------------------------------------------------------------
// Launch
// ---------------------------------------------------------------------------
extern "C" void kernel_launch(void* const* d_in, const int* in_sizes, int n_in,
                              void* d_out, int out_size)
{
    (void)in_sizes; (void)n_in; (void)out_size;
    const float* x    = (const float*)d_in[0];
    const float* Wqkv = (const float*)d_in[1];
    const float* bqkv = (const float*)d_in[2];
    const float* Wout = (const float*)d_in[3];
    const float* bout = (const float*)d_in[4];
    float* out = (float*)d_out;

    static __half *qkv_ptr = nullptr, *o_ptr = nullptr, *xh_ptr = nullptr;
    static __half *wqkvT_ptr = nullptr, *woutT_ptr = nullptr;
    static bool init_done = false;
    if (!init_done) {
        // First call is the (uncaptured) correctness run; these immediate host
        // APIs never land inside graph capture.
        cudaFuncSetAttribute(flash_mma_kernel,
                             cudaFuncAttributeMaxDynamicSharedMemorySize,
                             FLASH_SMEM);
        cudaFuncSetAttribute(mma_gemm_bias<true>,
                             cudaFuncAttributeMaxDynamicSharedMemorySize,
                             GEMM_SMEM);
        cudaFuncSetAttribute(mma_gemm_bias<false>,
                             cudaFuncAttributeMaxDynamicSharedMemorySize,
                             GEMM_SMEM);
        void* p;
        cudaGetSymbolAddress(&p, g_qkv);   qkv_ptr   = (__half*)p;
        cudaGetSymbolAddress(&p, g_o);     o_ptr     = (__half*)p;
        cudaGetSymbolAddress(&p, g_xh);    xh_ptr    = (__half*)p;
        cudaGetSymbolAddress(&p, g_WqkvT); wqkvT_ptr = (__half*)p;
        cudaGetSymbolAddress(&p, g_WoutT); woutT_ptr = (__half*)p;
        init_done = true;
    }

    // 0) pre-pass: x -> fp16; weights -> transposed fp16 [N,K]
    f2h_kernel<<<(MROWS * (size_t)D_ / 8) / 256, 256>>>(x, xh_ptr);
    transpose_kernel<<<dim3(QKV_N / 32, D_ / 32), dim3(32, 8)>>>(Wqkv, wqkvT_ptr, D_, QKV_N);
    transpose_kernel<<<dim3(D_ / 32, D_ / 32), dim3(32, 8)>>>(Wout, woutT_ptr, D_, D_);

    // 1) QKV = x @ Wqkv + bqkv (fp16 mma, fp32 accum; fp16 output)
    mma_gemm_bias<true><<<dim3(QKV_N / GBN, MROWS / GBM), 512, GEMM_SMEM>>>(
        xh_ptr, wqkvT_ptr, bqkv, qkv_ptr, MROWS, QKV_N, D_);

    // 2) causal flash attention (fp16 tensor cores) -> g_o (fp16)
    flash_mma_kernel<<<dim3(T_ / FBQ, H_, B_), 256, FLASH_SMEM>>>();

    // 3) out = g_o @ Wout + bout (fp16 mma, fp32 output)
    mma_gemm_bias<false><<<dim3(D_ / GBN, MROWS / GBM), 512, GEMM_SMEM>>>(
        o_ptr, woutT_ptr, bout, out, MROWS, D_, D_);
}

// round 7
// speedup vs baseline: 2.1998x; 1.1211x over previous
#include <cuda_runtime.h>
#include <cuda_fp16.h>
#include <math.h>
#include <stdint.h>

#define B_  2
#define T_  2048
#define D_  2048
#define H_  16
#define DH  128
#define MROWS (B_*T_)          // 4096
#define QKV_N (3*D_)           // 6144

// Scratch (device globals — no allocation allowed); all fp16 operands
__device__ __half g_qkv[(size_t)MROWS * QKV_N];    // 50 MB
__device__ __half g_o[(size_t)MROWS * D_];         // 16 MB
__device__ __half g_xh[(size_t)MROWS * D_];        // 16 MB
__device__ __half g_WqkvT[(size_t)QKV_N * D_];     // 25 MB ([N,K] K-contig)
__device__ __half g_WoutT[(size_t)D_ * D_];        // 8 MB

// ---------------------------------------------------------------------------
// Helpers
// ---------------------------------------------------------------------------
__device__ __forceinline__ void cp_async16(uint32_t s, const void* g) {
    asm volatile("cp.async.cg.shared.global [%0], [%1], 16;" :: "r"(s), "l"(g));
}
__device__ __forceinline__ void cp_commit() {
    asm volatile("cp.async.commit_group;" ::: "memory");
}
template <int N> __device__ __forceinline__ void cp_wait() {
    asm volatile("cp.async.wait_group %0;" :: "n"(N) : "memory");
}
__device__ __forceinline__ uint32_t smem_u32(const void* p) {
    uint32_t a;
    asm("{ .reg .u64 t; cvta.to.shared.u64 t, %1; cvt.u32.u64 %0, t; }"
        : "=r"(a) : "l"(p));
    return a;
}
__device__ __forceinline__ void ldm_x4(uint32_t& r0, uint32_t& r1,
                                       uint32_t& r2, uint32_t& r3, uint32_t a) {
    asm volatile("ldmatrix.sync.aligned.m8n8.x4.shared.b16 {%0,%1,%2,%3}, [%4];"
                 : "=r"(r0), "=r"(r1), "=r"(r2), "=r"(r3) : "r"(a));
}
__device__ __forceinline__ void ldm_x4_t(uint32_t& r0, uint32_t& r1,
                                         uint32_t& r2, uint32_t& r3, uint32_t a) {
    asm volatile("ldmatrix.sync.aligned.m8n8.x4.trans.shared.b16 {%0,%1,%2,%3}, [%4];"
                 : "=r"(r0), "=r"(r1), "=r"(r2), "=r"(r3) : "r"(a));
}
__device__ __forceinline__ void mma_f16(float c[4],
    uint32_t a0, uint32_t a1, uint32_t a2, uint32_t a3,
    uint32_t b0, uint32_t b1)
{
    asm volatile(
        "mma.sync.aligned.m16n8k16.row.col.f32.f16.f16.f32 "
        "{%0,%1,%2,%3}, {%4,%5,%6,%7}, {%8,%9}, {%0,%1,%2,%3};"
        : "+f"(c[0]), "+f"(c[1]), "+f"(c[2]), "+f"(c[3])
        : "r"(a0), "r"(a1), "r"(a2), "r"(a3), "r"(b0), "r"(b1));
}
__device__ __forceinline__ uint32_t pack_h2(float x, float y) {
    __half2 h = __floats2half2_rn(x, y);
    return *(uint32_t*)&h;
}

// ---------------------------------------------------------------------------
// x pre-pass: fp32 -> fp16. Each thread converts 8 floats.
// ---------------------------------------------------------------------------
__global__ __launch_bounds__(256) void f2h_kernel(
    const float* __restrict__ in, __half* __restrict__ out)
{
    const size_t i = (size_t)blockIdx.x * 256 + threadIdx.x;
    float4 a = ((const float4*)in)[2 * i];
    float4 b = ((const float4*)in)[2 * i + 1];
    uint4 u;
    u.x = pack_h2(a.x, a.y); u.y = pack_h2(a.z, a.w);
    u.z = pack_h2(b.x, b.y); u.w = pack_h2(b.z, b.w);
    ((uint4*)out)[i] = u;
}

// ---------------------------------------------------------------------------
// Weight transpose + fp16: At[N,K] = h(A[K,N]^T)
// ---------------------------------------------------------------------------
__global__ __launch_bounds__(256) void transpose_kernel(
    const float* __restrict__ A, __half* __restrict__ At, int R, int C)
{
    __shared__ float tile[32][33];
    const int c = blockIdx.x * 32 + threadIdx.x;
    const int r = blockIdx.y * 32 + threadIdx.y;
    #pragma unroll
    for (int i = 0; i < 32; i += 8)
        tile[threadIdx.y + i][threadIdx.x] = A[(size_t)(r + i) * C + c];
    __syncthreads();
    const int tc = blockIdx.y * 32 + threadIdx.x;
    const int tr = blockIdx.x * 32 + threadIdx.y;
    #pragma unroll
    for (int i = 0; i < 32; i += 8)
        At[(size_t)(tr + i) * R + tc] = __float2half_rn(tile[threadIdx.x][threadIdx.y + i]);
}

// ---------------------------------------------------------------------------
// fp16 mma.sync GEMM + bias: C[M,N] = A[M,K] @ BT[N,K]^T + bias[N]
// CTA 128x128, 256 threads (8 warps, 4m x 2n), warp tile 32x64.
// BK=64 halves, 3-stage cp.async, smem row stride 72 halves.
// 2 CTAs/SM (smem 110592 x2 = 221184 <= 228KB) so one CTA's barrier/load
// convoy overlaps the other CTA's MMA phase.
// ---------------------------------------------------------------------------
#define GBM 128
#define GBN 128
#define GBK 64
#define STRH 72
#define A_TILE_H (128 * STRH)                 // 9216 halves
#define B_TILE_H (128 * STRH)                 // 9216
#define STAGE_B  ((A_TILE_H + B_TILE_H) * 2)  // 36864 bytes
#define GEMM_SMEM (3 * STAGE_B)               // 110592

__device__ __forceinline__ void gemm_load_stage(
    const __half* __restrict__ A, const __half* __restrict__ BT, int K,
    uint32_t sa, uint32_t sb, int brow, int bcol, int k0, int tid)
{
    #pragma unroll
    for (int i = 0; i < 4; i++) {           // A: 128 rows x 8 chunks
        int idx = tid + i * 256;            // 0..1023
        int row = idx >> 3;
        int c = idx & 7;
        cp_async16(sa + (row * STRH + c * 8) * 2,
                   &A[(size_t)(brow + row) * K + k0 + c * 8]);
    }
    #pragma unroll
    for (int i = 0; i < 4; i++) {           // B^T: 128 n-rows x 8 chunks
        int idx = tid + i * 256;
        int row = idx >> 3;
        int c = idx & 7;
        cp_async16(sb + (row * STRH + c * 8) * 2,
                   &BT[(size_t)(bcol + row) * K + k0 + c * 8]);
    }
}

template <bool OUT_HALF>
__global__ __launch_bounds__(256, 2) void mma_gemm_bias(
    const __half* __restrict__ A, const __half* __restrict__ BT,
    const float* __restrict__ bias, void* __restrict__ Cv,
    int M, int N, int K)
{
    extern __shared__ char sm[];
    const int tid  = threadIdx.x;
    const int wid  = tid >> 5;
    const int lane = tid & 31;
    const int brow = blockIdx.y * GBM;
    const int bcol = blockIdx.x * GBN;
    const int warp_m = wid & 3;            // rows warp_m*32
    const int warp_n = wid >> 2;           // cols warp_n*64
    const int qr = lane >> 2;
    const int qc = lane & 3;

    const uint32_t base = smem_u32(sm);

    float acc[2][8][4];
    #pragma unroll
    for (int mt = 0; mt < 2; mt++)
        #pragma unroll
        for (int nt = 0; nt < 8; nt++)
            #pragma unroll
            for (int i = 0; i < 4; i++)
                acc[mt][nt][i] = 0.0f;

    const int KT = K / GBK;   // 32

    #pragma unroll
    for (int s = 0; s < 3; s++) {
        uint32_t sa = base + s * STAGE_B;
        gemm_load_stage(A, BT, K, sa, sa + A_TILE_H * 2, brow, bcol, s * GBK, tid);
        cp_commit();
    }

    // per-lane ldmatrix offsets (halves)
    const int la_off = (warp_m * 32 + (lane & 15)) * STRH + (lane >> 4) * 8;
    const int g = lane >> 3;
    const int lb_off = (warp_n * 64 + ((g & 2) ? 8 : 0) + (lane & 7)) * STRH
                     + (g & 1) * 8;

    int st = 0;
    for (int kt = 0; kt < KT; kt++) {
        cp_wait<2>();
        __syncthreads();

        const uint32_t sa = base + st * STAGE_B;
        const uint32_t sb = sa + A_TILE_H * 2;

        #pragma unroll
        for (int k16 = 0; k16 < 4; k16++) {
            const int ko = k16 * 16;
            uint32_t a0[4], a1[4], b0[4], b1[4], b2[4], b3[4];
            ldm_x4(a0[0], a0[1], a0[2], a0[3], sa + (la_off + ko) * 2);
            ldm_x4(a1[0], a1[1], a1[2], a1[3], sa + (la_off + 16 * STRH + ko) * 2);
            ldm_x4(b0[0], b0[1], b0[2], b0[3], sb + (lb_off + ko) * 2);
            ldm_x4(b1[0], b1[1], b1[2], b1[3], sb + (lb_off + 16 * STRH + ko) * 2);
            ldm_x4(b2[0], b2[1], b2[2], b2[3], sb + (lb_off + 32 * STRH + ko) * 2);
            ldm_x4(b3[0], b3[1], b3[2], b3[3], sb + (lb_off + 48 * STRH + ko) * 2);
            mma_f16(acc[0][0], a0[0], a0[1], a0[2], a0[3], b0[0], b0[1]);
            mma_f16(acc[1][0], a1[0], a1[1], a1[2], a1[3], b0[0], b0[1]);
            mma_f16(acc[0][1], a0[0], a0[1], a0[2], a0[3], b0[2], b0[3]);
            mma_f16(acc[1][1], a1[0], a1[1], a1[2], a1[3], b0[2], b0[3]);
            mma_f16(acc[0][2], a0[0], a0[1], a0[2], a0[3], b1[0], b1[1]);
            mma_f16(acc[1][2], a1[0], a1[1], a1[2], a1[3], b1[0], b1[1]);
            mma_f16(acc[0][3], a0[0], a0[1], a0[2], a0[3], b1[2], b1[3]);
            mma_f16(acc[1][3], a1[0], a1[1], a1[2], a1[3], b1[2], b1[3]);
            mma_f16(acc[0][4], a0[0], a0[1], a0[2], a0[3], b2[0], b2[1]);
            mma_f16(acc[1][4], a1[0], a1[1], a1[2], a1[3], b2[0], b2[1]);
            mma_f16(acc[0][5], a0[0], a0[1], a0[2], a0[3], b2[2], b2[3]);
            mma_f16(acc[1][5], a1[0], a1[1], a1[2], a1[3], b2[2], b2[3]);
            mma_f16(acc[0][6], a0[0], a0[1], a0[2], a0[3], b3[0], b3[1]);
            mma_f16(acc[1][6], a1[0], a1[1], a1[2], a1[3], b3[0], b3[1]);
            mma_f16(acc[0][7], a0[0], a0[1], a0[2], a0[3], b3[2], b3[3]);
            mma_f16(acc[1][7], a1[0], a1[1], a1[2], a1[3], b3[2], b3[3]);
        }
        __syncthreads();

        const int lkt = kt + 3;
        if (lkt < KT) {
            const uint32_t pa = base + st * STAGE_B;
            gemm_load_stage(A, BT, K, pa, pa + A_TILE_H * 2, brow, bcol, lkt * GBK, tid);
        }
        cp_commit();

        if (++st == 3) st = 0;
    }

    // Epilogue
    #pragma unroll
    for (int mt = 0; mt < 2; mt++) {
        const int row0 = brow + warp_m * 32 + mt * 16 + qr;
        #pragma unroll
        for (int nt = 0; nt < 8; nt++) {
            const int col = bcol + warp_n * 64 + nt * 8 + 2 * qc;
            const float2 bb = *(const float2*)&bias[col];
            const float vx = acc[mt][nt][0] + bb.x;
            const float vy = acc[mt][nt][1] + bb.y;
            const float wx = acc[mt][nt][2] + bb.x;
            const float wy = acc[mt][nt][3] + bb.y;
            if (OUT_HALF) {
                __half* C = (__half*)Cv;
                *(uint32_t*)&C[(size_t)row0 * N + col]       = pack_h2(vx, vy);
                *(uint32_t*)&C[(size_t)(row0 + 8) * N + col] = pack_h2(wx, wy);
            } else {
                float* C = (float*)Cv;
                float2 o0; o0.x = vx; o0.y = vy;
                float2 o1; o1.x = wx; o1.y = wy;
                *(float2*)&C[(size_t)row0 * N + col]       = o0;
                *(float2*)&C[(size_t)(row0 + 8) * N + col] = o1;
            }
        }
    }
}

// ---------------------------------------------------------------------------
// fp16 tensor-core flash attention (causal, register softmax, ldmatrix).
// CTA: 128 q-rows, 256 threads (8 warps x 16 rows). KV tiles of 64,
// double-buffered cp.async. 2 CTAs/SM. Row stride 136 halves.
// ---------------------------------------------------------------------------
#define FBQ   128
#define FSTR  136
#define Q_BYTES     (128 * FSTR * 2)          // 34816
#define KV_TILE_B   (64 * FSTR * 2)           // 17408
#define KV_STAGE_B  (2 * KV_TILE_B)           // 34816
#define FLASH_SMEM  (Q_BYTES + 2 * KV_STAGE_B)  // 104448

__device__ __forceinline__ void load_kv_tile(
    uint32_t kbase, uint32_t vbase, size_t rowbase, int j0, int qcol, int tid)
{
    #pragma unroll
    for (int i = 0; i < 4; i++) {
        int idx = tid + i * 256;          // 0..1023
        int r = idx >> 4;                 // 0..63
        int c = idx & 15;
        cp_async16(kbase + (r * FSTR + c * 8) * 2,
                   &g_qkv[(rowbase + j0 + r) * (size_t)QKV_N + qcol + D_ + c * 8]);
    }
    #pragma unroll
    for (int i = 0; i < 4; i++) {
        int idx = tid + i * 256;
        int r = idx >> 4;
        int c = idx & 15;
        cp_async16(vbase + (r * FSTR + c * 8) * 2,
                   &g_qkv[(rowbase + j0 + r) * (size_t)QKV_N + qcol + 2 * D_ + c * 8]);
    }
}

__global__ __launch_bounds__(256, 2) void flash_mma_kernel()
{
    extern __shared__ char smc[];
    const int qi  = (gridDim.x - 1) - blockIdx.x;   // big q-blocks first
    const int q0  = qi * FBQ;
    const int h   = blockIdx.y;
    const int b   = blockIdx.z;
    const int tid = threadIdx.x;
    const int lane = tid & 31;
    const int wid  = tid >> 5;
    const int qr = lane >> 2;
    const int qc = lane & 3;

    const size_t rowbase = (size_t)b * T_;
    const int qcol = h * DH;
    const float SCALE = 0.08838834764831845f;   // 1/sqrt(128)

    const uint32_t base = smem_u32(smc);
    const uint32_t Qs = base;
    const int ntile = 2 * qi + 2;

    #pragma unroll
    for (int i = 0; i < 8; i++) {
        int idx = tid + i * 256;          // 0..2047
        int r = idx >> 4;
        int c = idx & 15;
        cp_async16(Qs + (r * FSTR + c * 8) * 2,
                   &g_qkv[(rowbase + q0 + r) * (size_t)QKV_N + qcol + c * 8]);
    }
    {
        uint32_t s0 = base + Q_BYTES;
        load_kv_tile(s0, s0 + KV_TILE_B, rowbase, 0, qcol, tid);
        cp_commit();
        if (ntile > 1) {
            uint32_t s1 = base + Q_BYTES + KV_STAGE_B;
            load_kv_tile(s1, s1 + KV_TILE_B, rowbase, 64, qcol, tid);
        }
        cp_commit();
    }

    float oacc[16][4];
    #pragma unroll
    for (int n = 0; n < 16; n++)
        #pragma unroll
        for (int i = 0; i < 4; i++) oacc[n][i] = 0.0f;
    float mrow0 = -3.0e38f, mrow1 = -3.0e38f;
    float lrow0 = 0.0f, lrow1 = 0.0f;

    const int mloc = wid * 16;
    const int g = lane >> 3;
    const int lq_off = (mloc + (lane & 15)) * FSTR + (lane >> 4) * 8;
    const int lk_off = (((g & 2) ? 8 : 0) + (lane & 7)) * FSTR + (g & 1) * 8;
    const int lv_off = ((g & 1) * 8 + (lane & 7)) * FSTR + ((g & 2) ? 8 : 0);

    for (int t = 0; t < ntile; t++) {
        cp_wait<1>();
        __syncthreads();

        const uint32_t Ks = base + Q_BYTES + (t & 1) * KV_STAGE_B;
        const uint32_t Vs = Ks + KV_TILE_B;

        // ---- S = Q @ K^T ----
        float sacc[8][4];
        #pragma unroll
        for (int n = 0; n < 8; n++)
            #pragma unroll
            for (int i = 0; i < 4; i++) sacc[n][i] = 0.0f;

        #pragma unroll
        for (int k16 = 0; k16 < 8; k16++) {
            const int ko = k16 * 16;
            uint32_t qa0, qa1, qa2, qa3;
            ldm_x4(qa0, qa1, qa2, qa3, Qs + (lq_off + ko) * 2);
            #pragma unroll
            for (int ntp = 0; ntp < 4; ntp++) {
                uint32_t b0, b1, b2, b3;
                ldm_x4(b0, b1, b2, b3, Ks + (lk_off + ntp * 16 * FSTR + ko) * 2);
                mma_f16(sacc[2 * ntp    ], qa0, qa1, qa2, qa3, b0, b1);
                mma_f16(sacc[2 * ntp + 1], qa0, qa1, qa2, qa3, b2, b3);
            }
        }

        // ---- causal mask (only last 2 tiles touch the diagonal) ----
        if (t >= ntile - 2) {
            const int j0 = t * 64;
            const int rg0 = q0 + mloc + qr;
            const int rg1 = rg0 + 8;
            #pragma unroll
            for (int nt = 0; nt < 8; nt++) {
                const int cg = j0 + nt * 8 + 2 * qc;
                if (cg     > rg0) sacc[nt][0] = -1.0e30f;
                if (cg + 1 > rg0) sacc[nt][1] = -1.0e30f;
                if (cg     > rg1) sacc[nt][2] = -1.0e30f;
                if (cg + 1 > rg1) sacc[nt][3] = -1.0e30f;
            }
        }

        // ---- online softmax (per-row, quad lanes) ----
        float mx0 = -3.0e38f, mx1 = -3.0e38f;
        #pragma unroll
        for (int nt = 0; nt < 8; nt++) {
            mx0 = fmaxf(mx0, fmaxf(sacc[nt][0], sacc[nt][1]));
            mx1 = fmaxf(mx1, fmaxf(sacc[nt][2], sacc[nt][3]));
        }
        mx0 = fmaxf(mx0, __shfl_xor_sync(0xFFFFFFFFu, mx0, 1));
        mx0 = fmaxf(mx0, __shfl_xor_sync(0xFFFFFFFFu, mx0, 2));
        mx1 = fmaxf(mx1, __shfl_xor_sync(0xFFFFFFFFu, mx1, 1));
        mx1 = fmaxf(mx1, __shfl_xor_sync(0xFFFFFFFFu, mx1, 2));
        const float mn0 = fmaxf(mrow0, mx0);
        const float mn1 = fmaxf(mrow1, mx1);
        const float al0 = __expf((mrow0 - mn0) * SCALE);
        const float al1 = __expf((mrow1 - mn1) * SCALE);
        mrow0 = mn0; mrow1 = mn1;

        float ps0 = 0.0f, ps1 = 0.0f;
        #pragma unroll
        for (int nt = 0; nt < 8; nt++) {
            sacc[nt][0] = __expf((sacc[nt][0] - mn0) * SCALE);
            sacc[nt][1] = __expf((sacc[nt][1] - mn0) * SCALE);
            sacc[nt][2] = __expf((sacc[nt][2] - mn1) * SCALE);
            sacc[nt][3] = __expf((sacc[nt][3] - mn1) * SCALE);
            ps0 += sacc[nt][0] + sacc[nt][1];
            ps1 += sacc[nt][2] + sacc[nt][3];
        }
        ps0 += __shfl_xor_sync(0xFFFFFFFFu, ps0, 1);
        ps0 += __shfl_xor_sync(0xFFFFFFFFu, ps0, 2);
        ps1 += __shfl_xor_sync(0xFFFFFFFFu, ps1, 1);
        ps1 += __shfl_xor_sync(0xFFFFFFFFu, ps1, 2);
        lrow0 = lrow0 * al0 + ps0;
        lrow1 = lrow1 * al1 + ps1;

        #pragma unroll
        for (int n = 0; n < 16; n++) {
            oacc[n][0] *= al0; oacc[n][1] *= al0;
            oacc[n][2] *= al1; oacc[n][3] *= al1;
        }

        // ---- P fragments: direct pack (C-layout == A-layout in fp16) ----
        uint32_t pA[4][4];
        #pragma unroll
        for (int j = 0; j < 4; j++) {
            pA[j][0] = pack_h2(sacc[2 * j][0],     sacc[2 * j][1]);
            pA[j][1] = pack_h2(sacc[2 * j][2],     sacc[2 * j][3]);
            pA[j][2] = pack_h2(sacc[2 * j + 1][0], sacc[2 * j + 1][1]);
            pA[j][3] = pack_h2(sacc[2 * j + 1][2], sacc[2 * j + 1][3]);
        }

        // ---- O += P @ V  (V^T fragments via ldmatrix.trans) ----
        #pragma unroll
        for (int j = 0; j < 4; j++) {
            #pragma unroll
            for (int ntp = 0; ntp < 8; ntp++) {
                uint32_t b0, b1, b2, b3;
                ldm_x4_t(b0, b1, b2, b3,
                         Vs + (lv_off + j * 16 * FSTR + ntp * 16) * 2);
                mma_f16(oacc[2 * ntp    ], pA[j][0], pA[j][1], pA[j][2], pA[j][3], b0, b1);
                mma_f16(oacc[2 * ntp + 1], pA[j][0], pA[j][1], pA[j][2], pA[j][3], b2, b3);
            }
        }

        __syncthreads();
        if (t + 2 < ntile) {
            uint32_t sb = base + Q_BYTES + (t & 1) * KV_STAGE_B;
            load_kv_tile(sb, sb + KV_TILE_B, rowbase, (t + 2) * 64, qcol, tid);
        }
        cp_commit();
    }

    // ---- epilogue: normalize, fp16 store (feeds out-proj GEMM) ----
    const float li0 = 1.0f / lrow0;
    const float li1 = 1.0f / lrow1;
    const int r0 = q0 + mloc + qr;
    const int r1 = r0 + 8;
    #pragma unroll
    for (int ntd = 0; ntd < 16; ntd++) {
        const int col = qcol + ntd * 8 + 2 * qc;
        *(uint32_t*)&g_o[(rowbase + r0) * (size_t)D_ + col] =
            pack_h2(oacc[ntd][0] * li0, oacc[ntd][1] * li0);
        *(uint32_t*)&g_o[(rowbase + r1) * (size_t)D_ + col] =
            pack_h2(oacc[ntd][2] * li1, oacc[ntd][3] * li1);
    }
}

// ---------------------------------------------------------------------------
// Launch
// ---------------------------------------------------------------------------
extern "C" void kernel_launch(void* const* d_in, const int* in_sizes, int n_in,
                              void* d_out, int out_size)
{
    (void)in_sizes; (void)n_in; (void)out_size;
    const float* x    = (const float*)d_in[0];
    const float* Wqkv = (const float*)d_in[1];
    const float* bqkv = (const float*)d_in[2];
    const float* Wout = (const float*)d_in[3];
    const float* bout = (const float*)d_in[4];
    float* out = (float*)d_out;

    static __half *qkv_ptr = nullptr, *o_ptr = nullptr, *xh_ptr = nullptr;
    static __half *wqkvT_ptr = nullptr, *woutT_ptr = nullptr;
    static bool init_done = false;
    if (!init_done) {
        // First call is the (uncaptured) correctness run; these immediate host
        // APIs never land inside graph capture.
        cudaFuncSetAttribute(flash_mma_kernel,
                             cudaFuncAttributeMaxDynamicSharedMemorySize,
                             FLASH_SMEM);
        cudaFuncSetAttribute(mma_gemm_bias<true>,
                             cudaFuncAttributeMaxDynamicSharedMemorySize,
                             GEMM_SMEM);
        cudaFuncSetAttribute(mma_gemm_bias<false>,
                             cudaFuncAttributeMaxDynamicSharedMemorySize,
                             GEMM_SMEM);
        void* p;
        cudaGetSymbolAddress(&p, g_qkv);   qkv_ptr   = (__half*)p;
        cudaGetSymbolAddress(&p, g_o);     o_ptr     = (__half*)p;
        cudaGetSymbolAddress(&p, g_xh);    xh_ptr    = (__half*)p;
        cudaGetSymbolAddress(&p, g_WqkvT); wqkvT_ptr = (__half*)p;
        cudaGetSymbolAddress(&p, g_WoutT); woutT_ptr = (__half*)p;
        init_done = true;
    }

    // 0) pre-pass: x -> fp16; weights -> transposed fp16 [N,K]
    f2h_kernel<<<(MROWS * (size_t)D_ / 8) / 256, 256>>>(x, xh_ptr);
    transpose_kernel<<<dim3(QKV_N / 32, D_ / 32), dim3(32, 8)>>>(Wqkv, wqkvT_ptr, D_, QKV_N);
    transpose_kernel<<<dim3(D_ / 32, D_ / 32), dim3(32, 8)>>>(Wout, woutT_ptr, D_, D_);

    // 1) QKV = x @ Wqkv + bqkv (fp16 mma, fp32 accum; fp16 output)
    mma_gemm_bias<true><<<dim3(QKV_N / GBN, MROWS / GBM), 256, GEMM_SMEM>>>(
        xh_ptr, wqkvT_ptr, bqkv, qkv_ptr, MROWS, QKV_N, D_);

    // 2) causal flash attention (fp16 tensor cores) -> g_o (fp16)
    flash_mma_kernel<<<dim3(T_ / FBQ, H_, B_), 256, FLASH_SMEM>>>();

    // 3) out = g_o @ Wout + bout (fp16 mma, fp32 output)
    mma_gemm_bias<false><<<dim3(D_ / GBN, MROWS / GBM), 256, GEMM_SMEM>>>(
        o_ptr, woutT_ptr, bout, out, MROWS, D_, D_);
}

// round 8
// speedup vs baseline: 2.2057x; 1.0027x over previous
#include <cuda_runtime.h>
#include <cuda_fp16.h>
#include <math.h>
#include <stdint.h>

#define B_  2
#define T_  2048
#define D_  2048
#define H_  16
#define DH  128
#define MROWS (B_*T_)          // 4096
#define QKV_N (3*D_)           // 6144

// Scratch (device globals — no allocation allowed); all fp16 operands
__device__ __half g_qkv[(size_t)MROWS * QKV_N];    // 50 MB
__device__ __half g_o[(size_t)MROWS * D_];         // 16 MB
__device__ __half g_xh[(size_t)MROWS * D_];        // 16 MB
__device__ __half g_WqkvT[(size_t)QKV_N * D_];     // 25 MB ([N,K] K-contig)
__device__ __half g_WoutT[(size_t)D_ * D_];        // 8 MB

// ---------------------------------------------------------------------------
// Helpers
// ---------------------------------------------------------------------------
__device__ __forceinline__ void cp_async16(uint32_t s, const void* g) {
    asm volatile("cp.async.cg.shared.global [%0], [%1], 16;" :: "r"(s), "l"(g));
}
__device__ __forceinline__ void cp_commit() {
    asm volatile("cp.async.commit_group;" ::: "memory");
}
template <int N> __device__ __forceinline__ void cp_wait() {
    asm volatile("cp.async.wait_group %0;" :: "n"(N) : "memory");
}
__device__ __forceinline__ uint32_t smem_u32(const void* p) {
    uint32_t a;
    asm("{ .reg .u64 t; cvta.to.shared.u64 t, %1; cvt.u32.u64 %0, t; }"
        : "=r"(a) : "l"(p));
    return a;
}
__device__ __forceinline__ void ldm_x4(uint32_t& r0, uint32_t& r1,
                                       uint32_t& r2, uint32_t& r3, uint32_t a) {
    asm volatile("ldmatrix.sync.aligned.m8n8.x4.shared.b16 {%0,%1,%2,%3}, [%4];"
                 : "=r"(r0), "=r"(r1), "=r"(r2), "=r"(r3) : "r"(a));
}
__device__ __forceinline__ void ldm_x4_t(uint32_t& r0, uint32_t& r1,
                                         uint32_t& r2, uint32_t& r3, uint32_t a) {
    asm volatile("ldmatrix.sync.aligned.m8n8.x4.trans.shared.b16 {%0,%1,%2,%3}, [%4];"
                 : "=r"(r0), "=r"(r1), "=r"(r2), "=r"(r3) : "r"(a));
}
__device__ __forceinline__ void mma_f16(float c[4],
    uint32_t a0, uint32_t a1, uint32_t a2, uint32_t a3,
    uint32_t b0, uint32_t b1)
{
    asm volatile(
        "mma.sync.aligned.m16n8k16.row.col.f32.f16.f16.f32 "
        "{%0,%1,%2,%3}, {%4,%5,%6,%7}, {%8,%9}, {%0,%1,%2,%3};"
        : "+f"(c[0]), "+f"(c[1]), "+f"(c[2]), "+f"(c[3])
        : "r"(a0), "r"(a1), "r"(a2), "r"(a3), "r"(b0), "r"(b1));
}
__device__ __forceinline__ uint32_t pack_h2(float x, float y) {
    __half2 h = __floats2half2_rn(x, y);
    return *(uint32_t*)&h;
}

// ---------------------------------------------------------------------------
// x pre-pass: fp32 -> fp16. Each thread converts 8 floats.
// ---------------------------------------------------------------------------
__global__ __launch_bounds__(256) void f2h_kernel(
    const float* __restrict__ in, __half* __restrict__ out)
{
    const size_t i = (size_t)blockIdx.x * 256 + threadIdx.x;
    float4 a = ((const float4*)in)[2 * i];
    float4 b = ((const float4*)in)[2 * i + 1];
    uint4 u;
    u.x = pack_h2(a.x, a.y); u.y = pack_h2(a.z, a.w);
    u.z = pack_h2(b.x, b.y); u.w = pack_h2(b.z, b.w);
    ((uint4*)out)[i] = u;
}

// ---------------------------------------------------------------------------
// Weight transpose + fp16: At[N,K] = h(A[K,N]^T)
// ---------------------------------------------------------------------------
__global__ __launch_bounds__(256) void transpose_kernel(
    const float* __restrict__ A, __half* __restrict__ At, int R, int C)
{
    __shared__ float tile[32][33];
    const int c = blockIdx.x * 32 + threadIdx.x;
    const int r = blockIdx.y * 32 + threadIdx.y;
    #pragma unroll
    for (int i = 0; i < 32; i += 8)
        tile[threadIdx.y + i][threadIdx.x] = A[(size_t)(r + i) * C + c];
    __syncthreads();
    const int tc = blockIdx.y * 32 + threadIdx.x;
    const int tr = blockIdx.x * 32 + threadIdx.y;
    #pragma unroll
    for (int i = 0; i < 32; i += 8)
        At[(size_t)(tr + i) * R + tc] = __float2half_rn(tile[threadIdx.x][threadIdx.y + i]);
}

// ---------------------------------------------------------------------------
// fp16 mma.sync GEMM + bias: C[M,N] = A[M,K] @ BT[N,K]^T + bias[N]
// CTA 128x128, 256 threads (8 warps, 4m x 2n), warp tile 32x64.
// BK=64 halves, rotated 3-stage cp.async pipeline with ONE barrier per
// iteration: the stage freed by the top-of-loop barrier is the one reloaded.
// 2 CTAs/SM (smem 110592 x2 <= 228KB).
// ---------------------------------------------------------------------------
#define GBM 128
#define GBN 128
#define GBK 64
#define STRH 72
#define A_TILE_H (128 * STRH)                 // 9216 halves
#define B_TILE_H (128 * STRH)                 // 9216
#define STAGE_B  ((A_TILE_H + B_TILE_H) * 2)  // 36864 bytes
#define GEMM_SMEM (3 * STAGE_B)               // 110592

__device__ __forceinline__ void gemm_load_stage(
    const __half* __restrict__ A, const __half* __restrict__ BT, int K,
    uint32_t sa, uint32_t sb, int brow, int bcol, int k0, int tid)
{
    #pragma unroll
    for (int i = 0; i < 4; i++) {           // A: 128 rows x 8 chunks
        int idx = tid + i * 256;            // 0..1023
        int row = idx >> 3;
        int c = idx & 7;
        cp_async16(sa + (row * STRH + c * 8) * 2,
                   &A[(size_t)(brow + row) * K + k0 + c * 8]);
    }
    #pragma unroll
    for (int i = 0; i < 4; i++) {           // B^T: 128 n-rows x 8 chunks
        int idx = tid + i * 256;
        int row = idx >> 3;
        int c = idx & 7;
        cp_async16(sb + (row * STRH + c * 8) * 2,
                   &BT[(size_t)(bcol + row) * K + k0 + c * 8]);
    }
}

template <bool OUT_HALF>
__global__ __launch_bounds__(256, 2) void mma_gemm_bias(
    const __half* __restrict__ A, const __half* __restrict__ BT,
    const float* __restrict__ bias, void* __restrict__ Cv,
    int M, int N, int K)
{
    extern __shared__ char sm[];
    const int tid  = threadIdx.x;
    const int wid  = tid >> 5;
    const int lane = tid & 31;
    const int brow = blockIdx.y * GBM;
    const int bcol = blockIdx.x * GBN;
    const int warp_m = wid & 3;            // rows warp_m*32
    const int warp_n = wid >> 2;           // cols warp_n*64
    const int qr = lane >> 2;
    const int qc = lane & 3;

    const uint32_t base = smem_u32(sm);

    float acc[2][8][4];
    #pragma unroll
    for (int mt = 0; mt < 2; mt++)
        #pragma unroll
        for (int nt = 0; nt < 8; nt++)
            #pragma unroll
            for (int i = 0; i < 4; i++)
                acc[mt][nt][i] = 0.0f;

    const int KT = K / GBK;   // 32

    // Prologue: load stages for kt=0, kt=1 (pipeline depth 2, 3 physical stages)
    gemm_load_stage(A, BT, K, base, base + A_TILE_H * 2, brow, bcol, 0, tid);
    cp_commit();
    gemm_load_stage(A, BT, K, base + STAGE_B, base + STAGE_B + A_TILE_H * 2,
                    brow, bcol, GBK, tid);
    cp_commit();

    // per-lane ldmatrix offsets (halves)
    const int la_off = (warp_m * 32 + (lane & 15)) * STRH + (lane >> 4) * 8;
    const int g = lane >> 3;
    const int lb_off = (warp_n * 64 + ((g & 2) ? 8 : 0) + (lane & 7)) * STRH
                     + (g & 1) * 8;

    int st = 0;
    for (int kt = 0; kt < KT; kt++) {
        cp_wait<1>();          // stage for kt is resident
        __syncthreads();       // also proves all warps done READING stage kt-1

        // reload the just-freed stage (kt+2)%3 with data for kt+2,
        // overlapping these cp.asyncs with the MMA phase below
        const int lkt = kt + 2;
        if (lkt < KT) {
            int fst = st + 2; if (fst >= 3) fst -= 3;
            const uint32_t pa = base + fst * STAGE_B;
            gemm_load_stage(A, BT, K, pa, pa + A_TILE_H * 2, brow, bcol,
                            lkt * GBK, tid);
        }
        cp_commit();

        const uint32_t sa = base + st * STAGE_B;
        const uint32_t sb = sa + A_TILE_H * 2;

        #pragma unroll
        for (int k16 = 0; k16 < 4; k16++) {
            const int ko = k16 * 16;
            uint32_t a0[4], a1[4], b0[4], b1[4], b2[4], b3[4];
            ldm_x4(a0[0], a0[1], a0[2], a0[3], sa + (la_off + ko) * 2);
            ldm_x4(a1[0], a1[1], a1[2], a1[3], sa + (la_off + 16 * STRH + ko) * 2);
            ldm_x4(b0[0], b0[1], b0[2], b0[3], sb + (lb_off + ko) * 2);
            ldm_x4(b1[0], b1[1], b1[2], b1[3], sb + (lb_off + 16 * STRH + ko) * 2);
            ldm_x4(b2[0], b2[1], b2[2], b2[3], sb + (lb_off + 32 * STRH + ko) * 2);
            ldm_x4(b3[0], b3[1], b3[2], b3[3], sb + (lb_off + 48 * STRH + ko) * 2);
            mma_f16(acc[0][0], a0[0], a0[1], a0[2], a0[3], b0[0], b0[1]);
            mma_f16(acc[1][0], a1[0], a1[1], a1[2], a1[3], b0[0], b0[1]);
            mma_f16(acc[0][1], a0[0], a0[1], a0[2], a0[3], b0[2], b0[3]);
            mma_f16(acc[1][1], a1[0], a1[1], a1[2], a1[3], b0[2], b0[3]);
            mma_f16(acc[0][2], a0[0], a0[1], a0[2], a0[3], b1[0], b1[1]);
            mma_f16(acc[1][2], a1[0], a1[1], a1[2], a1[3], b1[0], b1[1]);
            mma_f16(acc[0][3], a0[0], a0[1], a0[2], a0[3], b1[2], b1[3]);
            mma_f16(acc[1][3], a1[0], a1[1], a1[2], a1[3], b1[2], b1[3]);
            mma_f16(acc[0][4], a0[0], a0[1], a0[2], a0[3], b2[0], b2[1]);
            mma_f16(acc[1][4], a1[0], a1[1], a1[2], a1[3], b2[0], b2[1]);
            mma_f16(acc[0][5], a0[0], a0[1], a0[2], a0[3], b2[2], b2[3]);
            mma_f16(acc[1][5], a1[0], a1[1], a1[2], a1[3], b2[2], b2[3]);
            mma_f16(acc[0][6], a0[0], a0[1], a0[2], a0[3], b3[0], b3[1]);
            mma_f16(acc[1][6], a1[0], a1[1], a1[2], a1[3], b3[0], b3[1]);
            mma_f16(acc[0][7], a0[0], a0[1], a0[2], a0[3], b3[2], b3[3]);
            mma_f16(acc[1][7], a1[0], a1[1], a1[2], a1[3], b3[2], b3[3]);
        }

        if (++st == 3) st = 0;
    }

    // Epilogue
    #pragma unroll
    for (int mt = 0; mt < 2; mt++) {
        const int row0 = brow + warp_m * 32 + mt * 16 + qr;
        #pragma unroll
        for (int nt = 0; nt < 8; nt++) {
            const int col = bcol + warp_n * 64 + nt * 8 + 2 * qc;
            const float2 bb = *(const float2*)&bias[col];
            const float vx = acc[mt][nt][0] + bb.x;
            const float vy = acc[mt][nt][1] + bb.y;
            const float wx = acc[mt][nt][2] + bb.x;
            const float wy = acc[mt][nt][3] + bb.y;
            if (OUT_HALF) {
                __half* C = (__half*)Cv;
                *(uint32_t*)&C[(size_t)row0 * N + col]       = pack_h2(vx, vy);
                *(uint32_t*)&C[(size_t)(row0 + 8) * N + col] = pack_h2(wx, wy);
            } else {
                float* C = (float*)Cv;
                float2 o0; o0.x = vx; o0.y = vy;
                float2 o1; o1.x = wx; o1.y = wy;
                *(float2*)&C[(size_t)row0 * N + col]       = o0;
                *(float2*)&C[(size_t)(row0 + 8) * N + col] = o1;
            }
        }
    }
}

// ---------------------------------------------------------------------------
// fp16 tensor-core flash attention (causal, register softmax, ldmatrix).
// CTA: 128 q-rows, 256 threads (8 warps x 16 rows). KV tiles of 64,
// double-buffered cp.async. 2 CTAs/SM. Row stride 136 halves.
// ---------------------------------------------------------------------------
#define FBQ   128
#define FSTR  136
#define Q_BYTES     (128 * FSTR * 2)          // 34816
#define KV_TILE_B   (64 * FSTR * 2)           // 17408
#define KV_STAGE_B  (2 * KV_TILE_B)           // 34816
#define FLASH_SMEM  (Q_BYTES + 2 * KV_STAGE_B)  // 104448

__device__ __forceinline__ void load_kv_tile(
    uint32_t kbase, uint32_t vbase, size_t rowbase, int j0, int qcol, int tid)
{
    #pragma unroll
    for (int i = 0; i < 4; i++) {
        int idx = tid + i * 256;          // 0..1023
        int r = idx >> 4;                 // 0..63
        int c = idx & 15;
        cp_async16(kbase + (r * FSTR + c * 8) * 2,
                   &g_qkv[(rowbase + j0 + r) * (size_t)QKV_N + qcol + D_ + c * 8]);
    }
    #pragma unroll
    for (int i = 0; i < 4; i++) {
        int idx = tid + i * 256;
        int r = idx >> 4;
        int c = idx & 15;
        cp_async16(vbase + (r * FSTR + c * 8) * 2,
                   &g_qkv[(rowbase + j0 + r) * (size_t)QKV_N + qcol + 2 * D_ + c * 8]);
    }
}

__global__ __launch_bounds__(256, 2) void flash_mma_kernel()
{
    extern __shared__ char smc[];
    const int qi  = (gridDim.x - 1) - blockIdx.x;   // big q-blocks first
    const int q0  = qi * FBQ;
    const int h   = blockIdx.y;
    const int b   = blockIdx.z;
    const int tid = threadIdx.x;
    const int lane = tid & 31;
    const int wid  = tid >> 5;
    const int qr = lane >> 2;
    const int qc = lane & 3;

    const size_t rowbase = (size_t)b * T_;
    const int qcol = h * DH;
    const float SCALE = 0.08838834764831845f;   // 1/sqrt(128)

    const uint32_t base = smem_u32(smc);
    const uint32_t Qs = base;
    const int ntile = 2 * qi + 2;

    #pragma unroll
    for (int i = 0; i < 8; i++) {
        int idx = tid + i * 256;          // 0..2047
        int r = idx >> 4;
        int c = idx & 15;
        cp_async16(Qs + (r * FSTR + c * 8) * 2,
                   &g_qkv[(rowbase + q0 + r) * (size_t)QKV_N + qcol + c * 8]);
    }
    {
        uint32_t s0 = base + Q_BYTES;
        load_kv_tile(s0, s0 + KV_TILE_B, rowbase, 0, qcol, tid);
        cp_commit();
        if (ntile > 1) {
            uint32_t s1 = base + Q_BYTES + KV_STAGE_B;
            load_kv_tile(s1, s1 + KV_TILE_B, rowbase, 64, qcol, tid);
        }
        cp_commit();
    }

    float oacc[16][4];
    #pragma unroll
    for (int n = 0; n < 16; n++)
        #pragma unroll
        for (int i = 0; i < 4; i++) oacc[n][i] = 0.0f;
    float mrow0 = -3.0e38f, mrow1 = -3.0e38f;
    float lrow0 = 0.0f, lrow1 = 0.0f;

    const int mloc = wid * 16;
    const int g = lane >> 3;
    const int lq_off = (mloc + (lane & 15)) * FSTR + (lane >> 4) * 8;
    const int lk_off = (((g & 2) ? 8 : 0) + (lane & 7)) * FSTR + (g & 1) * 8;
    const int lv_off = ((g & 1) * 8 + (lane & 7)) * FSTR + ((g & 2) ? 8 : 0);

    for (int t = 0; t < ntile; t++) {
        cp_wait<1>();
        __syncthreads();

        const uint32_t Ks = base + Q_BYTES + (t & 1) * KV_STAGE_B;
        const uint32_t Vs = Ks + KV_TILE_B;

        // ---- S = Q @ K^T ----
        float sacc[8][4];
        #pragma unroll
        for (int n = 0; n < 8; n++)
            #pragma unroll
            for (int i = 0; i < 4; i++) sacc[n][i] = 0.0f;

        #pragma unroll
        for (int k16 = 0; k16 < 8; k16++) {
            const int ko = k16 * 16;
            uint32_t qa0, qa1, qa2, qa3;
            ldm_x4(qa0, qa1, qa2, qa3, Qs + (lq_off + ko) * 2);
            #pragma unroll
            for (int ntp = 0; ntp < 4; ntp++) {
                uint32_t b0, b1, b2, b3;
                ldm_x4(b0, b1, b2, b3, Ks + (lk_off + ntp * 16 * FSTR + ko) * 2);
                mma_f16(sacc[2 * ntp    ], qa0, qa1, qa2, qa3, b0, b1);
                mma_f16(sacc[2 * ntp + 1], qa0, qa1, qa2, qa3, b2, b3);
            }
        }

        // ---- causal mask (only last 2 tiles touch the diagonal) ----
        if (t >= ntile - 2) {
            const int j0 = t * 64;
            const int rg0 = q0 + mloc + qr;
            const int rg1 = rg0 + 8;
            #pragma unroll
            for (int nt = 0; nt < 8; nt++) {
                const int cg = j0 + nt * 8 + 2 * qc;
                if (cg     > rg0) sacc[nt][0] = -1.0e30f;
                if (cg + 1 > rg0) sacc[nt][1] = -1.0e30f;
                if (cg     > rg1) sacc[nt][2] = -1.0e30f;
                if (cg + 1 > rg1) sacc[nt][3] = -1.0e30f;
            }
        }

        // ---- online softmax (per-row, quad lanes) ----
        float mx0 = -3.0e38f, mx1 = -3.0e38f;
        #pragma unroll
        for (int nt = 0; nt < 8; nt++) {
            mx0 = fmaxf(mx0, fmaxf(sacc[nt][0], sacc[nt][1]));
            mx1 = fmaxf(mx1, fmaxf(sacc[nt][2], sacc[nt][3]));
        }
        mx0 = fmaxf(mx0, __shfl_xor_sync(0xFFFFFFFFu, mx0, 1));
        mx0 = fmaxf(mx0, __shfl_xor_sync(0xFFFFFFFFu, mx0, 2));
        mx1 = fmaxf(mx1, __shfl_xor_sync(0xFFFFFFFFu, mx1, 1));
        mx1 = fmaxf(mx1, __shfl_xor_sync(0xFFFFFFFFu, mx1, 2));
        const float mn0 = fmaxf(mrow0, mx0);
        const float mn1 = fmaxf(mrow1, mx1);
        const float al0 = __expf((mrow0 - mn0) * SCALE);
        const float al1 = __expf((mrow1 - mn1) * SCALE);
        mrow0 = mn0; mrow1 = mn1;

        float ps0 = 0.0f, ps1 = 0.0f;
        #pragma unroll
        for (int nt = 0; nt < 8; nt++) {
            sacc[nt][0] = __expf((sacc[nt][0] - mn0) * SCALE);
            sacc[nt][1] = __expf((sacc[nt][1] - mn0) * SCALE);
            sacc[nt][2] = __expf((sacc[nt][2] - mn1) * SCALE);
            sacc[nt][3] = __expf((sacc[nt][3] - mn1) * SCALE);
            ps0 += sacc[nt][0] + sacc[nt][1];
            ps1 += sacc[nt][2] + sacc[nt][3];
        }
        ps0 += __shfl_xor_sync(0xFFFFFFFFu, ps0, 1);
        ps0 += __shfl_xor_sync(0xFFFFFFFFu, ps0, 2);
        ps1 += __shfl_xor_sync(0xFFFFFFFFu, ps1, 1);
        ps1 += __shfl_xor_sync(0xFFFFFFFFu, ps1, 2);
        lrow0 = lrow0 * al0 + ps0;
        lrow1 = lrow1 * al1 + ps1;

        #pragma unroll
        for (int n = 0; n < 16; n++) {
            oacc[n][0] *= al0; oacc[n][1] *= al0;
            oacc[n][2] *= al1; oacc[n][3] *= al1;
        }

        // ---- P fragments: direct pack (C-layout == A-layout in fp16) ----
        uint32_t pA[4][4];
        #pragma unroll
        for (int j = 0; j < 4; j++) {
            pA[j][0] = pack_h2(sacc[2 * j][0],     sacc[2 * j][1]);
            pA[j][1] = pack_h2(sacc[2 * j][2],     sacc[2 * j][3]);
            pA[j][2] = pack_h2(sacc[2 * j + 1][0], sacc[2 * j + 1][1]);
            pA[j][3] = pack_h2(sacc[2 * j + 1][2], sacc[2 * j + 1][3]);
        }

        // ---- O += P @ V  (V^T fragments via ldmatrix.trans) ----
        #pragma unroll
        for (int j = 0; j < 4; j++) {
            #pragma unroll
            for (int ntp = 0; ntp < 8; ntp++) {
                uint32_t b0, b1, b2, b3;
                ldm_x4_t(b0, b1, b2, b3,
                         Vs + (lv_off + j * 16 * FSTR + ntp * 16) * 2);
                mma_f16(oacc[2 * ntp    ], pA[j][0], pA[j][1], pA[j][2], pA[j][3], b0, b1);
                mma_f16(oacc[2 * ntp + 1], pA[j][0], pA[j][1], pA[j][2], pA[j][3], b2, b3);
            }
        }

        __syncthreads();
        if (t + 2 < ntile) {
            uint32_t sb = base + Q_BYTES + (t & 1) * KV_STAGE_B;
            load_kv_tile(sb, sb + KV_TILE_B, rowbase, (t + 2) * 64, qcol, tid);
        }
        cp_commit();
    }

    // ---- epilogue: normalize, fp16 store (feeds out-proj GEMM) ----
    const float li0 = 1.0f / lrow0;
    const float li1 = 1.0f / lrow1;
    const int r0 = q0 + mloc + qr;
    const int r1 = r0 + 8;
    #pragma unroll
    for (int ntd = 0; ntd < 16; ntd++) {
        const int col = qcol + ntd * 8 + 2 * qc;
        *(uint32_t*)&g_o[(rowbase + r0) * (size_t)D_ + col] =
            pack_h2(oacc[ntd][0] * li0, oacc[ntd][1] * li0);
        *(uint32_t*)&g_o[(rowbase + r1) * (size_t)D_ + col] =
            pack_h2(oacc[ntd][2] * li1, oacc[ntd][3] * li1);
    }
}

// ---------------------------------------------------------------------------
// Launch
// ---------------------------------------------------------------------------
extern "C" void kernel_launch(void* const* d_in, const int* in_sizes, int n_in,
                              void* d_out, int out_size)
{
    (void)in_sizes; (void)n_in; (void)out_size;
    const float* x    = (const float*)d_in[0];
    const float* Wqkv = (const float*)d_in[1];
    const float* bqkv = (const float*)d_in[2];
    const float* Wout = (const float*)d_in[3];
    const float* bout = (const float*)d_in[4];
    float* out = (float*)d_out;

    static __half *qkv_ptr = nullptr, *o_ptr = nullptr, *xh_ptr = nullptr;
    static __half *wqkvT_ptr = nullptr, *woutT_ptr = nullptr;
    static bool init_done = false;
    if (!init_done) {
        // First call is the (uncaptured) correctness run; these immediate host
        // APIs never land inside graph capture.
        cudaFuncSetAttribute(flash_mma_kernel,
                             cudaFuncAttributeMaxDynamicSharedMemorySize,
                             FLASH_SMEM);
        cudaFuncSetAttribute(mma_gemm_bias<true>,
                             cudaFuncAttributeMaxDynamicSharedMemorySize,
                             GEMM_SMEM);
        cudaFuncSetAttribute(mma_gemm_bias<false>,
                             cudaFuncAttributeMaxDynamicSharedMemorySize,
                             GEMM_SMEM);
        void* p;
        cudaGetSymbolAddress(&p, g_qkv);   qkv_ptr   = (__half*)p;
        cudaGetSymbolAddress(&p, g_o);     o_ptr     = (__half*)p;
        cudaGetSymbolAddress(&p, g_xh);    xh_ptr    = (__half*)p;
        cudaGetSymbolAddress(&p, g_WqkvT); wqkvT_ptr = (__half*)p;
        cudaGetSymbolAddress(&p, g_WoutT); woutT_ptr = (__half*)p;
        init_done = true;
    }

    // 0) pre-pass: x -> fp16; weights -> transposed fp16 [N,K]
    f2h_kernel<<<(MROWS * (size_t)D_ / 8) / 256, 256>>>(x, xh_ptr);
    transpose_kernel<<<dim3(QKV_N / 32, D_ / 32), dim3(32, 8)>>>(Wqkv, wqkvT_ptr, D_, QKV_N);
    transpose_kernel<<<dim3(D_ / 32, D_ / 32), dim3(32, 8)>>>(Wout, woutT_ptr, D_, D_);

    // 1) QKV = x @ Wqkv + bqkv (fp16 mma, fp32 accum; fp16 output)
    mma_gemm_bias<true><<<dim3(QKV_N / GBN, MROWS / GBM), 256, GEMM_SMEM>>>(
        xh_ptr, wqkvT_ptr, bqkv, qkv_ptr, MROWS, QKV_N, D_);

    // 2) causal flash attention (fp16 tensor cores) -> g_o (fp16)
    flash_mma_kernel<<<dim3(T_ / FBQ, H_, B_), 256, FLASH_SMEM>>>();

    // 3) out = g_o @ Wout + bout (fp16 mma, fp32 output)
    mma_gemm_bias<false><<<dim3(D_ / GBN, MROWS / GBM), 256, GEMM_SMEM>>>(
        o_ptr, woutT_ptr, bout, out, MROWS, D_, D_);
}

// round 10
// speedup vs baseline: 2.3334x; 1.0579x over previous
#include <cuda_runtime.h>
#include <cuda_fp16.h>
#include <math.h>
#include <stdint.h>

#define B_  2
#define T_  2048
#define D_  2048
#define H_  16
#define DH  128
#define MROWS (B_*T_)          // 4096
#define QKV_N (3*D_)           // 6144

// Scratch (device globals — no allocation allowed); all fp16 operands
__device__ __half g_qkv[(size_t)MROWS * QKV_N];    // 50 MB
__device__ __half g_o[(size_t)MROWS * D_];         // 16 MB
__device__ __half g_xh[(size_t)MROWS * D_];        // 16 MB
__device__ __half g_WqkvT[(size_t)QKV_N * D_];     // 25 MB ([N,K] K-contig)
__device__ __half g_WoutT[(size_t)D_ * D_];        // 8 MB

// ---------------------------------------------------------------------------
// Helpers
// ---------------------------------------------------------------------------
__device__ __forceinline__ void cp_async16(uint32_t s, const void* g) {
    asm volatile("cp.async.cg.shared.global [%0], [%1], 16;" :: "r"(s), "l"(g));
}
__device__ __forceinline__ void cp_commit() {
    asm volatile("cp.async.commit_group;" ::: "memory");
}
template <int N> __device__ __forceinline__ void cp_wait() {
    asm volatile("cp.async.wait_group %0;" :: "n"(N) : "memory");
}
__device__ __forceinline__ uint32_t smem_u32(const void* p) {
    uint32_t a;
    asm("{ .reg .u64 t; cvta.to.shared.u64 t, %1; cvt.u32.u64 %0, t; }"
        : "=r"(a) : "l"(p));
    return a;
}
__device__ __forceinline__ void ldm_x4(uint32_t& r0, uint32_t& r1,
                                       uint32_t& r2, uint32_t& r3, uint32_t a) {
    asm volatile("ldmatrix.sync.aligned.m8n8.x4.shared.b16 {%0,%1,%2,%3}, [%4];"
                 : "=r"(r0), "=r"(r1), "=r"(r2), "=r"(r3) : "r"(a));
}
__device__ __forceinline__ void ldm_x4_t(uint32_t& r0, uint32_t& r1,
                                         uint32_t& r2, uint32_t& r3, uint32_t a) {
    asm volatile("ldmatrix.sync.aligned.m8n8.x4.trans.shared.b16 {%0,%1,%2,%3}, [%4];"
                 : "=r"(r0), "=r"(r1), "=r"(r2), "=r"(r3) : "r"(a));
}
__device__ __forceinline__ void mma_f16(float c[4],
    uint32_t a0, uint32_t a1, uint32_t a2, uint32_t a3,
    uint32_t b0, uint32_t b1)
{
    asm volatile(
        "mma.sync.aligned.m16n8k16.row.col.f32.f16.f16.f32 "
        "{%0,%1,%2,%3}, {%4,%5,%6,%7}, {%8,%9}, {%0,%1,%2,%3};"
        : "+f"(c[0]), "+f"(c[1]), "+f"(c[2]), "+f"(c[3])
        : "r"(a0), "r"(a1), "r"(a2), "r"(a3), "r"(b0), "r"(b1));
}
__device__ __forceinline__ uint32_t pack_h2(float x, float y) {
    __half2 h = __floats2half2_rn(x, y);
    return *(uint32_t*)&h;
}

// ---------------------------------------------------------------------------
// x pre-pass: fp32 -> fp16. Each thread converts 8 floats.
// ---------------------------------------------------------------------------
__global__ __launch_bounds__(256) void f2h_kernel(
    const float* __restrict__ in, __half* __restrict__ out)
{
    const size_t i = (size_t)blockIdx.x * 256 + threadIdx.x;
    float4 a = ((const float4*)in)[2 * i];
    float4 b = ((const float4*)in)[2 * i + 1];
    uint4 u;
    u.x = pack_h2(a.x, a.y); u.y = pack_h2(a.z, a.w);
    u.z = pack_h2(b.x, b.y); u.w = pack_h2(b.z, b.w);
    ((uint4*)out)[i] = u;
}

// ---------------------------------------------------------------------------
// Weight transpose + fp16: At[N,K] = h(A[K,N]^T)
// ---------------------------------------------------------------------------
__global__ __launch_bounds__(256) void transpose_kernel(
    const float* __restrict__ A, __half* __restrict__ At, int R, int C)
{
    __shared__ float tile[32][33];
    const int c = blockIdx.x * 32 + threadIdx.x;
    const int r = blockIdx.y * 32 + threadIdx.y;
    #pragma unroll
    for (int i = 0; i < 32; i += 8)
        tile[threadIdx.y + i][threadIdx.x] = A[(size_t)(r + i) * C + c];
    __syncthreads();
    const int tc = blockIdx.y * 32 + threadIdx.x;
    const int tr = blockIdx.x * 32 + threadIdx.y;
    #pragma unroll
    for (int i = 0; i < 32; i += 8)
        At[(size_t)(tr + i) * R + tc] = __float2half_rn(tile[threadIdx.x][threadIdx.y + i]);
}

// ---------------------------------------------------------------------------
// fp16 mma.sync GEMM + bias: C[M,N] = A[M,K] @ BT[N,K]^T + bias[N]
// CTA 128x128, 256 threads (8 warps, 4m x 2n), warp tile 32x64.
// BK=64 halves, rotated 3-stage cp.async pipeline, ONE barrier/iteration,
// register-level fragment double-buffering WITHIN a stage. At the stage
// boundary the next stage's k0 fragments are loaded only AFTER
// cp_wait + __syncthreads (cp.async completion is per-thread; cross-thread
// reads require the barrier — the R9 NaN bug).
// 2 CTAs/SM (smem 110592 x2 <= 228KB, regs <= 128).
// ---------------------------------------------------------------------------
#define GBM 128
#define GBN 128
#define GBK 64
#define STRH 72
#define A_TILE_H (128 * STRH)                 // 9216 halves
#define B_TILE_H (128 * STRH)                 // 9216
#define STAGE_B  ((A_TILE_H + B_TILE_H) * 2)  // 36864 bytes
#define GEMM_SMEM (3 * STAGE_B)               // 110592

__device__ __forceinline__ void gemm_load_stage(
    const __half* __restrict__ A, const __half* __restrict__ BT, int K,
    uint32_t sa, uint32_t sb, int brow, int bcol, int k0, int tid)
{
    #pragma unroll
    for (int i = 0; i < 4; i++) {           // A: 128 rows x 8 chunks
        int idx = tid + i * 256;            // 0..1023
        int row = idx >> 3;
        int c = idx & 7;
        cp_async16(sa + (row * STRH + c * 8) * 2,
                   &A[(size_t)(brow + row) * K + k0 + c * 8]);
    }
    #pragma unroll
    for (int i = 0; i < 4; i++) {           // B^T: 128 n-rows x 8 chunks
        int idx = tid + i * 256;
        int row = idx >> 3;
        int c = idx & 7;
        cp_async16(sb + (row * STRH + c * 8) * 2,
                   &BT[(size_t)(bcol + row) * K + k0 + c * 8]);
    }
}

// load one k16 fragment set (6 ldmatrix.x4) from stage (sa, sb) at k-offset ko
#define LOAD_FRAGS(FA, FB, sa, sb, ko)                                        \
    do {                                                                      \
        ldm_x4((FA)[0], (FA)[1], (FA)[2], (FA)[3],                            \
               (sa) + (la_off + (ko)) * 2);                                   \
        ldm_x4((FA)[4], (FA)[5], (FA)[6], (FA)[7],                            \
               (sa) + (la_off + 16 * STRH + (ko)) * 2);                       \
        ldm_x4((FB)[0], (FB)[1], (FB)[2], (FB)[3],                            \
               (sb) + (lb_off + (ko)) * 2);                                   \
        ldm_x4((FB)[4], (FB)[5], (FB)[6], (FB)[7],                            \
               (sb) + (lb_off + 16 * STRH + (ko)) * 2);                       \
        ldm_x4((FB)[8], (FB)[9], (FB)[10], (FB)[11],                          \
               (sb) + (lb_off + 32 * STRH + (ko)) * 2);                       \
        ldm_x4((FB)[12], (FB)[13], (FB)[14], (FB)[15],                        \
               (sb) + (lb_off + 48 * STRH + (ko)) * 2);                       \
    } while (0)

#define MMA_BLOCK(cur)                                                                                     \
    do {                                                                                                   \
        mma_f16(acc[0][0], fa[cur][0], fa[cur][1], fa[cur][2], fa[cur][3], fb[cur][0],  fb[cur][1]);       \
        mma_f16(acc[1][0], fa[cur][4], fa[cur][5], fa[cur][6], fa[cur][7], fb[cur][0],  fb[cur][1]);       \
        mma_f16(acc[0][1], fa[cur][0], fa[cur][1], fa[cur][2], fa[cur][3], fb[cur][2],  fb[cur][3]);       \
        mma_f16(acc[1][1], fa[cur][4], fa[cur][5], fa[cur][6], fa[cur][7], fb[cur][2],  fb[cur][3]);       \
        mma_f16(acc[0][2], fa[cur][0], fa[cur][1], fa[cur][2], fa[cur][3], fb[cur][4],  fb[cur][5]);       \
        mma_f16(acc[1][2], fa[cur][4], fa[cur][5], fa[cur][6], fa[cur][7], fb[cur][4],  fb[cur][5]);       \
        mma_f16(acc[0][3], fa[cur][0], fa[cur][1], fa[cur][2], fa[cur][3], fb[cur][6],  fb[cur][7]);       \
        mma_f16(acc[1][3], fa[cur][4], fa[cur][5], fa[cur][6], fa[cur][7], fb[cur][6],  fb[cur][7]);       \
        mma_f16(acc[0][4], fa[cur][0], fa[cur][1], fa[cur][2], fa[cur][3], fb[cur][8],  fb[cur][9]);       \
        mma_f16(acc[1][4], fa[cur][4], fa[cur][5], fa[cur][6], fa[cur][7], fb[cur][8],  fb[cur][9]);       \
        mma_f16(acc[0][5], fa[cur][0], fa[cur][1], fa[cur][2], fa[cur][3], fb[cur][10], fb[cur][11]);      \
        mma_f16(acc[1][5], fa[cur][4], fa[cur][5], fa[cur][6], fa[cur][7], fb[cur][10], fb[cur][11]);      \
        mma_f16(acc[0][6], fa[cur][0], fa[cur][1], fa[cur][2], fa[cur][3], fb[cur][12], fb[cur][13]);      \
        mma_f16(acc[1][6], fa[cur][4], fa[cur][5], fa[cur][6], fa[cur][7], fb[cur][12], fb[cur][13]);      \
        mma_f16(acc[0][7], fa[cur][0], fa[cur][1], fa[cur][2], fa[cur][3], fb[cur][14], fb[cur][15]);      \
        mma_f16(acc[1][7], fa[cur][4], fa[cur][5], fa[cur][6], fa[cur][7], fb[cur][14], fb[cur][15]);      \
    } while (0)

template <bool OUT_HALF>
__global__ __launch_bounds__(256, 2) void mma_gemm_bias(
    const __half* __restrict__ A, const __half* __restrict__ BT,
    const float* __restrict__ bias, void* __restrict__ Cv,
    int M, int N, int K)
{
    extern __shared__ char sm[];
    const int tid  = threadIdx.x;
    const int wid  = tid >> 5;
    const int lane = tid & 31;
    const int brow = blockIdx.y * GBM;
    const int bcol = blockIdx.x * GBN;
    const int warp_m = wid & 3;            // rows warp_m*32
    const int warp_n = wid >> 2;           // cols warp_n*64
    const int qr = lane >> 2;
    const int qc = lane & 3;

    const uint32_t base = smem_u32(sm);

    float acc[2][8][4];
    #pragma unroll
    for (int mt = 0; mt < 2; mt++)
        #pragma unroll
        for (int nt = 0; nt < 8; nt++)
            #pragma unroll
            for (int i = 0; i < 4; i++)
                acc[mt][nt][i] = 0.0f;

    const int KT = K / GBK;   // 32

    // Prologue: load stages for kt=0, kt=1
    gemm_load_stage(A, BT, K, base, base + A_TILE_H * 2, brow, bcol, 0, tid);
    cp_commit();
    gemm_load_stage(A, BT, K, base + STAGE_B, base + STAGE_B + A_TILE_H * 2,
                    brow, bcol, GBK, tid);
    cp_commit();

    // per-lane ldmatrix offsets (halves)
    const int la_off = (warp_m * 32 + (lane & 15)) * STRH + (lane >> 4) * 8;
    const int g = lane >> 3;
    const int lb_off = (warp_n * 64 + ((g & 2) ? 8 : 0) + (lane & 7)) * STRH
                     + (g & 1) * 8;

    uint32_t fa[2][8], fb[2][16];

    cp_wait<1>();          // stage 0 resident (this thread)
    __syncthreads();       // ...and all threads' copies visible
    LOAD_FRAGS(fa[0], fb[0], base, base + A_TILE_H * 2, 0);   // k16=0 of kt=0

    int st = 0;
    for (int kt = 0; kt < KT; kt++) {
        // issue global loads for kt+2 into stage (kt+2)%3
        // (== stage kt-1, whose readers were proven done by last barrier)
        const int lkt = kt + 2;
        if (lkt < KT) {
            int fst = st + 2; if (fst >= 3) fst -= 3;
            const uint32_t pa = base + fst * STAGE_B;
            gemm_load_stage(A, BT, K, pa, pa + A_TILE_H * 2, brow, bcol,
                            lkt * GBK, tid);
        }
        cp_commit();

        const uint32_t sa = base + st * STAGE_B;
        const uint32_t sb = sa + A_TILE_H * 2;

        // k16 = 0..2: prefetch next k16 fragments (same stage), then MMA
        #pragma unroll
        for (int k16 = 0; k16 < 3; k16++) {
            const int cur = k16 & 1, nxt = cur ^ 1;
            LOAD_FRAGS(fa[nxt], fb[nxt], sa, sb, (k16 + 1) * 16);
            MMA_BLOCK(cur);
        }
        // k16 = 3: MMA on the last fragment set (no prefetch in flight)
        MMA_BLOCK(1);

        // stage boundary: wait for stage kt+1's copies (own), barrier for
        // cross-thread visibility AND to free stage st for next iteration's
        // load issue, THEN prefetch next stage's k0 fragments.
        cp_wait<1>();
        __syncthreads();
        int nst = st + 1; if (nst >= 3) nst -= 3;
        if (kt + 1 < KT) {
            const uint32_t na = base + nst * STAGE_B;
            LOAD_FRAGS(fa[0], fb[0], na, na + A_TILE_H * 2, 0);
        }
        st = nst;
    }

    // Epilogue
    #pragma unroll
    for (int mt = 0; mt < 2; mt++) {
        const int row0 = brow + warp_m * 32 + mt * 16 + qr;
        #pragma unroll
        for (int nt = 0; nt < 8; nt++) {
            const int col = bcol + warp_n * 64 + nt * 8 + 2 * qc;
            const float2 bb = *(const float2*)&bias[col];
            const float vx = acc[mt][nt][0] + bb.x;
            const float vy = acc[mt][nt][1] + bb.y;
            const float wx = acc[mt][nt][2] + bb.x;
            const float wy = acc[mt][nt][3] + bb.y;
            if (OUT_HALF) {
                __half* C = (__half*)Cv;
                *(uint32_t*)&C[(size_t)row0 * N + col]       = pack_h2(vx, vy);
                *(uint32_t*)&C[(size_t)(row0 + 8) * N + col] = pack_h2(wx, wy);
            } else {
                float* C = (float*)Cv;
                float2 o0; o0.x = vx; o0.y = vy;
                float2 o1; o1.x = wx; o1.y = wy;
                *(float2*)&C[(size_t)row0 * N + col]       = o0;
                *(float2*)&C[(size_t)(row0 + 8) * N + col] = o1;
            }
        }
    }
}

// ---------------------------------------------------------------------------
// fp16 tensor-core flash attention (causal, register softmax, ldmatrix).
// CTA: 128 q-rows, 256 threads (8 warps x 16 rows). KV tiles of 64,
// double-buffered cp.async. 2 CTAs/SM. Row stride 136 halves.
// ---------------------------------------------------------------------------
#define FBQ   128
#define FSTR  136
#define Q_BYTES     (128 * FSTR * 2)          // 34816
#define KV_TILE_B   (64 * FSTR * 2)           // 17408
#define KV_STAGE_B  (2 * KV_TILE_B)           // 34816
#define FLASH_SMEM  (Q_BYTES + 2 * KV_STAGE_B)  // 104448

__device__ __forceinline__ void load_kv_tile(
    uint32_t kbase, uint32_t vbase, size_t rowbase, int j0, int qcol, int tid)
{
    #pragma unroll
    for (int i = 0; i < 4; i++) {
        int idx = tid + i * 256;          // 0..1023
        int r = idx >> 4;                 // 0..63
        int c = idx & 15;
        cp_async16(kbase + (r * FSTR + c * 8) * 2,
                   &g_qkv[(rowbase + j0 + r) * (size_t)QKV_N + qcol + D_ + c * 8]);
    }
    #pragma unroll
    for (int i = 0; i < 4; i++) {
        int idx = tid + i * 256;
        int r = idx >> 4;
        int c = idx & 15;
        cp_async16(vbase + (r * FSTR + c * 8) * 2,
                   &g_qkv[(rowbase + j0 + r) * (size_t)QKV_N + qcol + 2 * D_ + c * 8]);
    }
}

__global__ __launch_bounds__(256, 2) void flash_mma_kernel()
{
    extern __shared__ char smc[];
    const int qi  = (gridDim.x - 1) - blockIdx.x;   // big q-blocks first
    const int q0  = qi * FBQ;
    const int h   = blockIdx.y;
    const int b   = blockIdx.z;
    const int tid = threadIdx.x;
    const int lane = tid & 31;
    const int wid  = tid >> 5;
    const int qr = lane >> 2;
    const int qc = lane & 3;

    const size_t rowbase = (size_t)b * T_;
    const int qcol = h * DH;
    const float SCALE = 0.08838834764831845f;   // 1/sqrt(128)

    const uint32_t base = smem_u32(smc);
    const uint32_t Qs = base;
    const int ntile = 2 * qi + 2;

    #pragma unroll
    for (int i = 0; i < 8; i++) {
        int idx = tid + i * 256;          // 0..2047
        int r = idx >> 4;
        int c = idx & 15;
        cp_async16(Qs + (r * FSTR + c * 8) * 2,
                   &g_qkv[(rowbase + q0 + r) * (size_t)QKV_N + qcol + c * 8]);
    }
    {
        uint32_t s0 = base + Q_BYTES;
        load_kv_tile(s0, s0 + KV_TILE_B, rowbase, 0, qcol, tid);
        cp_commit();
        if (ntile > 1) {
            uint32_t s1 = base + Q_BYTES + KV_STAGE_B;
            load_kv_tile(s1, s1 + KV_TILE_B, rowbase, 64, qcol, tid);
        }
        cp_commit();
    }

    float oacc[16][4];
    #pragma unroll
    for (int n = 0; n < 16; n++)
        #pragma unroll
        for (int i = 0; i < 4; i++) oacc[n][i] = 0.0f;
    float mrow0 = -3.0e38f, mrow1 = -3.0e38f;
    float lrow0 = 0.0f, lrow1 = 0.0f;

    const int mloc = wid * 16;
    const int g = lane >> 3;
    const int lq_off = (mloc + (lane & 15)) * FSTR + (lane >> 4) * 8;
    const int lk_off = (((g & 2) ? 8 : 0) + (lane & 7)) * FSTR + (g & 1) * 8;
    const int lv_off = ((g & 1) * 8 + (lane & 7)) * FSTR + ((g & 2) ? 8 : 0);

    for (int t = 0; t < ntile; t++) {
        cp_wait<1>();
        __syncthreads();

        const uint32_t Ks = base + Q_BYTES + (t & 1) * KV_STAGE_B;
        const uint32_t Vs = Ks + KV_TILE_B;

        // ---- S = Q @ K^T ----
        float sacc[8][4];
        #pragma unroll
        for (int n = 0; n < 8; n++)
            #pragma unroll
            for (int i = 0; i < 4; i++) sacc[n][i] = 0.0f;

        #pragma unroll
        for (int k16 = 0; k16 < 8; k16++) {
            const int ko = k16 * 16;
            uint32_t qa0, qa1, qa2, qa3;
            ldm_x4(qa0, qa1, qa2, qa3, Qs + (lq_off + ko) * 2);
            #pragma unroll
            for (int ntp = 0; ntp < 4; ntp++) {
                uint32_t b0, b1, b2, b3;
                ldm_x4(b0, b1, b2, b3, Ks + (lk_off + ntp * 16 * FSTR + ko) * 2);
                mma_f16(sacc[2 * ntp    ], qa0, qa1, qa2, qa3, b0, b1);
                mma_f16(sacc[2 * ntp + 1], qa0, qa1, qa2, qa3, b2, b3);
            }
        }

        // ---- causal mask (only last 2 tiles touch the diagonal) ----
        if (t >= ntile - 2) {
            const int j0 = t * 64;
            const int rg0 = q0 + mloc + qr;
            const int rg1 = rg0 + 8;
            #pragma unroll
            for (int nt = 0; nt < 8; nt++) {
                const int cg = j0 + nt * 8 + 2 * qc;
                if (cg     > rg0) sacc[nt][0] = -1.0e30f;
                if (cg + 1 > rg0) sacc[nt][1] = -1.0e30f;
                if (cg     > rg1) sacc[nt][2] = -1.0e30f;
                if (cg + 1 > rg1) sacc[nt][3] = -1.0e30f;
            }
        }

        // ---- online softmax (per-row, quad lanes) ----
        float mx0 = -3.0e38f, mx1 = -3.0e38f;
        #pragma unroll
        for (int nt = 0; nt < 8; nt++) {
            mx0 = fmaxf(mx0, fmaxf(sacc[nt][0], sacc[nt][1]));
            mx1 = fmaxf(mx1, fmaxf(sacc[nt][2], sacc[nt][3]));
        }
        mx0 = fmaxf(mx0, __shfl_xor_sync(0xFFFFFFFFu, mx0, 1));
        mx0 = fmaxf(mx0, __shfl_xor_sync(0xFFFFFFFFu, mx0, 2));
        mx1 = fmaxf(mx1, __shfl_xor_sync(0xFFFFFFFFu, mx1, 1));
        mx1 = fmaxf(mx1, __shfl_xor_sync(0xFFFFFFFFu, mx1, 2));
        const float mn0 = fmaxf(mrow0, mx0);
        const float mn1 = fmaxf(mrow1, mx1);
        const float al0 = __expf((mrow0 - mn0) * SCALE);
        const float al1 = __expf((mrow1 - mn1) * SCALE);
        mrow0 = mn0; mrow1 = mn1;

        float ps0 = 0.0f, ps1 = 0.0f;
        #pragma unroll
        for (int nt = 0; nt < 8; nt++) {
            sacc[nt][0] = __expf((sacc[nt][0] - mn0) * SCALE);
            sacc[nt][1] = __expf((sacc[nt][1] - mn0) * SCALE);
            sacc[nt][2] = __expf((sacc[nt][2] - mn1) * SCALE);
            sacc[nt][3] = __expf((sacc[nt][3] - mn1) * SCALE);
            ps0 += sacc[nt][0] + sacc[nt][1];
            ps1 += sacc[nt][2] + sacc[nt][3];
        }
        ps0 += __shfl_xor_sync(0xFFFFFFFFu, ps0, 1);
        ps0 += __shfl_xor_sync(0xFFFFFFFFu, ps0, 2);
        ps1 += __shfl_xor_sync(0xFFFFFFFFu, ps1, 1);
        ps1 += __shfl_xor_sync(0xFFFFFFFFu, ps1, 2);
        lrow0 = lrow0 * al0 + ps0;
        lrow1 = lrow1 * al1 + ps1;

        #pragma unroll
        for (int n = 0; n < 16; n++) {
            oacc[n][0] *= al0; oacc[n][1] *= al0;
            oacc[n][2] *= al1; oacc[n][3] *= al1;
        }

        // ---- P fragments: direct pack (C-layout == A-layout in fp16) ----
        uint32_t pA[4][4];
        #pragma unroll
        for (int j = 0; j < 4; j++) {
            pA[j][0] = pack_h2(sacc[2 * j][0],     sacc[2 * j][1]);
            pA[j][1] = pack_h2(sacc[2 * j][2],     sacc[2 * j][3]);
            pA[j][2] = pack_h2(sacc[2 * j + 1][0], sacc[2 * j + 1][1]);
            pA[j][3] = pack_h2(sacc[2 * j + 1][2], sacc[2 * j + 1][3]);
        }

        // ---- O += P @ V  (V^T fragments via ldmatrix.trans) ----
        #pragma unroll
        for (int j = 0; j < 4; j++) {
            #pragma unroll
            for (int ntp = 0; ntp < 8; ntp++) {
                uint32_t b0, b1, b2, b3;
                ldm_x4_t(b0, b1, b2, b3,
                         Vs + (lv_off + j * 16 * FSTR + ntp * 16) * 2);
                mma_f16(oacc[2 * ntp    ], pA[j][0], pA[j][1], pA[j][2], pA[j][3], b0, b1);
                mma_f16(oacc[2 * ntp + 1], pA[j][0], pA[j][1], pA[j][2], pA[j][3], b2, b3);
            }
        }

        __syncthreads();
        if (t + 2 < ntile) {
            uint32_t sb = base + Q_BYTES + (t & 1) * KV_STAGE_B;
            load_kv_tile(sb, sb + KV_TILE_B, rowbase, (t + 2) * 64, qcol, tid);
        }
        cp_commit();
    }

    // ---- epilogue: normalize, fp16 store (feeds out-proj GEMM) ----
    const float li0 = 1.0f / lrow0;
    const float li1 = 1.0f / lrow1;
    const int r0 = q0 + mloc + qr;
    const int r1 = r0 + 8;
    #pragma unroll
    for (int ntd = 0; ntd < 16; ntd++) {
        const int col = qcol + ntd * 8 + 2 * qc;
        *(uint32_t*)&g_o[(rowbase + r0) * (size_t)D_ + col] =
            pack_h2(oacc[ntd][0] * li0, oacc[ntd][1] * li0);
        *(uint32_t*)&g_o[(rowbase + r1) * (size_t)D_ + col] =
            pack_h2(oacc[ntd][2] * li1, oacc[ntd][3] * li1);
    }
}

// ---------------------------------------------------------------------------
// Launch
// ---------------------------------------------------------------------------
extern "C" void kernel_launch(void* const* d_in, const int* in_sizes, int n_in,
                              void* d_out, int out_size)
{
    (void)in_sizes; (void)n_in; (void)out_size;
    const float* x    = (const float*)d_in[0];
    const float* Wqkv = (const float*)d_in[1];
    const float* bqkv = (const float*)d_in[2];
    const float* Wout = (const float*)d_in[3];
    const float* bout = (const float*)d_in[4];
    float* out = (float*)d_out;

    static __half *qkv_ptr = nullptr, *o_ptr = nullptr, *xh_ptr = nullptr;
    static __half *wqkvT_ptr = nullptr, *woutT_ptr = nullptr;
    static bool init_done = false;
    if (!init_done) {
        // First call is the (uncaptured) correctness run; these immediate host
        // APIs never land inside graph capture.
        cudaFuncSetAttribute(flash_mma_kernel,
                             cudaFuncAttributeMaxDynamicSharedMemorySize,
                             FLASH_SMEM);
        cudaFuncSetAttribute(mma_gemm_bias<true>,
                             cudaFuncAttributeMaxDynamicSharedMemorySize,
                             GEMM_SMEM);
        cudaFuncSetAttribute(mma_gemm_bias<false>,
                             cudaFuncAttributeMaxDynamicSharedMemorySize,
                             GEMM_SMEM);
        void* p;
        cudaGetSymbolAddress(&p, g_qkv);   qkv_ptr   = (__half*)p;
        cudaGetSymbolAddress(&p, g_o);     o_ptr     = (__half*)p;
        cudaGetSymbolAddress(&p, g_xh);    xh_ptr    = (__half*)p;
        cudaGetSymbolAddress(&p, g_WqkvT); wqkvT_ptr = (__half*)p;
        cudaGetSymbolAddress(&p, g_WoutT); woutT_ptr = (__half*)p;
        init_done = true;
    }

    // 0) pre-pass: x -> fp16; weights -> transposed fp16 [N,K]
    f2h_kernel<<<(MROWS * (size_t)D_ / 8) / 256, 256>>>(x, xh_ptr);
    transpose_kernel<<<dim3(QKV_N / 32, D_ / 32), dim3(32, 8)>>>(Wqkv, wqkvT_ptr, D_, QKV_N);
    transpose_kernel<<<dim3(D_ / 32, D_ / 32), dim3(32, 8)>>>(Wout, woutT_ptr, D_, D_);

    // 1) QKV = x @ Wqkv + bqkv (fp16 mma, fp32 accum; fp16 output)
    mma_gemm_bias<true><<<dim3(QKV_N / GBN, MROWS / GBM), 256, GEMM_SMEM>>>(
        xh_ptr, wqkvT_ptr, bqkv, qkv_ptr, MROWS, QKV_N, D_);

    // 2) causal flash attention (fp16 tensor cores) -> g_o (fp16)
    flash_mma_kernel<<<dim3(T_ / FBQ, H_, B_), 256, FLASH_SMEM>>>();

    // 3) out = g_o @ Wout + bout (fp16 mma, fp32 output)
    mma_gemm_bias<false><<<dim3(D_ / GBN, MROWS / GBM), 256, GEMM_SMEM>>>(
        o_ptr, woutT_ptr, bout, out, MROWS, D_, D_);
}

// round 11
// speedup vs baseline: 2.3490x; 1.0067x over previous
#include <cuda_runtime.h>
#include <cuda_fp16.h>
#include <math.h>
#include <stdint.h>

#define B_  2
#define T_  2048
#define D_  2048
#define H_  16
#define DH  128
#define MROWS (B_*T_)          // 4096
#define QKV_N (3*D_)           // 6144

// Scratch (device globals — no allocation allowed); all fp16 operands
__device__ __half g_qkv[(size_t)MROWS * QKV_N];    // 50 MB
__device__ __half g_o[(size_t)MROWS * D_];         // 16 MB
__device__ __half g_xh[(size_t)MROWS * D_];        // 16 MB
__device__ __half g_WqkvT[(size_t)QKV_N * D_];     // 25 MB ([N,K] K-contig)
__device__ __half g_WoutT[(size_t)D_ * D_];        // 8 MB

// ---------------------------------------------------------------------------
// Helpers
// ---------------------------------------------------------------------------
__device__ __forceinline__ void cp_async16(uint32_t s, const void* g) {
    asm volatile("cp.async.cg.shared.global [%0], [%1], 16;" :: "r"(s), "l"(g));
}
__device__ __forceinline__ void cp_commit() {
    asm volatile("cp.async.commit_group;" ::: "memory");
}
template <int N> __device__ __forceinline__ void cp_wait() {
    asm volatile("cp.async.wait_group %0;" :: "n"(N) : "memory");
}
__device__ __forceinline__ uint32_t smem_u32(const void* p) {
    uint32_t a;
    asm("{ .reg .u64 t; cvta.to.shared.u64 t, %1; cvt.u32.u64 %0, t; }"
        : "=r"(a) : "l"(p));
    return a;
}
__device__ __forceinline__ void ldm_x4(uint32_t& r0, uint32_t& r1,
                                       uint32_t& r2, uint32_t& r3, uint32_t a) {
    asm volatile("ldmatrix.sync.aligned.m8n8.x4.shared.b16 {%0,%1,%2,%3}, [%4];"
                 : "=r"(r0), "=r"(r1), "=r"(r2), "=r"(r3) : "r"(a));
}
__device__ __forceinline__ void ldm_x4_t(uint32_t& r0, uint32_t& r1,
                                         uint32_t& r2, uint32_t& r3, uint32_t a) {
    asm volatile("ldmatrix.sync.aligned.m8n8.x4.trans.shared.b16 {%0,%1,%2,%3}, [%4];"
                 : "=r"(r0), "=r"(r1), "=r"(r2), "=r"(r3) : "r"(a));
}
__device__ __forceinline__ void mma_f16(float c[4],
    uint32_t a0, uint32_t a1, uint32_t a2, uint32_t a3,
    uint32_t b0, uint32_t b1)
{
    asm volatile(
        "mma.sync.aligned.m16n8k16.row.col.f32.f16.f16.f32 "
        "{%0,%1,%2,%3}, {%4,%5,%6,%7}, {%8,%9}, {%0,%1,%2,%3};"
        : "+f"(c[0]), "+f"(c[1]), "+f"(c[2]), "+f"(c[3])
        : "r"(a0), "r"(a1), "r"(a2), "r"(a3), "r"(b0), "r"(b1));
}
__device__ __forceinline__ uint32_t pack_h2(float x, float y) {
    __half2 h = __floats2half2_rn(x, y);
    return *(uint32_t*)&h;
}

// ---------------------------------------------------------------------------
// x pre-pass: fp32 -> fp16. Each thread converts 8 floats.
// ---------------------------------------------------------------------------
__global__ __launch_bounds__(256) void f2h_kernel(
    const float* __restrict__ in, __half* __restrict__ out)
{
    const size_t i = (size_t)blockIdx.x * 256 + threadIdx.x;
    float4 a = ((const float4*)in)[2 * i];
    float4 b = ((const float4*)in)[2 * i + 1];
    uint4 u;
    u.x = pack_h2(a.x, a.y); u.y = pack_h2(a.z, a.w);
    u.z = pack_h2(b.x, b.y); u.w = pack_h2(b.z, b.w);
    ((uint4*)out)[i] = u;
}

// ---------------------------------------------------------------------------
// Weight transpose + fp16: At[N,K] = h(A[K,N]^T)
// ---------------------------------------------------------------------------
__global__ __launch_bounds__(256) void transpose_kernel(
    const float* __restrict__ A, __half* __restrict__ At, int R, int C)
{
    __shared__ float tile[32][33];
    const int c = blockIdx.x * 32 + threadIdx.x;
    const int r = blockIdx.y * 32 + threadIdx.y;
    #pragma unroll
    for (int i = 0; i < 32; i += 8)
        tile[threadIdx.y + i][threadIdx.x] = A[(size_t)(r + i) * C + c];
    __syncthreads();
    const int tc = blockIdx.y * 32 + threadIdx.x;
    const int tr = blockIdx.x * 32 + threadIdx.y;
    #pragma unroll
    for (int i = 0; i < 32; i += 8)
        At[(size_t)(tr + i) * R + tc] = __float2half_rn(tile[threadIdx.x][threadIdx.y + i]);
}

// ---------------------------------------------------------------------------
// fp16 mma.sync GEMM + bias: C[M,N] = A[M,K] @ BT[N,K]^T + bias[N]
// CTA 128x128, 256 threads (8 warps, 4m x 2n), warp tile 32x64.
// BK=64 halves, rotated 3-stage cp.async pipeline, ONE barrier/iteration,
// register-level fragment double-buffering, and a ROTATED stage boundary:
// cp_wait + barrier happen BEFORE the last MMA block of each stage, so the
// next stage's k0 LDSM chain is hidden under MMA k3 (the R10 version exposed
// one LDSM chain per BK at the boundary).
// 2 CTAs/SM (smem 110592 x2 <= 228KB, regs <= 128).
// ---------------------------------------------------------------------------
#define GBM 128
#define GBN 128
#define GBK 64
#define STRH 72
#define A_TILE_H (128 * STRH)                 // 9216 halves
#define B_TILE_H (128 * STRH)                 // 9216
#define STAGE_B  ((A_TILE_H + B_TILE_H) * 2)  // 36864 bytes
#define GEMM_SMEM (3 * STAGE_B)               // 110592

__device__ __forceinline__ void gemm_load_stage(
    const __half* __restrict__ A, const __half* __restrict__ BT, int K,
    uint32_t sa, uint32_t sb, int brow, int bcol, int k0, int tid)
{
    #pragma unroll
    for (int i = 0; i < 4; i++) {           // A: 128 rows x 8 chunks
        int idx = tid + i * 256;            // 0..1023
        int row = idx >> 3;
        int c = idx & 7;
        cp_async16(sa + (row * STRH + c * 8) * 2,
                   &A[(size_t)(brow + row) * K + k0 + c * 8]);
    }
    #pragma unroll
    for (int i = 0; i < 4; i++) {           // B^T: 128 n-rows x 8 chunks
        int idx = tid + i * 256;
        int row = idx >> 3;
        int c = idx & 7;
        cp_async16(sb + (row * STRH + c * 8) * 2,
                   &BT[(size_t)(bcol + row) * K + k0 + c * 8]);
    }
}

// load one k16 fragment set (6 ldmatrix.x4) from stage (sa, sb) at k-offset ko
#define LOAD_FRAGS(FA, FB, sa, sb, ko)                                        \
    do {                                                                      \
        ldm_x4((FA)[0], (FA)[1], (FA)[2], (FA)[3],                            \
               (sa) + (la_off + (ko)) * 2);                                   \
        ldm_x4((FA)[4], (FA)[5], (FA)[6], (FA)[7],                            \
               (sa) + (la_off + 16 * STRH + (ko)) * 2);                       \
        ldm_x4((FB)[0], (FB)[1], (FB)[2], (FB)[3],                            \
               (sb) + (lb_off + (ko)) * 2);                                   \
        ldm_x4((FB)[4], (FB)[5], (FB)[6], (FB)[7],                            \
               (sb) + (lb_off + 16 * STRH + (ko)) * 2);                       \
        ldm_x4((FB)[8], (FB)[9], (FB)[10], (FB)[11],                          \
               (sb) + (lb_off + 32 * STRH + (ko)) * 2);                       \
        ldm_x4((FB)[12], (FB)[13], (FB)[14], (FB)[15],                        \
               (sb) + (lb_off + 48 * STRH + (ko)) * 2);                       \
    } while (0)

#define MMA_BLOCK(cur)                                                                                     \
    do {                                                                                                   \
        mma_f16(acc[0][0], fa[cur][0], fa[cur][1], fa[cur][2], fa[cur][3], fb[cur][0],  fb[cur][1]);       \
        mma_f16(acc[1][0], fa[cur][4], fa[cur][5], fa[cur][6], fa[cur][7], fb[cur][0],  fb[cur][1]);       \
        mma_f16(acc[0][1], fa[cur][0], fa[cur][1], fa[cur][2], fa[cur][3], fb[cur][2],  fb[cur][3]);       \
        mma_f16(acc[1][1], fa[cur][4], fa[cur][5], fa[cur][6], fa[cur][7], fb[cur][2],  fb[cur][3]);       \
        mma_f16(acc[0][2], fa[cur][0], fa[cur][1], fa[cur][2], fa[cur][3], fb[cur][4],  fb[cur][5]);       \
        mma_f16(acc[1][2], fa[cur][4], fa[cur][5], fa[cur][6], fa[cur][7], fb[cur][4],  fb[cur][5]);       \
        mma_f16(acc[0][3], fa[cur][0], fa[cur][1], fa[cur][2], fa[cur][3], fb[cur][6],  fb[cur][7]);       \
        mma_f16(acc[1][3], fa[cur][4], fa[cur][5], fa[cur][6], fa[cur][7], fb[cur][6],  fb[cur][7]);       \
        mma_f16(acc[0][4], fa[cur][0], fa[cur][1], fa[cur][2], fa[cur][3], fb[cur][8],  fb[cur][9]);       \
        mma_f16(acc[1][4], fa[cur][4], fa[cur][5], fa[cur][6], fa[cur][7], fb[cur][8],  fb[cur][9]);       \
        mma_f16(acc[0][5], fa[cur][0], fa[cur][1], fa[cur][2], fa[cur][3], fb[cur][10], fb[cur][11]);      \
        mma_f16(acc[1][5], fa[cur][4], fa[cur][5], fa[cur][6], fa[cur][7], fb[cur][10], fb[cur][11]);      \
        mma_f16(acc[0][6], fa[cur][0], fa[cur][1], fa[cur][2], fa[cur][3], fb[cur][12], fb[cur][13]);      \
        mma_f16(acc[1][6], fa[cur][4], fa[cur][5], fa[cur][6], fa[cur][7], fb[cur][12], fb[cur][13]);      \
        mma_f16(acc[0][7], fa[cur][0], fa[cur][1], fa[cur][2], fa[cur][3], fb[cur][14], fb[cur][15]);      \
        mma_f16(acc[1][7], fa[cur][4], fa[cur][5], fa[cur][6], fa[cur][7], fb[cur][14], fb[cur][15]);      \
    } while (0)

template <bool OUT_HALF>
__global__ __launch_bounds__(256, 2) void mma_gemm_bias(
    const __half* __restrict__ A, const __half* __restrict__ BT,
    const float* __restrict__ bias, void* __restrict__ Cv,
    int M, int N, int K)
{
    extern __shared__ char sm[];
    const int tid  = threadIdx.x;
    const int wid  = tid >> 5;
    const int lane = tid & 31;
    const int brow = blockIdx.y * GBM;
    const int bcol = blockIdx.x * GBN;
    const int warp_m = wid & 3;            // rows warp_m*32
    const int warp_n = wid >> 2;           // cols warp_n*64
    const int qr = lane >> 2;
    const int qc = lane & 3;

    const uint32_t base = smem_u32(sm);

    float acc[2][8][4];
    #pragma unroll
    for (int mt = 0; mt < 2; mt++)
        #pragma unroll
        for (int nt = 0; nt < 8; nt++)
            #pragma unroll
            for (int i = 0; i < 4; i++)
                acc[mt][nt][i] = 0.0f;

    const int KT = K / GBK;   // 32

    // Prologue: load stages for kt=0, kt=1
    gemm_load_stage(A, BT, K, base, base + A_TILE_H * 2, brow, bcol, 0, tid);
    cp_commit();
    gemm_load_stage(A, BT, K, base + STAGE_B, base + STAGE_B + A_TILE_H * 2,
                    brow, bcol, GBK, tid);
    cp_commit();

    // per-lane ldmatrix offsets (halves)
    const int la_off = (warp_m * 32 + (lane & 15)) * STRH + (lane >> 4) * 8;
    const int g = lane >> 3;
    const int lb_off = (warp_n * 64 + ((g & 2) ? 8 : 0) + (lane & 7)) * STRH
                     + (g & 1) * 8;

    uint32_t fa[2][8], fb[2][16];

    cp_wait<1>();          // stage 0 resident (this thread)
    __syncthreads();       // ...and all threads' copies visible
    LOAD_FRAGS(fa[0], fb[0], base, base + A_TILE_H * 2, 0);   // k16=0 of kt=0

    int st = 0;
    for (int kt = 0; kt < KT; kt++) {
        // issue global loads for kt+2 into stage (kt+2)%3
        // (== stage kt-1, whose readers were proven done by last barrier)
        const int lkt = kt + 2;
        if (lkt < KT) {
            int fst = st + 2; if (fst >= 3) fst -= 3;
            const uint32_t pa = base + fst * STAGE_B;
            gemm_load_stage(A, BT, K, pa, pa + A_TILE_H * 2, brow, bcol,
                            lkt * GBK, tid);
        }
        cp_commit();

        const uint32_t sa = base + st * STAGE_B;
        const uint32_t sb = sa + A_TILE_H * 2;

        // k16 = 0..2: prefetch next k16 fragments (same stage), then MMA.
        // The k16=2 prefetch (of k3) is this warp's LAST read of stage st.
        #pragma unroll
        for (int k16 = 0; k16 < 3; k16++) {
            const int cur = k16 & 1, nxt = cur ^ 1;
            LOAD_FRAGS(fa[nxt], fb[nxt], sa, sb, (k16 + 1) * 16);
            MMA_BLOCK(cur);
        }

        // Rotated stage boundary: wait for stage kt+1's copies (own groups),
        // barrier for cross-thread visibility (all stage-st reads are done),
        // prefetch next stage's k0 fragments, THEN run MMA k3 — the 16 MMAs
        // hide the next-stage LDSM latency.
        cp_wait<1>();
        __syncthreads();
        int nst = st + 1; if (nst >= 3) nst -= 3;
        if (kt + 1 < KT) {
            const uint32_t na = base + nst * STAGE_B;
            LOAD_FRAGS(fa[0], fb[0], na, na + A_TILE_H * 2, 0);
        }
        MMA_BLOCK(1);      // k3 (fragments already in registers)
        st = nst;
    }

    // Epilogue
    #pragma unroll
    for (int mt = 0; mt < 2; mt++) {
        const int row0 = brow + warp_m * 32 + mt * 16 + qr;
        #pragma unroll
        for (int nt = 0; nt < 8; nt++) {
            const int col = bcol + warp_n * 64 + nt * 8 + 2 * qc;
            const float2 bb = *(const float2*)&bias[col];
            const float vx = acc[mt][nt][0] + bb.x;
            const float vy = acc[mt][nt][1] + bb.y;
            const float wx = acc[mt][nt][2] + bb.x;
            const float wy = acc[mt][nt][3] + bb.y;
            if (OUT_HALF) {
                __half* C = (__half*)Cv;
                *(uint32_t*)&C[(size_t)row0 * N + col]       = pack_h2(vx, vy);
                *(uint32_t*)&C[(size_t)(row0 + 8) * N + col] = pack_h2(wx, wy);
            } else {
                float* C = (float*)Cv;
                float2 o0; o0.x = vx; o0.y = vy;
                float2 o1; o1.x = wx; o1.y = wy;
                *(float2*)&C[(size_t)row0 * N + col]       = o0;
                *(float2*)&C[(size_t)(row0 + 8) * N + col] = o1;
            }
        }
    }
}

// ---------------------------------------------------------------------------
// fp16 tensor-core flash attention (causal, register softmax, ldmatrix).
// CTA: 128 q-rows, 256 threads (8 warps x 16 rows). KV tiles of 64,
// double-buffered cp.async. 2 CTAs/SM. Row stride 136 halves.
// ---------------------------------------------------------------------------
#define FBQ   128
#define FSTR  136
#define Q_BYTES     (128 * FSTR * 2)          // 34816
#define KV_TILE_B   (64 * FSTR * 2)           // 17408
#define KV_STAGE_B  (2 * KV_TILE_B)           // 34816
#define FLASH_SMEM  (Q_BYTES + 2 * KV_STAGE_B)  // 104448

__device__ __forceinline__ void load_kv_tile(
    uint32_t kbase, uint32_t vbase, size_t rowbase, int j0, int qcol, int tid)
{
    #pragma unroll
    for (int i = 0; i < 4; i++) {
        int idx = tid + i * 256;          // 0..1023
        int r = idx >> 4;                 // 0..63
        int c = idx & 15;
        cp_async16(kbase + (r * FSTR + c * 8) * 2,
                   &g_qkv[(rowbase + j0 + r) * (size_t)QKV_N + qcol + D_ + c * 8]);
    }
    #pragma unroll
    for (int i = 0; i < 4; i++) {
        int idx = tid + i * 256;
        int r = idx >> 4;
        int c = idx & 15;
        cp_async16(vbase + (r * FSTR + c * 8) * 2,
                   &g_qkv[(rowbase + j0 + r) * (size_t)QKV_N + qcol + 2 * D_ + c * 8]);
    }
}

__global__ __launch_bounds__(256, 2) void flash_mma_kernel()
{
    extern __shared__ char smc[];
    const int qi  = (gridDim.x - 1) - blockIdx.x;   // big q-blocks first
    const int q0  = qi * FBQ;
    const int h   = blockIdx.y;
    const int b   = blockIdx.z;
    const int tid = threadIdx.x;
    const int lane = tid & 31;
    const int wid  = tid >> 5;
    const int qr = lane >> 2;
    const int qc = lane & 3;

    const size_t rowbase = (size_t)b * T_;
    const int qcol = h * DH;
    const float SCALE = 0.08838834764831845f;   // 1/sqrt(128)

    const uint32_t base = smem_u32(smc);
    const uint32_t Qs = base;
    const int ntile = 2 * qi + 2;

    #pragma unroll
    for (int i = 0; i < 8; i++) {
        int idx = tid + i * 256;          // 0..2047
        int r = idx >> 4;
        int c = idx & 15;
        cp_async16(Qs + (r * FSTR + c * 8) * 2,
                   &g_qkv[(rowbase + q0 + r) * (size_t)QKV_N + qcol + c * 8]);
    }
    {
        uint32_t s0 = base + Q_BYTES;
        load_kv_tile(s0, s0 + KV_TILE_B, rowbase, 0, qcol, tid);
        cp_commit();
        if (ntile > 1) {
            uint32_t s1 = base + Q_BYTES + KV_STAGE_B;
            load_kv_tile(s1, s1 + KV_TILE_B, rowbase, 64, qcol, tid);
        }
        cp_commit();
    }

    float oacc[16][4];
    #pragma unroll
    for (int n = 0; n < 16; n++)
        #pragma unroll
        for (int i = 0; i < 4; i++) oacc[n][i] = 0.0f;
    float mrow0 = -3.0e38f, mrow1 = -3.0e38f;
    float lrow0 = 0.0f, lrow1 = 0.0f;

    const int mloc = wid * 16;
    const int g = lane >> 3;
    const int lq_off = (mloc + (lane & 15)) * FSTR + (lane >> 4) * 8;
    const int lk_off = (((g & 2) ? 8 : 0) + (lane & 7)) * FSTR + (g & 1) * 8;
    const int lv_off = ((g & 1) * 8 + (lane & 7)) * FSTR + ((g & 2) ? 8 : 0);

    for (int t = 0; t < ntile; t++) {
        cp_wait<1>();
        __syncthreads();

        const uint32_t Ks = base + Q_BYTES + (t & 1) * KV_STAGE_B;
        const uint32_t Vs = Ks + KV_TILE_B;

        // ---- S = Q @ K^T ----
        float sacc[8][4];
        #pragma unroll
        for (int n = 0; n < 8; n++)
            #pragma unroll
            for (int i = 0; i < 4; i++) sacc[n][i] = 0.0f;

        #pragma unroll
        for (int k16 = 0; k16 < 8; k16++) {
            const int ko = k16 * 16;
            uint32_t qa0, qa1, qa2, qa3;
            ldm_x4(qa0, qa1, qa2, qa3, Qs + (lq_off + ko) * 2);
            #pragma unroll
            for (int ntp = 0; ntp < 4; ntp++) {
                uint32_t b0, b1, b2, b3;
                ldm_x4(b0, b1, b2, b3, Ks + (lk_off + ntp * 16 * FSTR + ko) * 2);
                mma_f16(sacc[2 * ntp    ], qa0, qa1, qa2, qa3, b0, b1);
                mma_f16(sacc[2 * ntp + 1], qa0, qa1, qa2, qa3, b2, b3);
            }
        }

        // ---- causal mask (only last 2 tiles touch the diagonal) ----
        if (t >= ntile - 2) {
            const int j0 = t * 64;
            const int rg0 = q0 + mloc + qr;
            const int rg1 = rg0 + 8;
            #pragma unroll
            for (int nt = 0; nt < 8; nt++) {
                const int cg = j0 + nt * 8 + 2 * qc;
                if (cg     > rg0) sacc[nt][0] = -1.0e30f;
                if (cg + 1 > rg0) sacc[nt][1] = -1.0e30f;
                if (cg     > rg1) sacc[nt][2] = -1.0e30f;
                if (cg + 1 > rg1) sacc[nt][3] = -1.0e30f;
            }
        }

        // ---- online softmax (per-row, quad lanes) ----
        float mx0 = -3.0e38f, mx1 = -3.0e38f;
        #pragma unroll
        for (int nt = 0; nt < 8; nt++) {
            mx0 = fmaxf(mx0, fmaxf(sacc[nt][0], sacc[nt][1]));
            mx1 = fmaxf(mx1, fmaxf(sacc[nt][2], sacc[nt][3]));
        }
        mx0 = fmaxf(mx0, __shfl_xor_sync(0xFFFFFFFFu, mx0, 1));
        mx0 = fmaxf(mx0, __shfl_xor_sync(0xFFFFFFFFu, mx0, 2));
        mx1 = fmaxf(mx1, __shfl_xor_sync(0xFFFFFFFFu, mx1, 1));
        mx1 = fmaxf(mx1, __shfl_xor_sync(0xFFFFFFFFu, mx1, 2));
        const float mn0 = fmaxf(mrow0, mx0);
        const float mn1 = fmaxf(mrow1, mx1);
        const float al0 = __expf((mrow0 - mn0) * SCALE);
        const float al1 = __expf((mrow1 - mn1) * SCALE);
        mrow0 = mn0; mrow1 = mn1;

        float ps0 = 0.0f, ps1 = 0.0f;
        #pragma unroll
        for (int nt = 0; nt < 8; nt++) {
            sacc[nt][0] = __expf((sacc[nt][0] - mn0) * SCALE);
            sacc[nt][1] = __expf((sacc[nt][1] - mn0) * SCALE);
            sacc[nt][2] = __expf((sacc[nt][2] - mn1) * SCALE);
            sacc[nt][3] = __expf((sacc[nt][3] - mn1) * SCALE);
            ps0 += sacc[nt][0] + sacc[nt][1];
            ps1 += sacc[nt][2] + sacc[nt][3];
        }
        ps0 += __shfl_xor_sync(0xFFFFFFFFu, ps0, 1);
        ps0 += __shfl_xor_sync(0xFFFFFFFFu, ps0, 2);
        ps1 += __shfl_xor_sync(0xFFFFFFFFu, ps1, 1);
        ps1 += __shfl_xor_sync(0xFFFFFFFFu, ps1, 2);
        lrow0 = lrow0 * al0 + ps0;
        lrow1 = lrow1 * al1 + ps1;

        #pragma unroll
        for (int n = 0; n < 16; n++) {
            oacc[n][0] *= al0; oacc[n][1] *= al0;
            oacc[n][2] *= al1; oacc[n][3] *= al1;
        }

        // ---- P fragments: direct pack (C-layout == A-layout in fp16) ----
        uint32_t pA[4][4];
        #pragma unroll
        for (int j = 0; j < 4; j++) {
            pA[j][0] = pack_h2(sacc[2 * j][0],     sacc[2 * j][1]);
            pA[j][1] = pack_h2(sacc[2 * j][2],     sacc[2 * j][3]);
            pA[j][2] = pack_h2(sacc[2 * j + 1][0], sacc[2 * j + 1][1]);
            pA[j][3] = pack_h2(sacc[2 * j + 1][2], sacc[2 * j + 1][3]);
        }

        // ---- O += P @ V  (V^T fragments via ldmatrix.trans) ----
        #pragma unroll
        for (int j = 0; j < 4; j++) {
            #pragma unroll
            for (int ntp = 0; ntp < 8; ntp++) {
                uint32_t b0, b1, b2, b3;
                ldm_x4_t(b0, b1, b2, b3,
                         Vs + (lv_off + j * 16 * FSTR + ntp * 16) * 2);
                mma_f16(oacc[2 * ntp    ], pA[j][0], pA[j][1], pA[j][2], pA[j][3], b0, b1);
                mma_f16(oacc[2 * ntp + 1], pA[j][0], pA[j][1], pA[j][2], pA[j][3], b2, b3);
            }
        }

        __syncthreads();
        if (t + 2 < ntile) {
            uint32_t sb = base + Q_BYTES + (t & 1) * KV_STAGE_B;
            load_kv_tile(sb, sb + KV_TILE_B, rowbase, (t + 2) * 64, qcol, tid);
        }
        cp_commit();
    }

    // ---- epilogue: normalize, fp16 store (feeds out-proj GEMM) ----
    const float li0 = 1.0f / lrow0;
    const float li1 = 1.0f / lrow1;
    const int r0 = q0 + mloc + qr;
    const int r1 = r0 + 8;
    #pragma unroll
    for (int ntd = 0; ntd < 16; ntd++) {
        const int col = qcol + ntd * 8 + 2 * qc;
        *(uint32_t*)&g_o[(rowbase + r0) * (size_t)D_ + col] =
            pack_h2(oacc[ntd][0] * li0, oacc[ntd][1] * li0);
        *(uint32_t*)&g_o[(rowbase + r1) * (size_t)D_ + col] =
            pack_h2(oacc[ntd][2] * li1, oacc[ntd][3] * li1);
    }
}

// ---------------------------------------------------------------------------
// Launch
// ---------------------------------------------------------------------------
extern "C" void kernel_launch(void* const* d_in, const int* in_sizes, int n_in,
                              void* d_out, int out_size)
{
    (void)in_sizes; (void)n_in; (void)out_size;
    const float* x    = (const float*)d_in[0];
    const float* Wqkv = (const float*)d_in[1];
    const float* bqkv = (const float*)d_in[2];
    const float* Wout = (const float*)d_in[3];
    const float* bout = (const float*)d_in[4];
    float* out = (float*)d_out;

    static __half *qkv_ptr = nullptr, *o_ptr = nullptr, *xh_ptr = nullptr;
    static __half *wqkvT_ptr = nullptr, *woutT_ptr = nullptr;
    static bool init_done = false;
    if (!init_done) {
        // First call is the (uncaptured) correctness run; these immediate host
        // APIs never land inside graph capture.
        cudaFuncSetAttribute(flash_mma_kernel,
                             cudaFuncAttributeMaxDynamicSharedMemorySize,
                             FLASH_SMEM);
        cudaFuncSetAttribute(mma_gemm_bias<true>,
                             cudaFuncAttributeMaxDynamicSharedMemorySize,
                             GEMM_SMEM);
        cudaFuncSetAttribute(mma_gemm_bias<false>,
                             cudaFuncAttributeMaxDynamicSharedMemorySize,
                             GEMM_SMEM);
        void* p;
        cudaGetSymbolAddress(&p, g_qkv);   qkv_ptr   = (__half*)p;
        cudaGetSymbolAddress(&p, g_o);     o_ptr     = (__half*)p;
        cudaGetSymbolAddress(&p, g_xh);    xh_ptr    = (__half*)p;
        cudaGetSymbolAddress(&p, g_WqkvT); wqkvT_ptr = (__half*)p;
        cudaGetSymbolAddress(&p, g_WoutT); woutT_ptr = (__half*)p;
        init_done = true;
    }

    // 0) pre-pass: x -> fp16; weights -> transposed fp16 [N,K]
    f2h_kernel<<<(MROWS * (size_t)D_ / 8) / 256, 256>>>(x, xh_ptr);
    transpose_kernel<<<dim3(QKV_N / 32, D_ / 32), dim3(32, 8)>>>(Wqkv, wqkvT_ptr, D_, QKV_N);
    transpose_kernel<<<dim3(D_ / 32, D_ / 32), dim3(32, 8)>>>(Wout, woutT_ptr, D_, D_);

    // 1) QKV = x @ Wqkv + bqkv (fp16 mma, fp32 accum; fp16 output)
    mma_gemm_bias<true><<<dim3(QKV_N / GBN, MROWS / GBM), 256, GEMM_SMEM>>>(
        xh_ptr, wqkvT_ptr, bqkv, qkv_ptr, MROWS, QKV_N, D_);

    // 2) causal flash attention (fp16 tensor cores) -> g_o (fp16)
    flash_mma_kernel<<<dim3(T_ / FBQ, H_, B_), 256, FLASH_SMEM>>>();

    // 3) out = g_o @ Wout + bout (fp16 mma, fp32 output)
    mma_gemm_bias<false><<<dim3(D_ / GBN, MROWS / GBM), 256, GEMM_SMEM>>>(
        o_ptr, woutT_ptr, bout, out, MROWS, D_, D_);
}

// round 12
// speedup vs baseline: 2.4939x; 1.0617x over previous
#include <cuda_runtime.h>
#include <cuda_fp16.h>
#include <math.h>
#include <stdint.h>

#define B_  2
#define T_  2048
#define D_  2048
#define H_  16
#define DH  128
#define MROWS (B_*T_)          // 4096
#define QKV_N (3*D_)           // 6144

// Scratch (device globals — no allocation allowed); all fp16 operands
__device__ __half g_qkv[(size_t)MROWS * QKV_N];    // 50 MB
__device__ __half g_o[(size_t)MROWS * D_];         // 16 MB
__device__ __half g_xh[(size_t)MROWS * D_];        // 16 MB
__device__ __half g_WqkvT[(size_t)QKV_N * D_];     // 25 MB ([N,K] K-contig)
__device__ __half g_WoutT[(size_t)D_ * D_];        // 8 MB

// ---------------------------------------------------------------------------
// Helpers
// ---------------------------------------------------------------------------
__device__ __forceinline__ void cp_async16(uint32_t s, const void* g) {
    asm volatile("cp.async.cg.shared.global [%0], [%1], 16;" :: "r"(s), "l"(g));
}
__device__ __forceinline__ void cp_commit() {
    asm volatile("cp.async.commit_group;" ::: "memory");
}
template <int N> __device__ __forceinline__ void cp_wait() {
    asm volatile("cp.async.wait_group %0;" :: "n"(N) : "memory");
}
__device__ __forceinline__ uint32_t smem_u32(const void* p) {
    uint32_t a;
    asm("{ .reg .u64 t; cvta.to.shared.u64 t, %1; cvt.u32.u64 %0, t; }"
        : "=r"(a) : "l"(p));
    return a;
}
__device__ __forceinline__ void ldm_x4(uint32_t& r0, uint32_t& r1,
                                       uint32_t& r2, uint32_t& r3, uint32_t a) {
    asm volatile("ldmatrix.sync.aligned.m8n8.x4.shared.b16 {%0,%1,%2,%3}, [%4];"
                 : "=r"(r0), "=r"(r1), "=r"(r2), "=r"(r3) : "r"(a));
}
__device__ __forceinline__ void ldm_x4_t(uint32_t& r0, uint32_t& r1,
                                         uint32_t& r2, uint32_t& r3, uint32_t a) {
    asm volatile("ldmatrix.sync.aligned.m8n8.x4.trans.shared.b16 {%0,%1,%2,%3}, [%4];"
                 : "=r"(r0), "=r"(r1), "=r"(r2), "=r"(r3) : "r"(a));
}
__device__ __forceinline__ void mma_f16(float c[4],
    uint32_t a0, uint32_t a1, uint32_t a2, uint32_t a3,
    uint32_t b0, uint32_t b1)
{
    asm volatile(
        "mma.sync.aligned.m16n8k16.row.col.f32.f16.f16.f32 "
        "{%0,%1,%2,%3}, {%4,%5,%6,%7}, {%8,%9}, {%0,%1,%2,%3};"
        : "+f"(c[0]), "+f"(c[1]), "+f"(c[2]), "+f"(c[3])
        : "r"(a0), "r"(a1), "r"(a2), "r"(a3), "r"(b0), "r"(b1));
}
__device__ __forceinline__ uint32_t pack_h2(float x, float y) {
    __half2 h = __floats2half2_rn(x, y);
    return *(uint32_t*)&h;
}

// ---------------------------------------------------------------------------
// x pre-pass: fp32 -> fp16. Each thread converts 8 floats.
// ---------------------------------------------------------------------------
__global__ __launch_bounds__(256) void f2h_kernel(
    const float* __restrict__ in, __half* __restrict__ out)
{
    const size_t i = (size_t)blockIdx.x * 256 + threadIdx.x;
    float4 a = ((const float4*)in)[2 * i];
    float4 b = ((const float4*)in)[2 * i + 1];
    uint4 u;
    u.x = pack_h2(a.x, a.y); u.y = pack_h2(a.z, a.w);
    u.z = pack_h2(b.x, b.y); u.w = pack_h2(b.z, b.w);
    ((uint4*)out)[i] = u;
}

// ---------------------------------------------------------------------------
// Weight transpose + fp16: At[N,K] = h(A[K,N]^T)
// ---------------------------------------------------------------------------
__global__ __launch_bounds__(256) void transpose_kernel(
    const float* __restrict__ A, __half* __restrict__ At, int R, int C)
{
    __shared__ float tile[32][33];
    const int c = blockIdx.x * 32 + threadIdx.x;
    const int r = blockIdx.y * 32 + threadIdx.y;
    #pragma unroll
    for (int i = 0; i < 32; i += 8)
        tile[threadIdx.y + i][threadIdx.x] = A[(size_t)(r + i) * C + c];
    __syncthreads();
    const int tc = blockIdx.y * 32 + threadIdx.x;
    const int tr = blockIdx.x * 32 + threadIdx.y;
    #pragma unroll
    for (int i = 0; i < 32; i += 8)
        At[(size_t)(tr + i) * R + tc] = __float2half_rn(tile[threadIdx.x][threadIdx.y + i]);
}

// ---------------------------------------------------------------------------
// fp16 mma.sync GEMM + bias: C[M,N] = A[M,K] @ BT[N,K]^T + bias[N]
// CTA 128x256, 256 threads (8 warps, 2m x 4n), warp tile 64x64 (4mt x 8nt).
// Rationale: 64x64 warp tile cuts fragment smem traffic to 128 B/MMA (from
// 192) — the R11 profile showed the GEMM smem-crossbar co-bound at ~264 B/MMA
// against a ~256 B per-2-cycle budget. Cost: ~216 regs -> 1 CTA/SM, so a
// 4-stage depth-3 cp.async pipeline provides the latency cover that the
// second CTA used to. Fragment double-buffering + rotated stage boundary
// retained from R11.
// ---------------------------------------------------------------------------
#define GBM 128
#define GBN 256
#define GBK 64
#define STRH 72
#define A_TILE_H (128 * STRH)                 // 9216 halves
#define B_TILE_H (256 * STRH)                 // 18432 halves
#define STAGE_B  ((A_TILE_H + B_TILE_H) * 2)  // 55296 bytes
#define GSTAGES  4
#define GEMM_SMEM (GSTAGES * STAGE_B)         // 221184

__device__ __forceinline__ void gemm_load_stage(
    const __half* __restrict__ A, const __half* __restrict__ BT, int K,
    uint32_t sa, uint32_t sb, int brow, int bcol, int k0, int tid)
{
    #pragma unroll
    for (int i = 0; i < 4; i++) {           // A: 128 rows x 8 chunks
        int idx = tid + i * 256;            // 0..1023
        int row = idx >> 3;
        int c = idx & 7;
        cp_async16(sa + (row * STRH + c * 8) * 2,
                   &A[(size_t)(brow + row) * K + k0 + c * 8]);
    }
    #pragma unroll
    for (int i = 0; i < 8; i++) {           // B^T: 256 n-rows x 8 chunks
        int idx = tid + i * 256;            // 0..2047
        int row = idx >> 3;
        int c = idx & 7;
        cp_async16(sb + (row * STRH + c * 8) * 2,
                   &BT[(size_t)(bcol + row) * K + k0 + c * 8]);
    }
}

// load one k16 fragment set (8 ldmatrix.x4: 4 A blocks + 4 B blocks)
#define LOAD_FRAGS(FA, FB, sa, sb, ko)                                        \
    do {                                                                      \
        ldm_x4((FA)[0],  (FA)[1],  (FA)[2],  (FA)[3],                         \
               (sa) + (la_off + (ko)) * 2);                                   \
        ldm_x4((FA)[4],  (FA)[5],  (FA)[6],  (FA)[7],                         \
               (sa) + (la_off + 16 * STRH + (ko)) * 2);                       \
        ldm_x4((FA)[8],  (FA)[9],  (FA)[10], (FA)[11],                        \
               (sa) + (la_off + 32 * STRH + (ko)) * 2);                       \
        ldm_x4((FA)[12], (FA)[13], (FA)[14], (FA)[15],                        \
               (sa) + (la_off + 48 * STRH + (ko)) * 2);                       \
        ldm_x4((FB)[0],  (FB)[1],  (FB)[2],  (FB)[3],                         \
               (sb) + (lb_off + (ko)) * 2);                                   \
        ldm_x4((FB)[4],  (FB)[5],  (FB)[6],  (FB)[7],                         \
               (sb) + (lb_off + 16 * STRH + (ko)) * 2);                       \
        ldm_x4((FB)[8],  (FB)[9],  (FB)[10], (FB)[11],                        \
               (sb) + (lb_off + 32 * STRH + (ko)) * 2);                       \
        ldm_x4((FB)[12], (FB)[13], (FB)[14], (FB)[15],                        \
               (sb) + (lb_off + 48 * STRH + (ko)) * 2);                       \
    } while (0)

// 32 MMAs: B col-block j (16 cols -> nt 2j, 2j+1), A row-block i (16 rows)
#define MMA_BLOCK(cur)                                                        \
    do {                                                                      \
        _Pragma("unroll")                                                     \
        for (int j = 0; j < 4; j++) {                                         \
            _Pragma("unroll")                                                 \
            for (int i = 0; i < 4; i++) {                                     \
                mma_f16(acc[i][2 * j],                                        \
                        fa[cur][4 * i], fa[cur][4 * i + 1],                   \
                        fa[cur][4 * i + 2], fa[cur][4 * i + 3],               \
                        fb[cur][4 * j], fb[cur][4 * j + 1]);                  \
                mma_f16(acc[i][2 * j + 1],                                    \
                        fa[cur][4 * i], fa[cur][4 * i + 1],                   \
                        fa[cur][4 * i + 2], fa[cur][4 * i + 3],               \
                        fb[cur][4 * j + 2], fb[cur][4 * j + 3]);              \
            }                                                                 \
        }                                                                     \
    } while (0)

template <bool OUT_HALF>
__global__ __launch_bounds__(256, 1) void mma_gemm_bias(
    const __half* __restrict__ A, const __half* __restrict__ BT,
    const float* __restrict__ bias, void* __restrict__ Cv,
    int M, int N, int K)
{
    extern __shared__ char sm[];
    const int tid  = threadIdx.x;
    const int wid  = tid >> 5;
    const int lane = tid & 31;
    const int brow = blockIdx.y * GBM;
    const int bcol = blockIdx.x * GBN;
    const int warp_m = wid & 1;            // rows warp_m*64
    const int warp_n = wid >> 1;           // cols warp_n*64
    const int qr = lane >> 2;
    const int qc = lane & 3;

    const uint32_t base = smem_u32(sm);

    float acc[4][8][4];
    #pragma unroll
    for (int mt = 0; mt < 4; mt++)
        #pragma unroll
        for (int nt = 0; nt < 8; nt++)
            #pragma unroll
            for (int i = 0; i < 4; i++)
                acc[mt][nt][i] = 0.0f;

    const int KT = K / GBK;   // 32

    // Prologue: load stages for kt=0,1,2 (pipeline depth 3, 4 physical stages)
    #pragma unroll
    for (int s = 0; s < 3; s++) {
        const uint32_t sa = base + s * STAGE_B;
        gemm_load_stage(A, BT, K, sa, sa + A_TILE_H * 2, brow, bcol,
                        s * GBK, tid);
        cp_commit();
    }

    // per-lane ldmatrix offsets (halves)
    const int la_off = (warp_m * 64 + (lane & 15)) * STRH + (lane >> 4) * 8;
    const int g = lane >> 3;
    const int lb_off = (warp_n * 64 + ((g & 2) ? 8 : 0) + (lane & 7)) * STRH
                     + (g & 1) * 8;

    uint32_t fa[2][16], fb[2][16];

    cp_wait<2>();          // stage 0 resident (this thread)
    __syncthreads();       // ...and all threads' copies visible
    LOAD_FRAGS(fa[0], fb[0], base, base + A_TILE_H * 2, 0);   // k16=0 of kt=0

    int st = 0;
    for (int kt = 0; kt < KT; kt++) {
        // issue global loads for kt+3 into stage (kt+3)%4
        // (== stage kt-1, whose readers were proven done by last barrier)
        const int lkt = kt + 3;
        if (lkt < KT) {
            int fst = st + 3; if (fst >= GSTAGES) fst -= GSTAGES;
            const uint32_t pa = base + fst * STAGE_B;
            gemm_load_stage(A, BT, K, pa, pa + A_TILE_H * 2, brow, bcol,
                            lkt * GBK, tid);
        }
        cp_commit();

        const uint32_t sa = base + st * STAGE_B;
        const uint32_t sb = sa + A_TILE_H * 2;

        // k16 = 0..2: prefetch next k16 fragments (same stage), then MMA.
        // The k16=2 prefetch (of k3) is this warp's LAST read of stage st.
        #pragma unroll
        for (int k16 = 0; k16 < 3; k16++) {
            const int cur = k16 & 1, nxt = cur ^ 1;
            LOAD_FRAGS(fa[nxt], fb[nxt], sa, sb, (k16 + 1) * 16);
            MMA_BLOCK(cur);
        }

        // Rotated stage boundary: wait for stage kt+1's copies (own groups),
        // barrier for cross-thread visibility (all stage-st reads done),
        // prefetch next stage's k0 fragments, THEN run MMA k3 — the 32 MMAs
        // hide the next-stage LDSM latency.
        cp_wait<2>();
        __syncthreads();
        int nst = st + 1; if (nst >= GSTAGES) nst -= GSTAGES;
        if (kt + 1 < KT) {
            const uint32_t na = base + nst * STAGE_B;
            LOAD_FRAGS(fa[0], fb[0], na, na + A_TILE_H * 2, 0);
        }
        MMA_BLOCK(1);      // k3 (fragments already in registers)
        st = nst;
    }

    // Epilogue
    #pragma unroll
    for (int mt = 0; mt < 4; mt++) {
        const int row0 = brow + warp_m * 64 + mt * 16 + qr;
        #pragma unroll
        for (int nt = 0; nt < 8; nt++) {
            const int col = bcol + warp_n * 64 + nt * 8 + 2 * qc;
            const float2 bb = *(const float2*)&bias[col];
            const float vx = acc[mt][nt][0] + bb.x;
            const float vy = acc[mt][nt][1] + bb.y;
            const float wx = acc[mt][nt][2] + bb.x;
            const float wy = acc[mt][nt][3] + bb.y;
            if (OUT_HALF) {
                __half* C = (__half*)Cv;
                *(uint32_t*)&C[(size_t)row0 * N + col]       = pack_h2(vx, vy);
                *(uint32_t*)&C[(size_t)(row0 + 8) * N + col] = pack_h2(wx, wy);
            } else {
                float* C = (float*)Cv;
                float2 o0; o0.x = vx; o0.y = vy;
                float2 o1; o1.x = wx; o1.y = wy;
                *(float2*)&C[(size_t)row0 * N + col]       = o0;
                *(float2*)&C[(size_t)(row0 + 8) * N + col] = o1;
            }
        }
    }
}

// ---------------------------------------------------------------------------
// fp16 tensor-core flash attention (causal, register softmax, ldmatrix).
// CTA: 128 q-rows, 256 threads (8 warps x 16 rows). KV tiles of 64,
// double-buffered cp.async. 2 CTAs/SM. Row stride 136 halves.
// ---------------------------------------------------------------------------
#define FBQ   128
#define FSTR  136
#define Q_BYTES     (128 * FSTR * 2)          // 34816
#define KV_TILE_B   (64 * FSTR * 2)           // 17408
#define KV_STAGE_B  (2 * KV_TILE_B)           // 34816
#define FLASH_SMEM  (Q_BYTES + 2 * KV_STAGE_B)  // 104448

__device__ __forceinline__ void load_kv_tile(
    uint32_t kbase, uint32_t vbase, size_t rowbase, int j0, int qcol, int tid)
{
    #pragma unroll
    for (int i = 0; i < 4; i++) {
        int idx = tid + i * 256;          // 0..1023
        int r = idx >> 4;                 // 0..63
        int c = idx & 15;
        cp_async16(kbase + (r * FSTR + c * 8) * 2,
                   &g_qkv[(rowbase + j0 + r) * (size_t)QKV_N + qcol + D_ + c * 8]);
    }
    #pragma unroll
    for (int i = 0; i < 4; i++) {
        int idx = tid + i * 256;
        int r = idx >> 4;
        int c = idx & 15;
        cp_async16(vbase + (r * FSTR + c * 8) * 2,
                   &g_qkv[(rowbase + j0 + r) * (size_t)QKV_N + qcol + 2 * D_ + c * 8]);
    }
}

__global__ __launch_bounds__(256, 2) void flash_mma_kernel()
{
    extern __shared__ char smc[];
    const int qi  = (gridDim.x - 1) - blockIdx.x;   // big q-blocks first
    const int q0  = qi * FBQ;
    const int h   = blockIdx.y;
    const int b   = blockIdx.z;
    const int tid = threadIdx.x;
    const int lane = tid & 31;
    const int wid  = tid >> 5;
    const int qr = lane >> 2;
    const int qc = lane & 3;

    const size_t rowbase = (size_t)b * T_;
    const int qcol = h * DH;
    const float SCALE = 0.08838834764831845f;   // 1/sqrt(128)

    const uint32_t base = smem_u32(smc);
    const uint32_t Qs = base;
    const int ntile = 2 * qi + 2;

    #pragma unroll
    for (int i = 0; i < 8; i++) {
        int idx = tid + i * 256;          // 0..2047
        int r = idx >> 4;
        int c = idx & 15;
        cp_async16(Qs + (r * FSTR + c * 8) * 2,
                   &g_qkv[(rowbase + q0 + r) * (size_t)QKV_N + qcol + c * 8]);
    }
    {
        uint32_t s0 = base + Q_BYTES;
        load_kv_tile(s0, s0 + KV_TILE_B, rowbase, 0, qcol, tid);
        cp_commit();
        if (ntile > 1) {
            uint32_t s1 = base + Q_BYTES + KV_STAGE_B;
            load_kv_tile(s1, s1 + KV_TILE_B, rowbase, 64, qcol, tid);
        }
        cp_commit();
    }

    float oacc[16][4];
    #pragma unroll
    for (int n = 0; n < 16; n++)
        #pragma unroll
        for (int i = 0; i < 4; i++) oacc[n][i] = 0.0f;
    float mrow0 = -3.0e38f, mrow1 = -3.0e38f;
    float lrow0 = 0.0f, lrow1 = 0.0f;

    const int mloc = wid * 16;
    const int g = lane >> 3;
    const int lq_off = (mloc + (lane & 15)) * FSTR + (lane >> 4) * 8;
    const int lk_off = (((g & 2) ? 8 : 0) + (lane & 7)) * FSTR + (g & 1) * 8;
    const int lv_off = ((g & 1) * 8 + (lane & 7)) * FSTR + ((g & 2) ? 8 : 0);

    for (int t = 0; t < ntile; t++) {
        cp_wait<1>();
        __syncthreads();

        const uint32_t Ks = base + Q_BYTES + (t & 1) * KV_STAGE_B;
        const uint32_t Vs = Ks + KV_TILE_B;

        // ---- S = Q @ K^T ----
        float sacc[8][4];
        #pragma unroll
        for (int n = 0; n < 8; n++)
            #pragma unroll
            for (int i = 0; i < 4; i++) sacc[n][i] = 0.0f;

        #pragma unroll
        for (int k16 = 0; k16 < 8; k16++) {
            const int ko = k16 * 16;
            uint32_t qa0, qa1, qa2, qa3;
            ldm_x4(qa0, qa1, qa2, qa3, Qs + (lq_off + ko) * 2);
            #pragma unroll
            for (int ntp = 0; ntp < 4; ntp++) {
                uint32_t b0, b1, b2, b3;
                ldm_x4(b0, b1, b2, b3, Ks + (lk_off + ntp * 16 * FSTR + ko) * 2);
                mma_f16(sacc[2 * ntp    ], qa0, qa1, qa2, qa3, b0, b1);
                mma_f16(sacc[2 * ntp + 1], qa0, qa1, qa2, qa3, b2, b3);
            }
        }

        // ---- causal mask (only last 2 tiles touch the diagonal) ----
        if (t >= ntile - 2) {
            const int j0 = t * 64;
            const int rg0 = q0 + mloc + qr;
            const int rg1 = rg0 + 8;
            #pragma unroll
            for (int nt = 0; nt < 8; nt++) {
                const int cg = j0 + nt * 8 + 2 * qc;
                if (cg     > rg0) sacc[nt][0] = -1.0e30f;
                if (cg + 1 > rg0) sacc[nt][1] = -1.0e30f;
                if (cg     > rg1) sacc[nt][2] = -1.0e30f;
                if (cg + 1 > rg1) sacc[nt][3] = -1.0e30f;
            }
        }

        // ---- online softmax (per-row, quad lanes) ----
        float mx0 = -3.0e38f, mx1 = -3.0e38f;
        #pragma unroll
        for (int nt = 0; nt < 8; nt++) {
            mx0 = fmaxf(mx0, fmaxf(sacc[nt][0], sacc[nt][1]));
            mx1 = fmaxf(mx1, fmaxf(sacc[nt][2], sacc[nt][3]));
        }
        mx0 = fmaxf(mx0, __shfl_xor_sync(0xFFFFFFFFu, mx0, 1));
        mx0 = fmaxf(mx0, __shfl_xor_sync(0xFFFFFFFFu, mx0, 2));
        mx1 = fmaxf(mx1, __shfl_xor_sync(0xFFFFFFFFu, mx1, 1));
        mx1 = fmaxf(mx1, __shfl_xor_sync(0xFFFFFFFFu, mx1, 2));
        const float mn0 = fmaxf(mrow0, mx0);
        const float mn1 = fmaxf(mrow1, mx1);
        const float al0 = __expf((mrow0 - mn0) * SCALE);
        const float al1 = __expf((mrow1 - mn1) * SCALE);
        mrow0 = mn0; mrow1 = mn1;

        float ps0 = 0.0f, ps1 = 0.0f;
        #pragma unroll
        for (int nt = 0; nt < 8; nt++) {
            sacc[nt][0] = __expf((sacc[nt][0] - mn0) * SCALE);
            sacc[nt][1] = __expf((sacc[nt][1] - mn0) * SCALE);
            sacc[nt][2] = __expf((sacc[nt][2] - mn1) * SCALE);
            sacc[nt][3] = __expf((sacc[nt][3] - mn1) * SCALE);
            ps0 += sacc[nt][0] + sacc[nt][1];
            ps1 += sacc[nt][2] + sacc[nt][3];
        }
        ps0 += __shfl_xor_sync(0xFFFFFFFFu, ps0, 1);
        ps0 += __shfl_xor_sync(0xFFFFFFFFu, ps0, 2);
        ps1 += __shfl_xor_sync(0xFFFFFFFFu, ps1, 1);
        ps1 += __shfl_xor_sync(0xFFFFFFFFu, ps1, 2);
        lrow0 = lrow0 * al0 + ps0;
        lrow1 = lrow1 * al1 + ps1;

        #pragma unroll
        for (int n = 0; n < 16; n++) {
            oacc[n][0] *= al0; oacc[n][1] *= al0;
            oacc[n][2] *= al1; oacc[n][3] *= al1;
        }

        // ---- P fragments: direct pack (C-layout == A-layout in fp16) ----
        uint32_t pA[4][4];
        #pragma unroll
        for (int j = 0; j < 4; j++) {
            pA[j][0] = pack_h2(sacc[2 * j][0],     sacc[2 * j][1]);
            pA[j][1] = pack_h2(sacc[2 * j][2],     sacc[2 * j][3]);
            pA[j][2] = pack_h2(sacc[2 * j + 1][0], sacc[2 * j + 1][1]);
            pA[j][3] = pack_h2(sacc[2 * j + 1][2], sacc[2 * j + 1][3]);
        }

        // ---- O += P @ V  (V^T fragments via ldmatrix.trans) ----
        #pragma unroll
        for (int j = 0; j < 4; j++) {
            #pragma unroll
            for (int ntp = 0; ntp < 8; ntp++) {
                uint32_t b0, b1, b2, b3;
                ldm_x4_t(b0, b1, b2, b3,
                         Vs + (lv_off + j * 16 * FSTR + ntp * 16) * 2);
                mma_f16(oacc[2 * ntp    ], pA[j][0], pA[j][1], pA[j][2], pA[j][3], b0, b1);
                mma_f16(oacc[2 * ntp + 1], pA[j][0], pA[j][1], pA[j][2], pA[j][3], b2, b3);
            }
        }

        __syncthreads();
        if (t + 2 < ntile) {
            uint32_t sb = base + Q_BYTES + (t & 1) * KV_STAGE_B;
            load_kv_tile(sb, sb + KV_TILE_B, rowbase, (t + 2) * 64, qcol, tid);
        }
        cp_commit();
    }

    // ---- epilogue: normalize, fp16 store (feeds out-proj GEMM) ----
    const float li0 = 1.0f / lrow0;
    const float li1 = 1.0f / lrow1;
    const int r0 = q0 + mloc + qr;
    const int r1 = r0 + 8;
    #pragma unroll
    for (int ntd = 0; ntd < 16; ntd++) {
        const int col = qcol + ntd * 8 + 2 * qc;
        *(uint32_t*)&g_o[(rowbase + r0) * (size_t)D_ + col] =
            pack_h2(oacc[ntd][0] * li0, oacc[ntd][1] * li0);
        *(uint32_t*)&g_o[(rowbase + r1) * (size_t)D_ + col] =
            pack_h2(oacc[ntd][2] * li1, oacc[ntd][3] * li1);
    }
}

// ---------------------------------------------------------------------------
// Launch
// ---------------------------------------------------------------------------
extern "C" void kernel_launch(void* const* d_in, const int* in_sizes, int n_in,
                              void* d_out, int out_size)
{
    (void)in_sizes; (void)n_in; (void)out_size;
    const float* x    = (const float*)d_in[0];
    const float* Wqkv = (const float*)d_in[1];
    const float* bqkv = (const float*)d_in[2];
    const float* Wout = (const float*)d_in[3];
    const float* bout = (const float*)d_in[4];
    float* out = (float*)d_out;

    static __half *qkv_ptr = nullptr, *o_ptr = nullptr, *xh_ptr = nullptr;
    static __half *wqkvT_ptr = nullptr, *woutT_ptr = nullptr;
    static bool init_done = false;
    if (!init_done) {
        // First call is the (uncaptured) correctness run; these immediate host
        // APIs never land inside graph capture.
        cudaFuncSetAttribute(flash_mma_kernel,
                             cudaFuncAttributeMaxDynamicSharedMemorySize,
                             FLASH_SMEM);
        cudaFuncSetAttribute(mma_gemm_bias<true>,
                             cudaFuncAttributeMaxDynamicSharedMemorySize,
                             GEMM_SMEM);
        cudaFuncSetAttribute(mma_gemm_bias<false>,
                             cudaFuncAttributeMaxDynamicSharedMemorySize,
                             GEMM_SMEM);
        void* p;
        cudaGetSymbolAddress(&p, g_qkv);   qkv_ptr   = (__half*)p;
        cudaGetSymbolAddress(&p, g_o);     o_ptr     = (__half*)p;
        cudaGetSymbolAddress(&p, g_xh);    xh_ptr    = (__half*)p;
        cudaGetSymbolAddress(&p, g_WqkvT); wqkvT_ptr = (__half*)p;
        cudaGetSymbolAddress(&p, g_WoutT); woutT_ptr = (__half*)p;
        init_done = true;
    }

    // 0) pre-pass: x -> fp16; weights -> transposed fp16 [N,K]
    f2h_kernel<<<(MROWS * (size_t)D_ / 8) / 256, 256>>>(x, xh_ptr);
    transpose_kernel<<<dim3(QKV_N / 32, D_ / 32), dim3(32, 8)>>>(Wqkv, wqkvT_ptr, D_, QKV_N);
    transpose_kernel<<<dim3(D_ / 32, D_ / 32), dim3(32, 8)>>>(Wout, woutT_ptr, D_, D_);

    // 1) QKV = x @ Wqkv + bqkv (fp16 mma, fp32 accum; fp16 output)
    mma_gemm_bias<true><<<dim3(QKV_N / GBN, MROWS / GBM), 256, GEMM_SMEM>>>(
        xh_ptr, wqkvT_ptr, bqkv, qkv_ptr, MROWS, QKV_N, D_);

    // 2) causal flash attention (fp16 tensor cores) -> g_o (fp16)
    flash_mma_kernel<<<dim3(T_ / FBQ, H_, B_), 256, FLASH_SMEM>>>();

    // 3) out = g_o @ Wout + bout (fp16 mma, fp32 output)
    mma_gemm_bias<false><<<dim3(D_ / GBN, MROWS / GBM), 256, GEMM_SMEM>>>(
        o_ptr, woutT_ptr, bout, out, MROWS, D_, D_);
}

// round 13
// speedup vs baseline: 2.5287x; 1.0139x over previous
#include <cuda_runtime.h>
#include <cuda_fp16.h>
#include <math.h>
#include <stdint.h>

#define B_  2
#define T_  2048
#define D_  2048
#define H_  16
#define DH  128
#define MROWS (B_*T_)          // 4096
#define QKV_N (3*D_)           // 6144

// Scratch (device globals — no allocation allowed); all fp16 operands
__device__ __half g_qkv[(size_t)MROWS * QKV_N];    // 50 MB
__device__ __half g_o[(size_t)MROWS * D_];         // 16 MB
__device__ __half g_xh[(size_t)MROWS * D_];        // 16 MB
__device__ __half g_WqkvT[(size_t)QKV_N * D_];     // 25 MB ([N,K] K-contig)
__device__ __half g_WoutT[(size_t)D_ * D_];        // 8 MB

// ---------------------------------------------------------------------------
// Helpers
// ---------------------------------------------------------------------------
__device__ __forceinline__ void cp_async16(uint32_t s, const void* g) {
    asm volatile("cp.async.cg.shared.global [%0], [%1], 16;" :: "r"(s), "l"(g));
}
__device__ __forceinline__ void cp_commit() {
    asm volatile("cp.async.commit_group;" ::: "memory");
}
template <int N> __device__ __forceinline__ void cp_wait() {
    asm volatile("cp.async.wait_group %0;" :: "n"(N) : "memory");
}
__device__ __forceinline__ uint32_t smem_u32(const void* p) {
    uint32_t a;
    asm("{ .reg .u64 t; cvta.to.shared.u64 t, %1; cvt.u32.u64 %0, t; }"
        : "=r"(a) : "l"(p));
    return a;
}
__device__ __forceinline__ void ldm_x4(uint32_t& r0, uint32_t& r1,
                                       uint32_t& r2, uint32_t& r3, uint32_t a) {
    asm volatile("ldmatrix.sync.aligned.m8n8.x4.shared.b16 {%0,%1,%2,%3}, [%4];"
                 : "=r"(r0), "=r"(r1), "=r"(r2), "=r"(r3) : "r"(a));
}
__device__ __forceinline__ void ldm_x4_t(uint32_t& r0, uint32_t& r1,
                                         uint32_t& r2, uint32_t& r3, uint32_t a) {
    asm volatile("ldmatrix.sync.aligned.m8n8.x4.trans.shared.b16 {%0,%1,%2,%3}, [%4];"
                 : "=r"(r0), "=r"(r1), "=r"(r2), "=r"(r3) : "r"(a));
}
__device__ __forceinline__ void mma_f16(float c[4],
    uint32_t a0, uint32_t a1, uint32_t a2, uint32_t a3,
    uint32_t b0, uint32_t b1)
{
    asm volatile(
        "mma.sync.aligned.m16n8k16.row.col.f32.f16.f16.f32 "
        "{%0,%1,%2,%3}, {%4,%5,%6,%7}, {%8,%9}, {%0,%1,%2,%3};"
        : "+f"(c[0]), "+f"(c[1]), "+f"(c[2]), "+f"(c[3])
        : "r"(a0), "r"(a1), "r"(a2), "r"(a3), "r"(b0), "r"(b1));
}
__device__ __forceinline__ uint32_t pack_h2(float x, float y) {
    __half2 h = __floats2half2_rn(x, y);
    return *(uint32_t*)&h;
}

// ---------------------------------------------------------------------------
// x pre-pass: fp32 -> fp16. Each thread converts 8 floats.
// ---------------------------------------------------------------------------
__global__ __launch_bounds__(256) void f2h_kernel(
    const float* __restrict__ in, __half* __restrict__ out)
{
    const size_t i = (size_t)blockIdx.x * 256 + threadIdx.x;
    float4 a = ((const float4*)in)[2 * i];
    float4 b = ((const float4*)in)[2 * i + 1];
    uint4 u;
    u.x = pack_h2(a.x, a.y); u.y = pack_h2(a.z, a.w);
    u.z = pack_h2(b.x, b.y); u.w = pack_h2(b.z, b.w);
    ((uint4*)out)[i] = u;
}

// ---------------------------------------------------------------------------
// Weight transpose + fp16: At[N,K] = h(A[K,N]^T)
// ---------------------------------------------------------------------------
__global__ __launch_bounds__(256) void transpose_kernel(
    const float* __restrict__ A, __half* __restrict__ At, int R, int C)
{
    __shared__ float tile[32][33];
    const int c = blockIdx.x * 32 + threadIdx.x;
    const int r = blockIdx.y * 32 + threadIdx.y;
    #pragma unroll
    for (int i = 0; i < 32; i += 8)
        tile[threadIdx.y + i][threadIdx.x] = A[(size_t)(r + i) * C + c];
    __syncthreads();
    const int tc = blockIdx.y * 32 + threadIdx.x;
    const int tr = blockIdx.x * 32 + threadIdx.y;
    #pragma unroll
    for (int i = 0; i < 32; i += 8)
        At[(size_t)(tr + i) * R + tc] = __float2half_rn(tile[threadIdx.x][threadIdx.y + i]);
}

// ---------------------------------------------------------------------------
// fp16 mma.sync GEMM + bias (unchanged from R12 win):
// CTA 128x256, 256 threads (8 warps, 2m x 4n), warp tile 64x64.
// 4-stage depth-3 cp.async pipeline, fragment double-buffering, rotated
// stage boundary. 1 CTA/SM (254 regs).
// ---------------------------------------------------------------------------
#define GBM 128
#define GBN 256
#define GBK 64
#define STRH 72
#define A_TILE_H (128 * STRH)                 // 9216 halves
#define B_TILE_H (256 * STRH)                 // 18432 halves
#define STAGE_B  ((A_TILE_H + B_TILE_H) * 2)  // 55296 bytes
#define GSTAGES  4
#define GEMM_SMEM (GSTAGES * STAGE_B)         // 221184

__device__ __forceinline__ void gemm_load_stage(
    const __half* __restrict__ A, const __half* __restrict__ BT, int K,
    uint32_t sa, uint32_t sb, int brow, int bcol, int k0, int tid)
{
    #pragma unroll
    for (int i = 0; i < 4; i++) {           // A: 128 rows x 8 chunks
        int idx = tid + i * 256;            // 0..1023
        int row = idx >> 3;
        int c = idx & 7;
        cp_async16(sa + (row * STRH + c * 8) * 2,
                   &A[(size_t)(brow + row) * K + k0 + c * 8]);
    }
    #pragma unroll
    for (int i = 0; i < 8; i++) {           // B^T: 256 n-rows x 8 chunks
        int idx = tid + i * 256;            // 0..2047
        int row = idx >> 3;
        int c = idx & 7;
        cp_async16(sb + (row * STRH + c * 8) * 2,
                   &BT[(size_t)(bcol + row) * K + k0 + c * 8]);
    }
}

// load one k16 fragment set (8 ldmatrix.x4: 4 A blocks + 4 B blocks)
#define LOAD_FRAGS(FA, FB, sa, sb, ko)                                        \
    do {                                                                      \
        ldm_x4((FA)[0],  (FA)[1],  (FA)[2],  (FA)[3],                         \
               (sa) + (la_off + (ko)) * 2);                                   \
        ldm_x4((FA)[4],  (FA)[5],  (FA)[6],  (FA)[7],                         \
               (sa) + (la_off + 16 * STRH + (ko)) * 2);                       \
        ldm_x4((FA)[8],  (FA)[9],  (FA)[10], (FA)[11],                        \
               (sa) + (la_off + 32 * STRH + (ko)) * 2);                       \
        ldm_x4((FA)[12], (FA)[13], (FA)[14], (FA)[15],                        \
               (sa) + (la_off + 48 * STRH + (ko)) * 2);                       \
        ldm_x4((FB)[0],  (FB)[1],  (FB)[2],  (FB)[3],                         \
               (sb) + (lb_off + (ko)) * 2);                                   \
        ldm_x4((FB)[4],  (FB)[5],  (FB)[6],  (FB)[7],                         \
               (sb) + (lb_off + 16 * STRH + (ko)) * 2);                       \
        ldm_x4((FB)[8],  (FB)[9],  (FB)[10], (FB)[11],                        \
               (sb) + (lb_off + 32 * STRH + (ko)) * 2);                       \
        ldm_x4((FB)[12], (FB)[13], (FB)[14], (FB)[15],                        \
               (sb) + (lb_off + 48 * STRH + (ko)) * 2);                       \
    } while (0)

#define MMA_BLOCK(cur)                                                        \
    do {                                                                      \
        _Pragma("unroll")                                                     \
        for (int j = 0; j < 4; j++) {                                         \
            _Pragma("unroll")                                                 \
            for (int i = 0; i < 4; i++) {                                     \
                mma_f16(acc[i][2 * j],                                        \
                        fa[cur][4 * i], fa[cur][4 * i + 1],                   \
                        fa[cur][4 * i + 2], fa[cur][4 * i + 3],               \
                        fb[cur][4 * j], fb[cur][4 * j + 1]);                  \
                mma_f16(acc[i][2 * j + 1],                                    \
                        fa[cur][4 * i], fa[cur][4 * i + 1],                   \
                        fa[cur][4 * i + 2], fa[cur][4 * i + 3],               \
                        fb[cur][4 * j + 2], fb[cur][4 * j + 3]);              \
            }                                                                 \
        }                                                                     \
    } while (0)

template <bool OUT_HALF>
__global__ __launch_bounds__(256, 1) void mma_gemm_bias(
    const __half* __restrict__ A, const __half* __restrict__ BT,
    const float* __restrict__ bias, void* __restrict__ Cv,
    int M, int N, int K)
{
    extern __shared__ char sm[];
    const int tid  = threadIdx.x;
    const int wid  = tid >> 5;
    const int lane = tid & 31;
    const int brow = blockIdx.y * GBM;
    const int bcol = blockIdx.x * GBN;
    const int warp_m = wid & 1;            // rows warp_m*64
    const int warp_n = wid >> 1;           // cols warp_n*64
    const int qr = lane >> 2;
    const int qc = lane & 3;

    const uint32_t base = smem_u32(sm);

    float acc[4][8][4];
    #pragma unroll
    for (int mt = 0; mt < 4; mt++)
        #pragma unroll
        for (int nt = 0; nt < 8; nt++)
            #pragma unroll
            for (int i = 0; i < 4; i++)
                acc[mt][nt][i] = 0.0f;

    const int KT = K / GBK;   // 32

    #pragma unroll
    for (int s = 0; s < 3; s++) {
        const uint32_t sa = base + s * STAGE_B;
        gemm_load_stage(A, BT, K, sa, sa + A_TILE_H * 2, brow, bcol,
                        s * GBK, tid);
        cp_commit();
    }

    const int la_off = (warp_m * 64 + (lane & 15)) * STRH + (lane >> 4) * 8;
    const int g = lane >> 3;
    const int lb_off = (warp_n * 64 + ((g & 2) ? 8 : 0) + (lane & 7)) * STRH
                     + (g & 1) * 8;

    uint32_t fa[2][16], fb[2][16];

    cp_wait<2>();
    __syncthreads();
    LOAD_FRAGS(fa[0], fb[0], base, base + A_TILE_H * 2, 0);

    int st = 0;
    for (int kt = 0; kt < KT; kt++) {
        const int lkt = kt + 3;
        if (lkt < KT) {
            int fst = st + 3; if (fst >= GSTAGES) fst -= GSTAGES;
            const uint32_t pa = base + fst * STAGE_B;
            gemm_load_stage(A, BT, K, pa, pa + A_TILE_H * 2, brow, bcol,
                            lkt * GBK, tid);
        }
        cp_commit();

        const uint32_t sa = base + st * STAGE_B;
        const uint32_t sb = sa + A_TILE_H * 2;

        #pragma unroll
        for (int k16 = 0; k16 < 3; k16++) {
            const int cur = k16 & 1, nxt = cur ^ 1;
            LOAD_FRAGS(fa[nxt], fb[nxt], sa, sb, (k16 + 1) * 16);
            MMA_BLOCK(cur);
        }

        cp_wait<2>();
        __syncthreads();
        int nst = st + 1; if (nst >= GSTAGES) nst -= GSTAGES;
        if (kt + 1 < KT) {
            const uint32_t na = base + nst * STAGE_B;
            LOAD_FRAGS(fa[0], fb[0], na, na + A_TILE_H * 2, 0);
        }
        MMA_BLOCK(1);
        st = nst;
    }

    #pragma unroll
    for (int mt = 0; mt < 4; mt++) {
        const int row0 = brow + warp_m * 64 + mt * 16 + qr;
        #pragma unroll
        for (int nt = 0; nt < 8; nt++) {
            const int col = bcol + warp_n * 64 + nt * 8 + 2 * qc;
            const float2 bb = *(const float2*)&bias[col];
            const float vx = acc[mt][nt][0] + bb.x;
            const float vy = acc[mt][nt][1] + bb.y;
            const float wx = acc[mt][nt][2] + bb.x;
            const float wy = acc[mt][nt][3] + bb.y;
            if (OUT_HALF) {
                __half* C = (__half*)Cv;
                *(uint32_t*)&C[(size_t)row0 * N + col]       = pack_h2(vx, vy);
                *(uint32_t*)&C[(size_t)(row0 + 8) * N + col] = pack_h2(wx, wy);
            } else {
                float* C = (float*)Cv;
                float2 o0; o0.x = vx; o0.y = vy;
                float2 o1; o1.x = wx; o1.y = wy;
                *(float2*)&C[(size_t)row0 * N + col]       = o0;
                *(float2*)&C[(size_t)(row0 + 8) * N + col] = o1;
            }
        }
    }
}

// ---------------------------------------------------------------------------
// fp16 tensor-core flash attention (causal, register softmax, ldmatrix).
// CTA: 128 q-rows, 256 threads (8 warps x 16 rows). KV tiles of 64,
// double-buffered cp.async. 2 CTAs/SM. Row stride 136 halves.
// R13: S-loop and PV-loop fragments are software-pipelined (K/V fragments
// one step ahead, Q fragments one k16 ahead) — zero exposed LDSM latency.
// ---------------------------------------------------------------------------
#define FBQ   128
#define FSTR  136
#define Q_BYTES     (128 * FSTR * 2)          // 34816
#define KV_TILE_B   (64 * FSTR * 2)           // 17408
#define KV_STAGE_B  (2 * KV_TILE_B)           // 34816
#define FLASH_SMEM  (Q_BYTES + 2 * KV_STAGE_B)  // 104448

__device__ __forceinline__ void load_kv_tile(
    uint32_t kbase, uint32_t vbase, size_t rowbase, int j0, int qcol, int tid)
{
    #pragma unroll
    for (int i = 0; i < 4; i++) {
        int idx = tid + i * 256;          // 0..1023
        int r = idx >> 4;                 // 0..63
        int c = idx & 15;
        cp_async16(kbase + (r * FSTR + c * 8) * 2,
                   &g_qkv[(rowbase + j0 + r) * (size_t)QKV_N + qcol + D_ + c * 8]);
    }
    #pragma unroll
    for (int i = 0; i < 4; i++) {
        int idx = tid + i * 256;
        int r = idx >> 4;
        int c = idx & 15;
        cp_async16(vbase + (r * FSTR + c * 8) * 2,
                   &g_qkv[(rowbase + j0 + r) * (size_t)QKV_N + qcol + 2 * D_ + c * 8]);
    }
}

__global__ __launch_bounds__(256, 2) void flash_mma_kernel()
{
    extern __shared__ char smc[];
    const int qi  = (gridDim.x - 1) - blockIdx.x;   // big q-blocks first
    const int q0  = qi * FBQ;
    const int h   = blockIdx.y;
    const int b   = blockIdx.z;
    const int tid = threadIdx.x;
    const int lane = tid & 31;
    const int wid  = tid >> 5;
    const int qr = lane >> 2;
    const int qc = lane & 3;

    const size_t rowbase = (size_t)b * T_;
    const int qcol = h * DH;
    const float SCALE = 0.08838834764831845f;   // 1/sqrt(128)

    const uint32_t base = smem_u32(smc);
    const uint32_t Qs = base;
    const int ntile = 2 * qi + 2;

    #pragma unroll
    for (int i = 0; i < 8; i++) {
        int idx = tid + i * 256;          // 0..2047
        int r = idx >> 4;
        int c = idx & 15;
        cp_async16(Qs + (r * FSTR + c * 8) * 2,
                   &g_qkv[(rowbase + q0 + r) * (size_t)QKV_N + qcol + c * 8]);
    }
    {
        uint32_t s0 = base + Q_BYTES;
        load_kv_tile(s0, s0 + KV_TILE_B, rowbase, 0, qcol, tid);
        cp_commit();
        if (ntile > 1) {
            uint32_t s1 = base + Q_BYTES + KV_STAGE_B;
            load_kv_tile(s1, s1 + KV_TILE_B, rowbase, 64, qcol, tid);
        }
        cp_commit();
    }

    float oacc[16][4];
    #pragma unroll
    for (int n = 0; n < 16; n++)
        #pragma unroll
        for (int i = 0; i < 4; i++) oacc[n][i] = 0.0f;
    float mrow0 = -3.0e38f, mrow1 = -3.0e38f;
    float lrow0 = 0.0f, lrow1 = 0.0f;

    const int mloc = wid * 16;
    const int g = lane >> 3;
    const int lq_off = (mloc + (lane & 15)) * FSTR + (lane >> 4) * 8;
    const int lk_off = (((g & 2) ? 8 : 0) + (lane & 7)) * FSTR + (g & 1) * 8;
    const int lv_off = ((g & 1) * 8 + (lane & 7)) * FSTR + ((g & 2) ? 8 : 0);

    for (int t = 0; t < ntile; t++) {
        cp_wait<1>();
        __syncthreads();

        const uint32_t Ks = base + Q_BYTES + (t & 1) * KV_STAGE_B;
        const uint32_t Vs = Ks + KV_TILE_B;

        // ---- S = Q @ K^T (software-pipelined fragments) ----
        float sacc[8][4];
        #pragma unroll
        for (int n = 0; n < 8; n++)
            #pragma unroll
            for (int i = 0; i < 4; i++) sacc[n][i] = 0.0f;

        uint32_t qf[2][4], kf[2][4];
        ldm_x4(qf[0][0], qf[0][1], qf[0][2], qf[0][3], Qs + lq_off * 2);
        ldm_x4(kf[0][0], kf[0][1], kf[0][2], kf[0][3], Ks + lk_off * 2);
        #pragma unroll
        for (int k16 = 0; k16 < 8; k16++) {
            const int qb = k16 & 1;
            #pragma unroll
            for (int ntp = 0; ntp < 4; ntp++) {
                const int s = k16 * 4 + ntp;
                const int cur = s & 1, nxt = cur ^ 1;
                if (s < 31) {
                    const int sn = s + 1;
                    const int k16n = sn >> 2, ntpn = sn & 3;
                    ldm_x4(kf[nxt][0], kf[nxt][1], kf[nxt][2], kf[nxt][3],
                           Ks + (lk_off + ntpn * 16 * FSTR + k16n * 16) * 2);
                }
                if (ntp == 0 && k16 < 7) {
                    ldm_x4(qf[qb ^ 1][0], qf[qb ^ 1][1], qf[qb ^ 1][2],
                           qf[qb ^ 1][3], Qs + (lq_off + (k16 + 1) * 16) * 2);
                }
                mma_f16(sacc[2 * ntp    ], qf[qb][0], qf[qb][1], qf[qb][2],
                        qf[qb][3], kf[cur][0], kf[cur][1]);
                mma_f16(sacc[2 * ntp + 1], qf[qb][0], qf[qb][1], qf[qb][2],
                        qf[qb][3], kf[cur][2], kf[cur][3]);
            }
        }

        // ---- causal mask (only last 2 tiles touch the diagonal) ----
        if (t >= ntile - 2) {
            const int j0 = t * 64;
            const int rg0 = q0 + mloc + qr;
            const int rg1 = rg0 + 8;
            #pragma unroll
            for (int nt = 0; nt < 8; nt++) {
                const int cg = j0 + nt * 8 + 2 * qc;
                if (cg     > rg0) sacc[nt][0] = -1.0e30f;
                if (cg + 1 > rg0) sacc[nt][1] = -1.0e30f;
                if (cg     > rg1) sacc[nt][2] = -1.0e30f;
                if (cg + 1 > rg1) sacc[nt][3] = -1.0e30f;
            }
        }

        // ---- online softmax (per-row, quad lanes) ----
        float mx0 = -3.0e38f, mx1 = -3.0e38f;
        #pragma unroll
        for (int nt = 0; nt < 8; nt++) {
            mx0 = fmaxf(mx0, fmaxf(sacc[nt][0], sacc[nt][1]));
            mx1 = fmaxf(mx1, fmaxf(sacc[nt][2], sacc[nt][3]));
        }
        mx0 = fmaxf(mx0, __shfl_xor_sync(0xFFFFFFFFu, mx0, 1));
        mx0 = fmaxf(mx0, __shfl_xor_sync(0xFFFFFFFFu, mx0, 2));
        mx1 = fmaxf(mx1, __shfl_xor_sync(0xFFFFFFFFu, mx1, 1));
        mx1 = fmaxf(mx1, __shfl_xor_sync(0xFFFFFFFFu, mx1, 2));
        const float mn0 = fmaxf(mrow0, mx0);
        const float mn1 = fmaxf(mrow1, mx1);
        const float al0 = __expf((mrow0 - mn0) * SCALE);
        const float al1 = __expf((mrow1 - mn1) * SCALE);
        mrow0 = mn0; mrow1 = mn1;

        float ps0 = 0.0f, ps1 = 0.0f;
        #pragma unroll
        for (int nt = 0; nt < 8; nt++) {
            sacc[nt][0] = __expf((sacc[nt][0] - mn0) * SCALE);
            sacc[nt][1] = __expf((sacc[nt][1] - mn0) * SCALE);
            sacc[nt][2] = __expf((sacc[nt][2] - mn1) * SCALE);
            sacc[nt][3] = __expf((sacc[nt][3] - mn1) * SCALE);
            ps0 += sacc[nt][0] + sacc[nt][1];
            ps1 += sacc[nt][2] + sacc[nt][3];
        }
        ps0 += __shfl_xor_sync(0xFFFFFFFFu, ps0, 1);
        ps0 += __shfl_xor_sync(0xFFFFFFFFu, ps0, 2);
        ps1 += __shfl_xor_sync(0xFFFFFFFFu, ps1, 1);
        ps1 += __shfl_xor_sync(0xFFFFFFFFu, ps1, 2);
        lrow0 = lrow0 * al0 + ps0;
        lrow1 = lrow1 * al1 + ps1;

        #pragma unroll
        for (int n = 0; n < 16; n++) {
            oacc[n][0] *= al0; oacc[n][1] *= al0;
            oacc[n][2] *= al1; oacc[n][3] *= al1;
        }

        // ---- P fragments: direct pack (C-layout == A-layout in fp16) ----
        uint32_t pA[4][4];
        #pragma unroll
        for (int j = 0; j < 4; j++) {
            pA[j][0] = pack_h2(sacc[2 * j][0],     sacc[2 * j][1]);
            pA[j][1] = pack_h2(sacc[2 * j][2],     sacc[2 * j][3]);
            pA[j][2] = pack_h2(sacc[2 * j + 1][0], sacc[2 * j + 1][1]);
            pA[j][3] = pack_h2(sacc[2 * j + 1][2], sacc[2 * j + 1][3]);
        }

        // ---- O += P @ V (software-pipelined V fragments) ----
        uint32_t vf[2][4];
        ldm_x4_t(vf[0][0], vf[0][1], vf[0][2], vf[0][3], Vs + lv_off * 2);
        #pragma unroll
        for (int j = 0; j < 4; j++) {
            #pragma unroll
            for (int ntp = 0; ntp < 8; ntp++) {
                const int s = j * 8 + ntp;
                const int cur = s & 1, nxt = cur ^ 1;
                if (s < 31) {
                    const int sn = s + 1;
                    const int jn = sn >> 3, ntpn = sn & 7;
                    ldm_x4_t(vf[nxt][0], vf[nxt][1], vf[nxt][2], vf[nxt][3],
                             Vs + (lv_off + jn * 16 * FSTR + ntpn * 16) * 2);
                }
                mma_f16(oacc[2 * ntp    ], pA[j][0], pA[j][1], pA[j][2],
                        pA[j][3], vf[cur][0], vf[cur][1]);
                mma_f16(oacc[2 * ntp + 1], pA[j][0], pA[j][1], pA[j][2],
                        pA[j][3], vf[cur][2], vf[cur][3]);
            }
        }

        __syncthreads();
        if (t + 2 < ntile) {
            uint32_t sb = base + Q_BYTES + (t & 1) * KV_STAGE_B;
            load_kv_tile(sb, sb + KV_TILE_B, rowbase, (t + 2) * 64, qcol, tid);
        }
        cp_commit();
    }

    // ---- epilogue: normalize, fp16 store (feeds out-proj GEMM) ----
    const float li0 = 1.0f / lrow0;
    const float li1 = 1.0f / lrow1;
    const int r0 = q0 + mloc + qr;
    const int r1 = r0 + 8;
    #pragma unroll
    for (int ntd = 0; ntd < 16; ntd++) {
        const int col = qcol + ntd * 8 + 2 * qc;
        *(uint32_t*)&g_o[(rowbase + r0) * (size_t)D_ + col] =
            pack_h2(oacc[ntd][0] * li0, oacc[ntd][1] * li0);
        *(uint32_t*)&g_o[(rowbase + r1) * (size_t)D_ + col] =
            pack_h2(oacc[ntd][2] * li1, oacc[ntd][3] * li1);
    }
}

// ---------------------------------------------------------------------------
// Launch
// ---------------------------------------------------------------------------
extern "C" void kernel_launch(void* const* d_in, const int* in_sizes, int n_in,
                              void* d_out, int out_size)
{
    (void)in_sizes; (void)n_in; (void)out_size;
    const float* x    = (const float*)d_in[0];
    const float* Wqkv = (const float*)d_in[1];
    const float* bqkv = (const float*)d_in[2];
    const float* Wout = (const float*)d_in[3];
    const float* bout = (const float*)d_in[4];
    float* out = (float*)d_out;

    static __half *qkv_ptr = nullptr, *o_ptr = nullptr, *xh_ptr = nullptr;
    static __half *wqkvT_ptr = nullptr, *woutT_ptr = nullptr;
    static bool init_done = false;
    if (!init_done) {
        // First call is the (uncaptured) correctness run; these immediate host
        // APIs never land inside graph capture.
        cudaFuncSetAttribute(flash_mma_kernel,
                             cudaFuncAttributeMaxDynamicSharedMemorySize,
                             FLASH_SMEM);
        cudaFuncSetAttribute(mma_gemm_bias<true>,
                             cudaFuncAttributeMaxDynamicSharedMemorySize,
                             GEMM_SMEM);
        cudaFuncSetAttribute(mma_gemm_bias<false>,
                             cudaFuncAttributeMaxDynamicSharedMemorySize,
                             GEMM_SMEM);
        void* p;
        cudaGetSymbolAddress(&p, g_qkv);   qkv_ptr   = (__half*)p;
        cudaGetSymbolAddress(&p, g_o);     o_ptr     = (__half*)p;
        cudaGetSymbolAddress(&p, g_xh);    xh_ptr    = (__half*)p;
        cudaGetSymbolAddress(&p, g_WqkvT); wqkvT_ptr = (__half*)p;
        cudaGetSymbolAddress(&p, g_WoutT); woutT_ptr = (__half*)p;
        init_done = true;
    }

    // 0) pre-pass: x -> fp16; weights -> transposed fp16 [N,K]
    f2h_kernel<<<(MROWS * (size_t)D_ / 8) / 256, 256>>>(x, xh_ptr);
    transpose_kernel<<<dim3(QKV_N / 32, D_ / 32), dim3(32, 8)>>>(Wqkv, wqkvT_ptr, D_, QKV_N);
    transpose_kernel<<<dim3(D_ / 32, D_ / 32), dim3(32, 8)>>>(Wout, woutT_ptr, D_, D_);

    // 1) QKV = x @ Wqkv + bqkv (fp16 mma, fp32 accum; fp16 output)
    mma_gemm_bias<true><<<dim3(QKV_N / GBN, MROWS / GBM), 256, GEMM_SMEM>>>(
        xh_ptr, wqkvT_ptr, bqkv, qkv_ptr, MROWS, QKV_N, D_);

    // 2) causal flash attention (fp16 tensor cores) -> g_o (fp16)
    flash_mma_kernel<<<dim3(T_ / FBQ, H_, B_), 256, FLASH_SMEM>>>();

    // 3) out = g_o @ Wout + bout (fp16 mma, fp32 output)
    mma_gemm_bias<false><<<dim3(D_ / GBN, MROWS / GBM), 256, GEMM_SMEM>>>(
        o_ptr, woutT_ptr, bout, out, MROWS, D_, D_);
}